// round 10
// baseline (speedup 1.0000x reference)
#include <cuda_runtime.h>
#include <cuda_bf16.h>
#include <math.h>

#define HW 16384
#define LOG100f 4.605170185988092f

__device__ float g_x1[16u * HW * 128u];   // x1 token-major [tok][128]
__device__ float g_bias16[4 * 64 * 64];   // 16*sigmoid(cpb bias)
// pre-split weights, bf16 pairs packed in u32 along K
__device__ unsigned g_qkvh[24576], g_qkvl[24576];   // [384][64]
__device__ unsigned g_pwh[8192],   g_pwl[8192];     // [128][64]
__device__ unsigned g_f1h[32768],  g_f1l[32768];    // [512][64]
__device__ unsigned g_f2h[32768],  g_f2l[32768];    // [128][256]

// ---------------------------------------------------------------------------
__device__ __forceinline__ void mma_bf16(float d[4], unsigned a0, unsigned a1,
                                         unsigned a2, unsigned a3,
                                         unsigned b0, unsigned b1) {
    asm volatile(
        "mma.sync.aligned.m16n8k16.row.col.f32.bf16.bf16.f32 "
        "{%0,%1,%2,%3},{%4,%5,%6,%7},{%8,%9},{%0,%1,%2,%3};"
        : "+f"(d[0]), "+f"(d[1]), "+f"(d[2]), "+f"(d[3])
        : "r"(a0), "r"(a1), "r"(a2), "r"(a3), "r"(b0), "r"(b1));
}

__device__ __forceinline__ void ldsm4(const unsigned* base, int P, int r0, int kp,
                                      unsigned& o0, unsigned& o1, unsigned& o2, unsigned& o3) {
    int lane = threadIdx.x & 31;
    const unsigned* p = base + (r0 + (lane & 15)) * P + kp + ((lane >> 4) << 2);
    unsigned a = (unsigned)__cvta_generic_to_shared(p);
    asm volatile("ldmatrix.sync.aligned.m8n8.x4.shared.b16 {%0,%1,%2,%3}, [%4];"
                 : "=r"(o0), "=r"(o1), "=r"(o2), "=r"(o3) : "r"(a));
}

__device__ __forceinline__ void split2(float v0, float v1, unsigned& hi, unsigned& lo) {
    __nv_bfloat16 h0 = __float2bfloat16(v0);
    __nv_bfloat16 h1 = __float2bfloat16(v1);
    float r0 = v0 - __bfloat162float(h0);
    float r1 = v1 - __bfloat162float(h1);
    __nv_bfloat16 l0 = __float2bfloat16(r0);
    __nv_bfloat16 l1 = __float2bfloat16(r1);
    hi = (unsigned)__bfloat16_as_ushort(h0) | ((unsigned)__bfloat16_as_ushort(h1) << 16);
    lo = (unsigned)__bfloat16_as_ushort(l0) | ((unsigned)__bfloat16_as_ushort(l1) << 16);
}

__device__ __forceinline__ float2 unpack2(unsigned u) {
    __nv_bfloat162 b = *reinterpret_cast<__nv_bfloat162*>(&u);
    return __bfloat1622float2(b);
}

// ------------------------------ K0 ------------------------------------------
__global__ void k0_bias(const float* __restrict__ w1, const float* __restrict__ b1,
                        const float* __restrict__ w2) {
    __shared__ float tab[225][4];
    int tid = threadIdx.x;
    if (tid < 225) {
        int a = tid / 15, bb = tid % 15;
        float v0 = (a - 7) * (8.0f / 7.0f), v1 = (bb - 7) * (8.0f / 7.0f);
        float g0 = copysignf(log2f(fabsf(v0) + 1.0f) * (1.0f / 3.0f), v0);
        float g1 = copysignf(log2f(fabsf(v1) + 1.0f) * (1.0f / 3.0f), v1);
        float o0 = 0, o1 = 0, o2 = 0, o3 = 0;
        for (int j = 0; j < 512; j++) {
            float hv = fmaxf(w1[2 * j] * g0 + w1[2 * j + 1] * g1 + b1[j], 0.0f);
            o0 += hv * w2[j];        o1 += hv * w2[512 + j];
            o2 += hv * w2[1024 + j]; o3 += hv * w2[1536 + j];
        }
        tab[tid][0] = o0; tab[tid][1] = o1; tab[tid][2] = o2; tab[tid][3] = o3;
    }
    __syncthreads();
    for (int e = tid; e < 4 * 64 * 64; e += blockDim.x) {
        int h = e >> 12, i = (e >> 6) & 63, j = e & 63;
        int dy = (i >> 3) - (j >> 3) + 7, dx = (i & 7) - (j & 7) + 7;
        float v = tab[dy * 15 + dx][h];
        g_bias16[e] = 16.0f / (1.0f + expf(-v));
    }
}

__device__ __forceinline__ void splitpair(const float* w, unsigned* hi, unsigned* lo, int i) {
    split2(w[2 * i], w[2 * i + 1], hi[i], lo[i]);
}

__global__ void k0_wsplit(const float* __restrict__ qkvw, const float* __restrict__ pw,
                          const float* __restrict__ f1w, const float* __restrict__ f2w) {
    int i = blockIdx.x * 256 + threadIdx.x;
    if (i < 24576)       splitpair(qkvw, g_qkvh, g_qkvl, i);
    else if (i < 32768)  splitpair(pw,  g_pwh,  g_pwl,  i - 24576);
    else if (i < 65536)  splitpair(f1w, g_f1h,  g_f1l,  i - 32768);
    else if (i < 98304)  splitpair(f2w, g_f2h,  g_f2l,  i - 65536);
}

// ------------------------------ K1: attention (frozen from R9) --------------
#define XHI   0
#define XLO   4352
#define QSPH  8704
#define QSPL  13056
#define KSPH  17408
#define KSPL  21760
#define PHI_  8704
#define PLO_  17920
#define WPH   8704
#define WPL   13056
#define VSPH  27136
#define VSPL  31744
#define WQH   36352
#define WQL   40704
#define ATTN_ 36352
#define OHI_  36352
#define OLO_  40704
#define POUT  45056
#define RG_   53760
#define IQ_   53824
#define IK_   54080
#define K1_SMEM (54336 * 4)

__global__ void __launch_bounds__(512, 1)
k1_attn(const float* __restrict__ x,
        const float* __restrict__ n1w, const float* __restrict__ n1b,
        const float* __restrict__ qb, const float* __restrict__ vb,
        const float* __restrict__ ls, const float* __restrict__ pb) {
    extern __shared__ float sm[];
    unsigned* smu = (unsigned*)sm;
    int tid = threadIdx.x;
    int wid = tid >> 5, lane = tid & 31;
    int g = lane >> 2, q = lane & 3;
    int b = blockIdx.x >> 8, widx = blockIdx.x & 255;
    int wy = widx >> 4, wx = widx & 15;

    {
        const float* xb = x + (size_t)b * 128 * HW;
#pragma unroll
        for (int it = 0; it < 8; it++) {
            int idx = it * 512 + tid;
            int t = idx & 63, cp = idx >> 6;
            int ti = t >> 3, tj = t & 7;
            int hh = (wy * 8 + ti + 4) & 127;
            int ww = (wx * 8 + tj + 4) & 127;
            const float* p = xb + (size_t)(2 * cp) * HW + hh * 128 + ww;
            float v0 = p[0], v1 = p[HW];
            split2(v0, v1, smu[XHI + t * 68 + cp], smu[XLO + t * 68 + cp]);
        }
        if (tid < 64) {
            int ti = tid >> 3, tj = tid & 7;
            int hs = wy * 8 + ti, ws = wx * 8 + tj;
            int hr = hs < 120 ? 0 : (hs < 124 ? 1 : 2);
            int wr = ws < 120 ? 0 : (ws < 124 ? 1 : 2);
            sm[RG_ + tid] = (float)(hr * 3 + wr);
        }
    }

    int mi = wid & 3, nhw = wid >> 2;
    int m0 = mi * 16;
    int n0 = nhw * 16;

    for (int ch = 0; ch < 6; ch++) {
        __syncthreads();
#pragma unroll
        for (int it = 0; it < 8; it++) {
            int p = it * 512 + tid;
            int r = p >> 6, c = p & 63;
            smu[WQH + r * 68 + c] = g_qkvh[(ch * 64 + r) * 64 + c];
            smu[WQL + r * 68 + c] = g_qkvl[(ch * 64 + r) * 64 + c];
        }
        __syncthreads();
        float acc[2][4] = {};
#pragma unroll
        for (int ks = 0; ks < 8; ks++) {
            int kp = ks * 8;
            unsigned ah0, ah1, ah2, ah3, al0, al1, al2, al3;
            ldsm4(smu + XHI, 68, m0, kp, ah0, ah1, ah2, ah3);
            ldsm4(smu + XLO, 68, m0, kp, al0, al1, al2, al3);
            unsigned bh0, bh1, bh2, bh3, bl0, bl1, bl2, bl3;
            ldsm4(smu + WQH, 68, n0, kp, bh0, bh1, bh2, bh3);
            ldsm4(smu + WQL, 68, n0, kp, bl0, bl1, bl2, bl3);
            mma_bf16(acc[0], ah0, ah1, ah2, ah3, bh0, bh2);
            mma_bf16(acc[0], ah0, ah1, ah2, ah3, bl0, bl2);
            mma_bf16(acc[0], al0, al1, al2, al3, bh0, bh2);
            mma_bf16(acc[1], ah0, ah1, ah2, ah3, bh1, bh3);
            mma_bf16(acc[1], ah0, ah1, ah2, ah3, bl1, bl3);
            mma_bf16(acc[1], al0, al1, al2, al3, bh1, bh3);
        }
        int r0 = m0 + g, r1 = r0 + 8;
        if (ch < 2) {
#pragma unroll
            for (int nt = 0; nt < 2; nt++) {
                int col0 = ch * 64 + n0 + nt * 8 + 2 * q;
                float b0c = qb[col0], b1c = qb[col0 + 1];
                int dp = col0 >> 1;
                split2(acc[nt][0] + b0c, acc[nt][1] + b1c,
                       smu[QSPH + r0 * 68 + dp], smu[QSPL + r0 * 68 + dp]);
                split2(acc[nt][2] + b0c, acc[nt][3] + b1c,
                       smu[QSPH + r1 * 68 + dp], smu[QSPL + r1 * 68 + dp]);
            }
        } else if (ch < 4) {
#pragma unroll
            for (int nt = 0; nt < 2; nt++) {
                int col0 = ch * 64 + n0 + nt * 8 + 2 * q;
                int dp = (col0 - 128) >> 1;
                split2(acc[nt][0], acc[nt][1],
                       smu[KSPH + r0 * 68 + dp], smu[KSPL + r0 * 68 + dp]);
                split2(acc[nt][2], acc[nt][3],
                       smu[KSPH + r1 * 68 + dp], smu[KSPL + r1 * 68 + dp]);
            }
        } else {
#pragma unroll
            for (int nt = 0; nt < 2; nt++) {
                int col0 = ch * 64 + n0 + nt * 8 + 2 * q;
                int d0 = col0 - 256;
                float v0 = acc[nt][0] + vb[d0], v1 = acc[nt][1] + vb[d0 + 1];
                float v2 = acc[nt][2] + vb[d0], v3 = acc[nt][3] + vb[d0 + 1];
                float p0 = __shfl_xor_sync(0xffffffffu, v0, 4);
                float p1 = __shfl_xor_sync(0xffffffffu, v1, 4);
                float p2 = __shfl_xor_sync(0xffffffffu, v2, 4);
                float p3 = __shfl_xor_sync(0xffffffffu, v3, 4);
                if (!(g & 1)) {
                    int up = (m0 + g) >> 1;
                    split2(v0, p0, smu[VSPH + d0 * 36 + up], smu[VSPL + d0 * 36 + up]);
                    split2(v1, p1, smu[VSPH + (d0 + 1) * 36 + up], smu[VSPL + (d0 + 1) * 36 + up]);
                } else {
                    int up = (m0 + g + 7) >> 1;
                    split2(p2, v2, smu[VSPH + d0 * 36 + up], smu[VSPL + d0 * 36 + up]);
                    split2(p3, v3, smu[VSPH + (d0 + 1) * 36 + up], smu[VSPL + (d0 + 1) * 36 + up]);
                }
            }
        }
    }
    __syncthreads();

    {
        int qk = tid >> 8, rem = tid & 255;
        int h = rem >> 6, t = rem & 63;
        int base = (qk ? KSPH : QSPH) + t * 68 + h * 16;
        int baseL = base + (QSPL - QSPH);
        float s = 0.f;
#pragma unroll
        for (int i = 0; i < 16; i++) {
            float2 fh = unpack2(smu[base + i]);
            float2 fl = unpack2(smu[baseL + i]);
            float a0 = fh.x + fl.x, a1 = fh.y + fl.y;
            s += a0 * a0 + a1 * a1;
        }
        sm[(qk ? IK_ : IQ_) + h * 64 + t] = 1.0f / fmaxf(sqrtf(s), 1e-12f);
    }
    __syncthreads();

    {
        int hw = wid >> 2;
        float scale = __expf(fminf(ls[hw], LOG100f));
        float acc[4][2][4];
#pragma unroll
        for (int i = 0; i < 4; i++)
#pragma unroll
            for (int j = 0; j < 2; j++)
#pragma unroll
                for (int k = 0; k < 4; k++) acc[i][j][k] = 0.f;
#pragma unroll
        for (int ks = 0; ks < 2; ks++) {
            int kp = hw * 16 + ks * 8;
            unsigned ah0, ah1, ah2, ah3, al0, al1, al2, al3;
            ldsm4(smu + QSPH, 68, m0, kp, ah0, ah1, ah2, ah3);
            ldsm4(smu + QSPL, 68, m0, kp, al0, al1, al2, al3);
#pragma unroll
            for (int nh = 0; nh < 4; nh++) {
                unsigned bh0, bh1, bh2, bh3, bl0, bl1, bl2, bl3;
                ldsm4(smu + KSPH, 68, nh * 16, kp, bh0, bh1, bh2, bh3);
                ldsm4(smu + KSPL, 68, nh * 16, kp, bl0, bl1, bl2, bl3);
                mma_bf16(acc[nh][0], ah0, ah1, ah2, ah3, bh0, bh2);
                mma_bf16(acc[nh][0], ah0, ah1, ah2, ah3, bl0, bl2);
                mma_bf16(acc[nh][0], al0, al1, al2, al3, bh0, bh2);
                mma_bf16(acc[nh][1], ah0, ah1, ah2, ah3, bh1, bh3);
                mma_bf16(acc[nh][1], ah0, ah1, ah2, ah3, bl1, bl3);
                mma_bf16(acc[nh][1], al0, al1, al2, al3, bh1, bh3);
            }
        }
        int r0 = m0 + g, r1 = r0 + 8;
        float iq0 = sm[IQ_ + hw * 64 + r0] * scale;
        float iq1 = sm[IQ_ + hw * 64 + r1] * scale;
        float rt0 = sm[RG_ + r0], rt1 = sm[RG_ + r1];
        float* A = &sm[ATTN_ + hw * 4352];
#pragma unroll
        for (int nh = 0; nh < 4; nh++)
#pragma unroll
            for (int nt = 0; nt < 2; nt++) {
                int col = nh * 16 + nt * 8 + 2 * q;
                float ik0 = sm[IK_ + hw * 64 + col], ik1 = sm[IK_ + hw * 64 + col + 1];
                float ru0 = sm[RG_ + col], ru1 = sm[RG_ + col + 1];
                float2 b0v = *(const float2*)&g_bias16[(hw * 64 + r0) * 64 + col];
                float2 b1v = *(const float2*)&g_bias16[(hw * 64 + r1) * 64 + col];
                A[r0 * 68 + col]     = acc[nh][nt][0] * iq0 * ik0 + b0v.x + (rt0 != ru0 ? -100.f : 0.f);
                A[r0 * 68 + col + 1] = acc[nh][nt][1] * iq0 * ik1 + b0v.y + (rt0 != ru1 ? -100.f : 0.f);
                A[r1 * 68 + col]     = acc[nh][nt][2] * iq1 * ik0 + b1v.x + (rt1 != ru0 ? -100.f : 0.f);
                A[r1 * 68 + col + 1] = acc[nh][nt][3] * iq1 * ik1 + b1v.y + (rt1 != ru1 ? -100.f : 0.f);
            }
    }
    __syncthreads();

    {
        int r = tid >> 1, half = tid & 1;
        int hw = r >> 6, t = r & 63;
        const float* row = &sm[ATTN_ + hw * 4352 + t * 68 + half * 32];
        float e[32];
        float mx = -1e30f;
#pragma unroll
        for (int i = 0; i < 32; i++) { e[i] = row[i]; mx = fmaxf(mx, e[i]); }
        mx = fmaxf(mx, __shfl_xor_sync(0xffffffffu, mx, 1));
        float s = 0.f;
#pragma unroll
        for (int i = 0; i < 32; i++) { e[i] = __expf(e[i] - mx); s += e[i]; }
        s += __shfl_xor_sync(0xffffffffu, s, 1);
        float inv = 1.0f / s;
        int pb_ = hw * 2304 + t * 36 + half * 16;
#pragma unroll
        for (int i = 0; i < 16; i++)
            split2(e[2 * i] * inv, e[2 * i + 1] * inv,
                   smu[PHI_ + pb_ + i], smu[PLO_ + pb_ + i]);
    }
    __syncthreads();

    {
        int hw = wid >> 2;
        const unsigned* PH = smu + PHI_ + hw * 2304;
        const unsigned* PL = smu + PLO_ + hw * 2304;
        float acc[2][2][4];
#pragma unroll
        for (int i = 0; i < 2; i++)
#pragma unroll
            for (int j = 0; j < 2; j++)
#pragma unroll
                for (int k = 0; k < 4; k++) acc[i][j][k] = 0.f;
#pragma unroll
        for (int ks = 0; ks < 4; ks++) {
            int kp = ks * 8;
            unsigned ah0, ah1, ah2, ah3, al0, al1, al2, al3;
            ldsm4(PH, 36, m0, kp, ah0, ah1, ah2, ah3);
            ldsm4(PL, 36, m0, kp, al0, al1, al2, al3);
#pragma unroll
            for (int nd = 0; nd < 2; nd++) {
                int n0v = hw * 32 + nd * 16;
                unsigned bh0, bh1, bh2, bh3, bl0, bl1, bl2, bl3;
                ldsm4(smu + VSPH, 36, n0v, kp, bh0, bh1, bh2, bh3);
                ldsm4(smu + VSPL, 36, n0v, kp, bl0, bl1, bl2, bl3);
                mma_bf16(acc[nd][0], ah0, ah1, ah2, ah3, bh0, bh2);
                mma_bf16(acc[nd][0], ah0, ah1, ah2, ah3, bl0, bl2);
                mma_bf16(acc[nd][0], al0, al1, al2, al3, bh0, bh2);
                mma_bf16(acc[nd][1], ah0, ah1, ah2, ah3, bh1, bh3);
                mma_bf16(acc[nd][1], ah0, ah1, ah2, ah3, bl1, bl3);
                mma_bf16(acc[nd][1], al0, al1, al2, al3, bh1, bh3);
            }
        }
        int r0 = m0 + g, r1 = r0 + 8;
#pragma unroll
        for (int nd = 0; nd < 2; nd++)
#pragma unroll
            for (int nt = 0; nt < 2; nt++) {
                int dglob = hw * 32 + nd * 16 + nt * 8 + 2 * q;
                int dp = dglob >> 1;
                split2(acc[nd][nt][0], acc[nd][nt][1],
                       smu[OHI_ + r0 * 68 + dp], smu[OLO_ + r0 * 68 + dp]);
                split2(acc[nd][nt][2], acc[nd][nt][3],
                       smu[OHI_ + r1 * 68 + dp], smu[OLO_ + r1 * 68 + dp]);
            }
    }

    for (int ch = 0; ch < 2; ch++) {
        __syncthreads();
#pragma unroll
        for (int it = 0; it < 8; it++) {
            int p = it * 512 + tid;
            int r = p >> 6, c = p & 63;
            smu[WPH + r * 68 + c] = g_pwh[(ch * 64 + r) * 64 + c];
            smu[WPL + r * 68 + c] = g_pwl[(ch * 64 + r) * 64 + c];
        }
        __syncthreads();
        float acc[2][4] = {};
#pragma unroll
        for (int ks = 0; ks < 8; ks++) {
            int kp = ks * 8;
            unsigned ah0, ah1, ah2, ah3, al0, al1, al2, al3;
            ldsm4(smu + OHI_, 68, m0, kp, ah0, ah1, ah2, ah3);
            ldsm4(smu + OLO_, 68, m0, kp, al0, al1, al2, al3);
            unsigned bh0, bh1, bh2, bh3, bl0, bl1, bl2, bl3;
            ldsm4(smu + WPH, 68, n0, kp, bh0, bh1, bh2, bh3);
            ldsm4(smu + WPL, 68, n0, kp, bl0, bl1, bl2, bl3);
            mma_bf16(acc[0], ah0, ah1, ah2, ah3, bh0, bh2);
            mma_bf16(acc[0], ah0, ah1, ah2, ah3, bl0, bl2);
            mma_bf16(acc[0], al0, al1, al2, al3, bh0, bh2);
            mma_bf16(acc[1], ah0, ah1, ah2, ah3, bh1, bh3);
            mma_bf16(acc[1], ah0, ah1, ah2, ah3, bl1, bl3);
            mma_bf16(acc[1], al0, al1, al2, al3, bh1, bh3);
        }
        int r0 = m0 + g, r1 = r0 + 8;
#pragma unroll
        for (int nt = 0; nt < 2; nt++) {
            int col0 = ch * 64 + n0 + nt * 8 + 2 * q;
            sm[POUT + r0 * 132 + col0]     = acc[nt][0] + pb[col0];
            sm[POUT + r0 * 132 + col0 + 1] = acc[nt][1] + pb[col0 + 1];
            sm[POUT + r1 * 132 + col0]     = acc[nt][2] + pb[col0];
            sm[POUT + r1 * 132 + col0 + 1] = acc[nt][3] + pb[col0 + 1];
        }
    }
    __syncthreads();

    {
        int t = tid >> 3, ln = tid & 7;
        const float* prow = &sm[POUT + t * 132];
        int cb = ln * 16;
        float s1 = 0.f, s2 = 0.f;
#pragma unroll
        for (int c = 0; c < 16; c++) {
            float v = prow[cb + c];
            s1 += v; s2 += v * v;
        }
        s1 += __shfl_xor_sync(0xffffffffu, s1, 1);
        s2 += __shfl_xor_sync(0xffffffffu, s2, 1);
        s1 += __shfl_xor_sync(0xffffffffu, s1, 2);
        s2 += __shfl_xor_sync(0xffffffffu, s2, 2);
        s1 += __shfl_xor_sync(0xffffffffu, s1, 4);
        s2 += __shfl_xor_sync(0xffffffffu, s2, 4);
        float mu = s1 * (1.0f / 128.0f);
        float var = fmaxf(s2 * (1.0f / 128.0f) - mu * mu, 0.0f);
        float rs = rsqrtf(var + 1e-5f);
        int ti = t >> 3, tj = t & 7;
        int hh = (wy * 8 + ti + 4) & 127;
        int ww = (wx * 8 + tj + 4) & 127;
        float* dst = &g_x1[((size_t)b * HW + hh * 128 + ww) * 128];
#pragma unroll
        for (int cp = 0; cp < 8; cp++) {
            unsigned uh = smu[XHI + t * 68 + ln * 8 + cp];
            unsigned ul = smu[XLO + t * 68 + ln * 8 + cp];
            float2 fh = unpack2(uh), fl = unpack2(ul);
            int cc = cb + 2 * cp;
            float l0 = (prow[cc] - mu) * rs * n1w[cc] + n1b[cc];
            float l1 = (prow[cc + 1] - mu) * rs * n1w[cc + 1] + n1b[cc + 1];
            dst[cc]     = fh.x + fl.x + l0;
            dst[cc + 1] = fh.y + fl.y + l1;
        }
    }
}

// ------------------------------ K2: MLP v2 (m32xn32 tiles) ------------------
// words: X [128][68]x2, WS [128][68]x2 (W1/W2 staged sequentially), H [128][68]x2
#define K2XHI 0        // ends 8704
#define K2XLO 8704     // ends 17408
#define K2WSH 17408    // ends 26112
#define K2WSL 26112    // ends 34816
#define K2HH  34816    // ends 43520
#define K2HL  43520    // ends 52224
#define K2Y   17408    // [128][133] = 17024, aliases dead WS after final fc2
#define K2_SMEM (52224 * 4)

__global__ void __launch_bounds__(512, 1)
k2_mlp(const float* __restrict__ n2w, const float* __restrict__ n2b,
       const float* __restrict__ b1, const float* __restrict__ b2,
       float* __restrict__ out) {
    extern __shared__ float sm[];
    unsigned* smu = (unsigned*)sm;
    int tid = threadIdx.x;
    int wid = tid >> 5, lane = tid & 31;
    int g = lane >> 2, q = lane & 3;
    int p0 = blockIdx.x * 128;
    int b = p0 >> 14, h = (p0 >> 7) & 127;

    // load + split x1 (128 tokens)
#pragma unroll
    for (int it = 0; it < 16; it++) {
        int idx = it * 512 + tid;
        int cp = idx & 63, t = idx >> 6;
        float2 v = *(const float2*)&g_x1[((size_t)p0 + t) * 128 + 2 * cp];
        split2(v.x, v.y, smu[K2XHI + t * 68 + cp], smu[K2XLO + t * 68 + cp]);
    }

    int mi = wid & 3, nh = wid >> 2;   // 4 mi x 4 nh; warp tile m32 x n32
    int m0a = mi * 32, m0b = m0a + 16;
    int n0 = nh * 32;
    float acc2[2][2][2][4];            // [mtile][n16][n8][4] persistent fc2
#pragma unroll
    for (int a = 0; a < 2; a++)
#pragma unroll
        for (int t = 0; t < 2; t++)
#pragma unroll
            for (int u = 0; u < 2; u++)
#pragma unroll
                for (int j = 0; j < 4; j++) acc2[a][t][u][j] = 0.f;

    for (int ch = 0; ch < 4; ch++) {   // 128 fc1 cols per chunk
        __syncthreads();
        // stage W1 chunk [128 n][64 kp]
#pragma unroll
        for (int it = 0; it < 16; it++) {
            int p = it * 512 + tid;
            int r = p >> 6, c = p & 63;
            smu[K2WSH + r * 68 + c] = g_f1h[(ch * 128 + r) * 64 + c];
            smu[K2WSL + r * 68 + c] = g_f1l[(ch * 128 + r) * 64 + c];
        }
        __syncthreads();
        // fc1: m32 x n32
        float acc[2][2][2][4];
#pragma unroll
        for (int a = 0; a < 2; a++)
#pragma unroll
            for (int t = 0; t < 2; t++)
#pragma unroll
                for (int u = 0; u < 2; u++)
#pragma unroll
                    for (int j = 0; j < 4; j++) acc[a][t][u][j] = 0.f;
#pragma unroll
        for (int ks = 0; ks < 8; ks++) {
            int kp = ks * 8;
            unsigned ah[2][4], al[2][4], bh[2][4], bl[2][4];
            ldsm4(smu + K2XHI, 68, m0a, kp, ah[0][0], ah[0][1], ah[0][2], ah[0][3]);
            ldsm4(smu + K2XLO, 68, m0a, kp, al[0][0], al[0][1], al[0][2], al[0][3]);
            ldsm4(smu + K2XHI, 68, m0b, kp, ah[1][0], ah[1][1], ah[1][2], ah[1][3]);
            ldsm4(smu + K2XLO, 68, m0b, kp, al[1][0], al[1][1], al[1][2], al[1][3]);
            ldsm4(smu + K2WSH, 68, n0, kp, bh[0][0], bh[0][1], bh[0][2], bh[0][3]);
            ldsm4(smu + K2WSL, 68, n0, kp, bl[0][0], bl[0][1], bl[0][2], bl[0][3]);
            ldsm4(smu + K2WSH, 68, n0 + 16, kp, bh[1][0], bh[1][1], bh[1][2], bh[1][3]);
            ldsm4(smu + K2WSL, 68, n0 + 16, kp, bl[1][0], bl[1][1], bl[1][2], bl[1][3]);
#pragma unroll
            for (int a = 0; a < 2; a++)
#pragma unroll
                for (int t = 0; t < 2; t++)
#pragma unroll
                    for (int u = 0; u < 2; u++) {
                        mma_bf16(acc[a][t][u], ah[a][0], ah[a][1], ah[a][2], ah[a][3],
                                 bh[t][u], bh[t][u + 2]);
                        mma_bf16(acc[a][t][u], ah[a][0], ah[a][1], ah[a][2], ah[a][3],
                                 bl[t][u], bl[t][u + 2]);
                        mma_bf16(acc[a][t][u], al[a][0], al[a][1], al[a][2], al[a][3],
                                 bh[t][u], bh[t][u + 2]);
                    }
        }
        // silu + split -> H [t][hpair 0..63] pitch 68
#pragma unroll
        for (int a = 0; a < 2; a++) {
            int r0 = (a ? m0b : m0a) + g, r1 = r0 + 8;
#pragma unroll
            for (int t = 0; t < 2; t++)
#pragma unroll
                for (int u = 0; u < 2; u++) {
                    int cw = n0 + t * 16 + u * 8 + 2 * q;       // col within chunk
                    int col = ch * 128 + cw;
                    float v0 = acc[a][t][u][0] + b1[col];
                    float v1 = acc[a][t][u][1] + b1[col + 1];
                    float v2 = acc[a][t][u][2] + b1[col];
                    float v3 = acc[a][t][u][3] + b1[col + 1];
                    v0 = v0 / (1.0f + __expf(-v0));
                    v1 = v1 / (1.0f + __expf(-v1));
                    v2 = v2 / (1.0f + __expf(-v2));
                    v3 = v3 / (1.0f + __expf(-v3));
                    int pp = cw >> 1;
                    split2(v0, v1, smu[K2HH + r0 * 68 + pp], smu[K2HL + r0 * 68 + pp]);
                    split2(v2, v3, smu[K2HH + r1 * 68 + pp], smu[K2HL + r1 * 68 + pp]);
                }
        }
        __syncthreads();   // H ready; WS reads done
        // stage W2 k-slice [128 out][64 kp] over WS
#pragma unroll
        for (int it = 0; it < 16; it++) {
            int p = it * 512 + tid;
            int r = p >> 6, c = p & 63;
            smu[K2WSH + r * 68 + c] = g_f2h[r * 256 + ch * 64 + c];
            smu[K2WSL + r * 68 + c] = g_f2l[r * 256 + ch * 64 + c];
        }
        __syncthreads();
        // fc2 partial: m32 x n32
#pragma unroll
        for (int ks = 0; ks < 8; ks++) {
            int kp = ks * 8;
            unsigned ah[2][4], al[2][4], bh[2][4], bl[2][4];
            ldsm4(smu + K2HH, 68, m0a, kp, ah[0][0], ah[0][1], ah[0][2], ah[0][3]);
            ldsm4(smu + K2HL, 68, m0a, kp, al[0][0], al[0][1], al[0][2], al[0][3]);
            ldsm4(smu + K2HH, 68, m0b, kp, ah[1][0], ah[1][1], ah[1][2], ah[1][3]);
            ldsm4(smu + K2HL, 68, m0b, kp, al[1][0], al[1][1], al[1][2], al[1][3]);
            ldsm4(smu + K2WSH, 68, n0, kp, bh[0][0], bh[0][1], bh[0][2], bh[0][3]);
            ldsm4(smu + K2WSL, 68, n0, kp, bl[0][0], bl[0][1], bl[0][2], bl[0][3]);
            ldsm4(smu + K2WSH, 68, n0 + 16, kp, bh[1][0], bh[1][1], bh[1][2], bh[1][3]);
            ldsm4(smu + K2WSL, 68, n0 + 16, kp, bl[1][0], bl[1][1], bl[1][2], bl[1][3]);
#pragma unroll
            for (int a = 0; a < 2; a++)
#pragma unroll
                for (int t = 0; t < 2; t++)
#pragma unroll
                    for (int u = 0; u < 2; u++) {
                        mma_bf16(acc2[a][t][u], ah[a][0], ah[a][1], ah[a][2], ah[a][3],
                                 bh[t][u], bh[t][u + 2]);
                        mma_bf16(acc2[a][t][u], ah[a][0], ah[a][1], ah[a][2], ah[a][3],
                                 bl[t][u], bl[t][u + 2]);
                        mma_bf16(acc2[a][t][u], al[a][0], al[a][1], al[a][2], al[a][3],
                                 bh[t][u], bh[t][u + 2]);
                    }
        }
    }
    __syncthreads();   // WS/H dead; Y aliases WS
    // Y = fc2 out + bias
#pragma unroll
    for (int a = 0; a < 2; a++) {
        int r0 = (a ? m0b : m0a) + g, r1 = r0 + 8;
#pragma unroll
        for (int t = 0; t < 2; t++)
#pragma unroll
            for (int u = 0; u < 2; u++) {
                int col = n0 + t * 16 + u * 8 + 2 * q;
                sm[K2Y + r0 * 133 + col]     = acc2[a][t][u][0] + b2[col];
                sm[K2Y + r0 * 133 + col + 1] = acc2[a][t][u][1] + b2[col + 1];
                sm[K2Y + r1 * 133 + col]     = acc2[a][t][u][2] + b2[col];
                sm[K2Y + r1 * 133 + col + 1] = acc2[a][t][u][3] + b2[col + 1];
            }
    }
    __syncthreads();
    // LN + residual (x1 = hi + lo), 4 threads/row
    {
        int t = tid >> 2, ln = tid & 3;
        float* yrow = &sm[K2Y + t * 133];
        int cb = ln * 32;
        float s1 = 0.f, s2 = 0.f;
#pragma unroll 8
        for (int c = 0; c < 32; c++) {
            float v = yrow[cb + c];
            s1 += v; s2 += v * v;
        }
        s1 += __shfl_xor_sync(0xffffffffu, s1, 1);
        s2 += __shfl_xor_sync(0xffffffffu, s2, 1);
        s1 += __shfl_xor_sync(0xffffffffu, s1, 2);
        s2 += __shfl_xor_sync(0xffffffffu, s2, 2);
        float mu = s1 * (1.0f / 128.0f);
        float var = fmaxf(s2 * (1.0f / 128.0f) - mu * mu, 0.0f);
        float rs = rsqrtf(var + 1e-5f);
#pragma unroll 8
        for (int cp = 0; cp < 16; cp++) {
            unsigned uh = smu[K2XHI + t * 68 + (cb >> 1) + cp];
            unsigned ul = smu[K2XLO + t * 68 + (cb >> 1) + cp];
            float2 fh = unpack2(uh), fl = unpack2(ul);
            int cc = cb + 2 * cp;
            float l0 = (yrow[cc] - mu) * rs * n2w[cc] + n2b[cc];
            float l1 = (yrow[cc + 1] - mu) * rs * n2w[cc + 1] + n2b[cc + 1];
            yrow[cc]     = fh.x + fl.x + l0;
            yrow[cc + 1] = fh.y + fl.y + l1;
        }
    }
    __syncthreads();
    // transposed store -> NCHW (128 tokens = full image row h)
    {
        float* ob = out + (size_t)b * 128 * HW + h * 128;
#pragma unroll
        for (int it = 0; it < 32; it++) {
            int idx = it * 512 + tid;
            int c = idx >> 7, w = idx & 127;
            ob[(size_t)c * HW + w] = sm[K2Y + w * 133 + c];
        }
    }
}

// ------------------------------ launch --------------------------------------
extern "C" void kernel_launch(void* const* d_in, const int* in_sizes, int n_in,
                              void* d_out, int out_size) {
    const float* x    = (const float*)d_in[0];
    const float* n1w  = (const float*)d_in[1];
    const float* n1b  = (const float*)d_in[2];
    const float* qkvw = (const float*)d_in[3];
    const float* qb   = (const float*)d_in[4];
    const float* vb   = (const float*)d_in[5];
    const float* ls   = (const float*)d_in[6];
    const float* cw1  = (const float*)d_in[7];
    const float* cb1  = (const float*)d_in[8];
    const float* cw2  = (const float*)d_in[9];
    const float* pw   = (const float*)d_in[10];
    const float* pb   = (const float*)d_in[11];
    const float* n2w  = (const float*)d_in[12];
    const float* n2b  = (const float*)d_in[13];
    const float* f1w  = (const float*)d_in[14];
    const float* f1b  = (const float*)d_in[15];
    const float* f2w  = (const float*)d_in[16];
    const float* f2b  = (const float*)d_in[17];
    float* out = (float*)d_out;

    cudaFuncSetAttribute(k1_attn, cudaFuncAttributeMaxDynamicSharedMemorySize, K1_SMEM);
    cudaFuncSetAttribute(k2_mlp,  cudaFuncAttributeMaxDynamicSharedMemorySize, K2_SMEM);

    k0_bias<<<1, 256>>>(cw1, cb1, cw2);
    k0_wsplit<<<384, 256>>>(qkvw, pw, f1w, f2w);
    k1_attn<<<4096, 512, K1_SMEM>>>(x, n1w, n1b, qb, vb, ls, pb);
    k2_mlp<<<2048, 512, K2_SMEM>>>(n2w, n2b, f1b, f2b, out);
}

// round 11
// speedup vs baseline: 1.0279x; 1.0279x over previous
#include <cuda_runtime.h>
#include <cuda_bf16.h>
#include <math.h>

#define HW 16384
#define LOG100f 4.605170185988092f

__device__ float g_x1[16u * HW * 128u];   // x1 token-major [tok][128]
__device__ float g_bias16[4 * 64 * 64];   // 16*sigmoid(cpb bias)
// pre-split weights, bf16 pairs packed in u32 along K
__device__ unsigned g_qkvh[24576], g_qkvl[24576];   // [384][64]
__device__ unsigned g_pwh[8192],   g_pwl[8192];     // [128][64]
__device__ unsigned g_f1h[32768],  g_f1l[32768];    // [512][64]
__device__ unsigned g_f2h[32768],  g_f2l[32768];    // [128][256]

// ---------------------------------------------------------------------------
__device__ __forceinline__ void mma_bf16(float d[4], unsigned a0, unsigned a1,
                                         unsigned a2, unsigned a3,
                                         unsigned b0, unsigned b1) {
    asm volatile(
        "mma.sync.aligned.m16n8k16.row.col.f32.bf16.bf16.f32 "
        "{%0,%1,%2,%3},{%4,%5,%6,%7},{%8,%9},{%0,%1,%2,%3};"
        : "+f"(d[0]), "+f"(d[1]), "+f"(d[2]), "+f"(d[3])
        : "r"(a0), "r"(a1), "r"(a2), "r"(a3), "r"(b0), "r"(b1));
}

__device__ __forceinline__ void ldsm4(const unsigned* base, int P, int r0, int kp,
                                      unsigned& o0, unsigned& o1, unsigned& o2, unsigned& o3) {
    int lane = threadIdx.x & 31;
    const unsigned* p = base + (r0 + (lane & 15)) * P + kp + ((lane >> 4) << 2);
    unsigned a = (unsigned)__cvta_generic_to_shared(p);
    asm volatile("ldmatrix.sync.aligned.m8n8.x4.shared.b16 {%0,%1,%2,%3}, [%4];"
                 : "=r"(o0), "=r"(o1), "=r"(o2), "=r"(o3) : "r"(a));
}

__device__ __forceinline__ void cpa16(unsigned* dst, const unsigned* src) {
    unsigned d = (unsigned)__cvta_generic_to_shared(dst);
    asm volatile("cp.async.cg.shared.global [%0], [%1], 16;" :: "r"(d), "l"(src));
}
#define CP_COMMIT() asm volatile("cp.async.commit_group;" ::: "memory")
#define CP_WAIT0()  asm volatile("cp.async.wait_group 0;" ::: "memory")

__device__ __forceinline__ void split2(float v0, float v1, unsigned& hi, unsigned& lo) {
    __nv_bfloat16 h0 = __float2bfloat16(v0);
    __nv_bfloat16 h1 = __float2bfloat16(v1);
    float r0 = v0 - __bfloat162float(h0);
    float r1 = v1 - __bfloat162float(h1);
    __nv_bfloat16 l0 = __float2bfloat16(r0);
    __nv_bfloat16 l1 = __float2bfloat16(r1);
    hi = (unsigned)__bfloat16_as_ushort(h0) | ((unsigned)__bfloat16_as_ushort(h1) << 16);
    lo = (unsigned)__bfloat16_as_ushort(l0) | ((unsigned)__bfloat16_as_ushort(l1) << 16);
}

__device__ __forceinline__ float2 unpack2(unsigned u) {
    __nv_bfloat162 b = *reinterpret_cast<__nv_bfloat162*>(&u);
    return __bfloat1622float2(b);
}

// ------------------------------ K0 ------------------------------------------
__global__ void k0_bias(const float* __restrict__ w1, const float* __restrict__ b1,
                        const float* __restrict__ w2) {
    __shared__ float tab[225][4];
    int tid = threadIdx.x;
    if (tid < 225) {
        int a = tid / 15, bb = tid % 15;
        float v0 = (a - 7) * (8.0f / 7.0f), v1 = (bb - 7) * (8.0f / 7.0f);
        float g0 = copysignf(log2f(fabsf(v0) + 1.0f) * (1.0f / 3.0f), v0);
        float g1 = copysignf(log2f(fabsf(v1) + 1.0f) * (1.0f / 3.0f), v1);
        float o0 = 0, o1 = 0, o2 = 0, o3 = 0;
        for (int j = 0; j < 512; j++) {
            float hv = fmaxf(w1[2 * j] * g0 + w1[2 * j + 1] * g1 + b1[j], 0.0f);
            o0 += hv * w2[j];        o1 += hv * w2[512 + j];
            o2 += hv * w2[1024 + j]; o3 += hv * w2[1536 + j];
        }
        tab[tid][0] = o0; tab[tid][1] = o1; tab[tid][2] = o2; tab[tid][3] = o3;
    }
    __syncthreads();
    for (int e = tid; e < 4 * 64 * 64; e += blockDim.x) {
        int h = e >> 12, i = (e >> 6) & 63, j = e & 63;
        int dy = (i >> 3) - (j >> 3) + 7, dx = (i & 7) - (j & 7) + 7;
        float v = tab[dy * 15 + dx][h];
        g_bias16[e] = 16.0f / (1.0f + expf(-v));
    }
}

__device__ __forceinline__ void splitpair(const float* w, unsigned* hi, unsigned* lo, int i) {
    split2(w[2 * i], w[2 * i + 1], hi[i], lo[i]);
}

__global__ void k0_wsplit(const float* __restrict__ qkvw, const float* __restrict__ pw,
                          const float* __restrict__ f1w, const float* __restrict__ f2w) {
    int i = blockIdx.x * 256 + threadIdx.x;
    if (i < 24576)       splitpair(qkvw, g_qkvh, g_qkvl, i);
    else if (i < 32768)  splitpair(pw,  g_pwh,  g_pwl,  i - 24576);
    else if (i < 65536)  splitpair(f1w, g_f1h,  g_f1l,  i - 32768);
    else if (i < 98304)  splitpair(f2w, g_f2h,  g_f2l,  i - 65536);
}

// ------------------------------ K1: attention (frozen from R9) --------------
#define XHI   0
#define XLO   4352
#define QSPH  8704
#define QSPL  13056
#define KSPH  17408
#define KSPL  21760
#define PHI_  8704
#define PLO_  17920
#define WPH   8704
#define WPL   13056
#define VSPH  27136
#define VSPL  31744
#define WQH   36352
#define WQL   40704
#define ATTN_ 36352
#define OHI_  36352
#define OLO_  40704
#define POUT  45056
#define RG_   53760
#define IQ_   53824
#define IK_   54080
#define K1_SMEM (54336 * 4)

__global__ void __launch_bounds__(512, 1)
k1_attn(const float* __restrict__ x,
        const float* __restrict__ n1w, const float* __restrict__ n1b,
        const float* __restrict__ qb, const float* __restrict__ vb,
        const float* __restrict__ ls, const float* __restrict__ pb) {
    extern __shared__ float sm[];
    unsigned* smu = (unsigned*)sm;
    int tid = threadIdx.x;
    int wid = tid >> 5, lane = tid & 31;
    int g = lane >> 2, q = lane & 3;
    int b = blockIdx.x >> 8, widx = blockIdx.x & 255;
    int wy = widx >> 4, wx = widx & 15;

    {
        const float* xb = x + (size_t)b * 128 * HW;
#pragma unroll
        for (int it = 0; it < 8; it++) {
            int idx = it * 512 + tid;
            int t = idx & 63, cp = idx >> 6;
            int ti = t >> 3, tj = t & 7;
            int hh = (wy * 8 + ti + 4) & 127;
            int ww = (wx * 8 + tj + 4) & 127;
            const float* p = xb + (size_t)(2 * cp) * HW + hh * 128 + ww;
            float v0 = p[0], v1 = p[HW];
            split2(v0, v1, smu[XHI + t * 68 + cp], smu[XLO + t * 68 + cp]);
        }
        if (tid < 64) {
            int ti = tid >> 3, tj = tid & 7;
            int hs = wy * 8 + ti, ws = wx * 8 + tj;
            int hr = hs < 120 ? 0 : (hs < 124 ? 1 : 2);
            int wr = ws < 120 ? 0 : (ws < 124 ? 1 : 2);
            sm[RG_ + tid] = (float)(hr * 3 + wr);
        }
    }

    int mi = wid & 3, nhw = wid >> 2;
    int m0 = mi * 16;
    int n0 = nhw * 16;

    for (int ch = 0; ch < 6; ch++) {
        __syncthreads();
#pragma unroll
        for (int it = 0; it < 8; it++) {
            int p = it * 512 + tid;
            int r = p >> 6, c = p & 63;
            smu[WQH + r * 68 + c] = g_qkvh[(ch * 64 + r) * 64 + c];
            smu[WQL + r * 68 + c] = g_qkvl[(ch * 64 + r) * 64 + c];
        }
        __syncthreads();
        float acc[2][4] = {};
#pragma unroll
        for (int ks = 0; ks < 8; ks++) {
            int kp = ks * 8;
            unsigned ah0, ah1, ah2, ah3, al0, al1, al2, al3;
            ldsm4(smu + XHI, 68, m0, kp, ah0, ah1, ah2, ah3);
            ldsm4(smu + XLO, 68, m0, kp, al0, al1, al2, al3);
            unsigned bh0, bh1, bh2, bh3, bl0, bl1, bl2, bl3;
            ldsm4(smu + WQH, 68, n0, kp, bh0, bh1, bh2, bh3);
            ldsm4(smu + WQL, 68, n0, kp, bl0, bl1, bl2, bl3);
            mma_bf16(acc[0], ah0, ah1, ah2, ah3, bh0, bh2);
            mma_bf16(acc[0], ah0, ah1, ah2, ah3, bl0, bl2);
            mma_bf16(acc[0], al0, al1, al2, al3, bh0, bh2);
            mma_bf16(acc[1], ah0, ah1, ah2, ah3, bh1, bh3);
            mma_bf16(acc[1], ah0, ah1, ah2, ah3, bl1, bl3);
            mma_bf16(acc[1], al0, al1, al2, al3, bh1, bh3);
        }
        int r0 = m0 + g, r1 = r0 + 8;
        if (ch < 2) {
#pragma unroll
            for (int nt = 0; nt < 2; nt++) {
                int col0 = ch * 64 + n0 + nt * 8 + 2 * q;
                float b0c = qb[col0], b1c = qb[col0 + 1];
                int dp = col0 >> 1;
                split2(acc[nt][0] + b0c, acc[nt][1] + b1c,
                       smu[QSPH + r0 * 68 + dp], smu[QSPL + r0 * 68 + dp]);
                split2(acc[nt][2] + b0c, acc[nt][3] + b1c,
                       smu[QSPH + r1 * 68 + dp], smu[QSPL + r1 * 68 + dp]);
            }
        } else if (ch < 4) {
#pragma unroll
            for (int nt = 0; nt < 2; nt++) {
                int col0 = ch * 64 + n0 + nt * 8 + 2 * q;
                int dp = (col0 - 128) >> 1;
                split2(acc[nt][0], acc[nt][1],
                       smu[KSPH + r0 * 68 + dp], smu[KSPL + r0 * 68 + dp]);
                split2(acc[nt][2], acc[nt][3],
                       smu[KSPH + r1 * 68 + dp], smu[KSPL + r1 * 68 + dp]);
            }
        } else {
#pragma unroll
            for (int nt = 0; nt < 2; nt++) {
                int col0 = ch * 64 + n0 + nt * 8 + 2 * q;
                int d0 = col0 - 256;
                float v0 = acc[nt][0] + vb[d0], v1 = acc[nt][1] + vb[d0 + 1];
                float v2 = acc[nt][2] + vb[d0], v3 = acc[nt][3] + vb[d0 + 1];
                float p0 = __shfl_xor_sync(0xffffffffu, v0, 4);
                float p1 = __shfl_xor_sync(0xffffffffu, v1, 4);
                float p2 = __shfl_xor_sync(0xffffffffu, v2, 4);
                float p3 = __shfl_xor_sync(0xffffffffu, v3, 4);
                if (!(g & 1)) {
                    int up = (m0 + g) >> 1;
                    split2(v0, p0, smu[VSPH + d0 * 36 + up], smu[VSPL + d0 * 36 + up]);
                    split2(v1, p1, smu[VSPH + (d0 + 1) * 36 + up], smu[VSPL + (d0 + 1) * 36 + up]);
                } else {
                    int up = (m0 + g + 7) >> 1;
                    split2(p2, v2, smu[VSPH + d0 * 36 + up], smu[VSPL + d0 * 36 + up]);
                    split2(p3, v3, smu[VSPH + (d0 + 1) * 36 + up], smu[VSPL + (d0 + 1) * 36 + up]);
                }
            }
        }
    }
    __syncthreads();

    {
        int qk = tid >> 8, rem = tid & 255;
        int h = rem >> 6, t = rem & 63;
        int base = (qk ? KSPH : QSPH) + t * 68 + h * 16;
        int baseL = base + (QSPL - QSPH);
        float s = 0.f;
#pragma unroll
        for (int i = 0; i < 16; i++) {
            float2 fh = unpack2(smu[base + i]);
            float2 fl = unpack2(smu[baseL + i]);
            float a0 = fh.x + fl.x, a1 = fh.y + fl.y;
            s += a0 * a0 + a1 * a1;
        }
        sm[(qk ? IK_ : IQ_) + h * 64 + t] = 1.0f / fmaxf(sqrtf(s), 1e-12f);
    }
    __syncthreads();

    {
        int hw = wid >> 2;
        float scale = __expf(fminf(ls[hw], LOG100f));
        float acc[4][2][4];
#pragma unroll
        for (int i = 0; i < 4; i++)
#pragma unroll
            for (int j = 0; j < 2; j++)
#pragma unroll
                for (int k = 0; k < 4; k++) acc[i][j][k] = 0.f;
#pragma unroll
        for (int ks = 0; ks < 2; ks++) {
            int kp = hw * 16 + ks * 8;
            unsigned ah0, ah1, ah2, ah3, al0, al1, al2, al3;
            ldsm4(smu + QSPH, 68, m0, kp, ah0, ah1, ah2, ah3);
            ldsm4(smu + QSPL, 68, m0, kp, al0, al1, al2, al3);
#pragma unroll
            for (int nh = 0; nh < 4; nh++) {
                unsigned bh0, bh1, bh2, bh3, bl0, bl1, bl2, bl3;
                ldsm4(smu + KSPH, 68, nh * 16, kp, bh0, bh1, bh2, bh3);
                ldsm4(smu + KSPL, 68, nh * 16, kp, bl0, bl1, bl2, bl3);
                mma_bf16(acc[nh][0], ah0, ah1, ah2, ah3, bh0, bh2);
                mma_bf16(acc[nh][0], ah0, ah1, ah2, ah3, bl0, bl2);
                mma_bf16(acc[nh][0], al0, al1, al2, al3, bh0, bh2);
                mma_bf16(acc[nh][1], ah0, ah1, ah2, ah3, bh1, bh3);
                mma_bf16(acc[nh][1], ah0, ah1, ah2, ah3, bl1, bl3);
                mma_bf16(acc[nh][1], al0, al1, al2, al3, bh1, bh3);
            }
        }
        int r0 = m0 + g, r1 = r0 + 8;
        float iq0 = sm[IQ_ + hw * 64 + r0] * scale;
        float iq1 = sm[IQ_ + hw * 64 + r1] * scale;
        float rt0 = sm[RG_ + r0], rt1 = sm[RG_ + r1];
        float* A = &sm[ATTN_ + hw * 4352];
#pragma unroll
        for (int nh = 0; nh < 4; nh++)
#pragma unroll
            for (int nt = 0; nt < 2; nt++) {
                int col = nh * 16 + nt * 8 + 2 * q;
                float ik0 = sm[IK_ + hw * 64 + col], ik1 = sm[IK_ + hw * 64 + col + 1];
                float ru0 = sm[RG_ + col], ru1 = sm[RG_ + col + 1];
                float2 b0v = *(const float2*)&g_bias16[(hw * 64 + r0) * 64 + col];
                float2 b1v = *(const float2*)&g_bias16[(hw * 64 + r1) * 64 + col];
                A[r0 * 68 + col]     = acc[nh][nt][0] * iq0 * ik0 + b0v.x + (rt0 != ru0 ? -100.f : 0.f);
                A[r0 * 68 + col + 1] = acc[nh][nt][1] * iq0 * ik1 + b0v.y + (rt0 != ru1 ? -100.f : 0.f);
                A[r1 * 68 + col]     = acc[nh][nt][2] * iq1 * ik0 + b1v.x + (rt1 != ru0 ? -100.f : 0.f);
                A[r1 * 68 + col + 1] = acc[nh][nt][3] * iq1 * ik1 + b1v.y + (rt1 != ru1 ? -100.f : 0.f);
            }
    }
    __syncthreads();

    {
        int r = tid >> 1, half = tid & 1;
        int hw = r >> 6, t = r & 63;
        const float* row = &sm[ATTN_ + hw * 4352 + t * 68 + half * 32];
        float e[32];
        float mx = -1e30f;
#pragma unroll
        for (int i = 0; i < 32; i++) { e[i] = row[i]; mx = fmaxf(mx, e[i]); }
        mx = fmaxf(mx, __shfl_xor_sync(0xffffffffu, mx, 1));
        float s = 0.f;
#pragma unroll
        for (int i = 0; i < 32; i++) { e[i] = __expf(e[i] - mx); s += e[i]; }
        s += __shfl_xor_sync(0xffffffffu, s, 1);
        float inv = 1.0f / s;
        int pb_ = hw * 2304 + t * 36 + half * 16;
#pragma unroll
        for (int i = 0; i < 16; i++)
            split2(e[2 * i] * inv, e[2 * i + 1] * inv,
                   smu[PHI_ + pb_ + i], smu[PLO_ + pb_ + i]);
    }
    __syncthreads();

    {
        int hw = wid >> 2;
        const unsigned* PH = smu + PHI_ + hw * 2304;
        const unsigned* PL = smu + PLO_ + hw * 2304;
        float acc[2][2][4];
#pragma unroll
        for (int i = 0; i < 2; i++)
#pragma unroll
            for (int j = 0; j < 2; j++)
#pragma unroll
                for (int k = 0; k < 4; k++) acc[i][j][k] = 0.f;
#pragma unroll
        for (int ks = 0; ks < 4; ks++) {
            int kp = ks * 8;
            unsigned ah0, ah1, ah2, ah3, al0, al1, al2, al3;
            ldsm4(PH, 36, m0, kp, ah0, ah1, ah2, ah3);
            ldsm4(PL, 36, m0, kp, al0, al1, al2, al3);
#pragma unroll
            for (int nd = 0; nd < 2; nd++) {
                int n0v = hw * 32 + nd * 16;
                unsigned bh0, bh1, bh2, bh3, bl0, bl1, bl2, bl3;
                ldsm4(smu + VSPH, 36, n0v, kp, bh0, bh1, bh2, bh3);
                ldsm4(smu + VSPL, 36, n0v, kp, bl0, bl1, bl2, bl3);
                mma_bf16(acc[nd][0], ah0, ah1, ah2, ah3, bh0, bh2);
                mma_bf16(acc[nd][0], ah0, ah1, ah2, ah3, bl0, bl2);
                mma_bf16(acc[nd][0], al0, al1, al2, al3, bh0, bh2);
                mma_bf16(acc[nd][1], ah0, ah1, ah2, ah3, bh1, bh3);
                mma_bf16(acc[nd][1], ah0, ah1, ah2, ah3, bl1, bl3);
                mma_bf16(acc[nd][1], al0, al1, al2, al3, bh1, bh3);
            }
        }
        int r0 = m0 + g, r1 = r0 + 8;
#pragma unroll
        for (int nd = 0; nd < 2; nd++)
#pragma unroll
            for (int nt = 0; nt < 2; nt++) {
                int dglob = hw * 32 + nd * 16 + nt * 8 + 2 * q;
                int dp = dglob >> 1;
                split2(acc[nd][nt][0], acc[nd][nt][1],
                       smu[OHI_ + r0 * 68 + dp], smu[OLO_ + r0 * 68 + dp]);
                split2(acc[nd][nt][2], acc[nd][nt][3],
                       smu[OHI_ + r1 * 68 + dp], smu[OLO_ + r1 * 68 + dp]);
            }
    }

    for (int ch = 0; ch < 2; ch++) {
        __syncthreads();
#pragma unroll
        for (int it = 0; it < 8; it++) {
            int p = it * 512 + tid;
            int r = p >> 6, c = p & 63;
            smu[WPH + r * 68 + c] = g_pwh[(ch * 64 + r) * 64 + c];
            smu[WPL + r * 68 + c] = g_pwl[(ch * 64 + r) * 64 + c];
        }
        __syncthreads();
        float acc[2][4] = {};
#pragma unroll
        for (int ks = 0; ks < 8; ks++) {
            int kp = ks * 8;
            unsigned ah0, ah1, ah2, ah3, al0, al1, al2, al3;
            ldsm4(smu + OHI_, 68, m0, kp, ah0, ah1, ah2, ah3);
            ldsm4(smu + OLO_, 68, m0, kp, al0, al1, al2, al3);
            unsigned bh0, bh1, bh2, bh3, bl0, bl1, bl2, bl3;
            ldsm4(smu + WPH, 68, n0, kp, bh0, bh1, bh2, bh3);
            ldsm4(smu + WPL, 68, n0, kp, bl0, bl1, bl2, bl3);
            mma_bf16(acc[0], ah0, ah1, ah2, ah3, bh0, bh2);
            mma_bf16(acc[0], ah0, ah1, ah2, ah3, bl0, bl2);
            mma_bf16(acc[0], al0, al1, al2, al3, bh0, bh2);
            mma_bf16(acc[1], ah0, ah1, ah2, ah3, bh1, bh3);
            mma_bf16(acc[1], ah0, ah1, ah2, ah3, bl1, bl3);
            mma_bf16(acc[1], al0, al1, al2, al3, bh1, bh3);
        }
        int r0 = m0 + g, r1 = r0 + 8;
#pragma unroll
        for (int nt = 0; nt < 2; nt++) {
            int col0 = ch * 64 + n0 + nt * 8 + 2 * q;
            sm[POUT + r0 * 132 + col0]     = acc[nt][0] + pb[col0];
            sm[POUT + r0 * 132 + col0 + 1] = acc[nt][1] + pb[col0 + 1];
            sm[POUT + r1 * 132 + col0]     = acc[nt][2] + pb[col0];
            sm[POUT + r1 * 132 + col0 + 1] = acc[nt][3] + pb[col0 + 1];
        }
    }
    __syncthreads();

    {
        int t = tid >> 3, ln = tid & 7;
        const float* prow = &sm[POUT + t * 132];
        int cb = ln * 16;
        float s1 = 0.f, s2 = 0.f;
#pragma unroll
        for (int c = 0; c < 16; c++) {
            float v = prow[cb + c];
            s1 += v; s2 += v * v;
        }
        s1 += __shfl_xor_sync(0xffffffffu, s1, 1);
        s2 += __shfl_xor_sync(0xffffffffu, s2, 1);
        s1 += __shfl_xor_sync(0xffffffffu, s1, 2);
        s2 += __shfl_xor_sync(0xffffffffu, s2, 2);
        s1 += __shfl_xor_sync(0xffffffffu, s1, 4);
        s2 += __shfl_xor_sync(0xffffffffu, s2, 4);
        float mu = s1 * (1.0f / 128.0f);
        float var = fmaxf(s2 * (1.0f / 128.0f) - mu * mu, 0.0f);
        float rs = rsqrtf(var + 1e-5f);
        int ti = t >> 3, tj = t & 7;
        int hh = (wy * 8 + ti + 4) & 127;
        int ww = (wx * 8 + tj + 4) & 127;
        float* dst = &g_x1[((size_t)b * HW + hh * 128 + ww) * 128];
#pragma unroll
        for (int cp = 0; cp < 8; cp++) {
            unsigned uh = smu[XHI + t * 68 + ln * 8 + cp];
            unsigned ul = smu[XLO + t * 68 + ln * 8 + cp];
            float2 fh = unpack2(uh), fl = unpack2(ul);
            int cc = cb + 2 * cp;
            float l0 = (prow[cc] - mu) * rs * n1w[cc] + n1b[cc];
            float l1 = (prow[cc + 1] - mu) * rs * n1w[cc + 1] + n1b[cc + 1];
            dst[cc]     = fh.x + fl.x + l0;
            dst[cc + 1] = fh.y + fl.y + l1;
        }
    }
}

// ------------------- K2: MLP (R8 tiling + cp.async pipelining) --------------
// words: X [128][68]x2 | W1 bufs x2 (each hi+lo [64][68]) | W2 hi+lo [128][36] | H hi+lo [128][36]
#define K2XHI 0        // ends 8704
#define K2XLO 8704     // ends 17408
#define K2W1  17408    // 2 bufs * 8704 -> ends 34816 (buf: hi 4352 + lo 4352)
#define K2W2H 34816    // ends 39424
#define K2W2L 39424    // ends 44032
#define K2HH  44032    // ends 48640
#define K2HL  48640    // ends 53248
#define K2Y   17408    // [128][133] = 17024 words, aliases W1 bufs (dead after loop)
#define K2_SMEM (53248 * 4)   // 212992 bytes

__global__ void __launch_bounds__(512, 1)
k2_mlp(const float* __restrict__ n2w, const float* __restrict__ n2b,
       const float* __restrict__ b1, const float* __restrict__ b2,
       float* __restrict__ out) {
    extern __shared__ float sm[];
    unsigned* smu = (unsigned*)sm;
    int tid = threadIdx.x;
    int wid = tid >> 5, lane = tid & 31;
    int g = lane >> 2, q = lane & 3;
    int p0 = blockIdx.x * 128;
    int b = p0 >> 14, h = (p0 >> 7) & 127;

    // prologue: async-stage W1 chunk 0 into buf 0
    {
        // hi: 1024 x 16B ops, lo: 1024 -> 4 per thread
#pragma unroll
        for (int it = 0; it < 2; it++) {
            int o = it * 512 + tid;          // 0..1023
            int r = o >> 4, cq = (o & 15) << 2;
            cpa16(&smu[K2W1 + r * 68 + cq], &g_f1h[r * 64 + cq]);
            cpa16(&smu[K2W1 + 4352 + r * 68 + cq], &g_f1l[r * 64 + cq]);
        }
        CP_COMMIT();
    }

    // load + split x1 (128 tokens) — overlaps the W1 prefetch
#pragma unroll
    for (int it = 0; it < 16; it++) {
        int idx = it * 512 + tid;
        int cp = idx & 63, t = idx >> 6;
        float2 v = *(const float2*)&g_x1[((size_t)p0 + t) * 128 + 2 * cp];
        split2(v.x, v.y, smu[K2XHI + t * 68 + cp], smu[K2XLO + t * 68 + cp]);
    }

    int mi = wid & 7, nh = wid >> 3;   // 8 x 2 warp grid
    int m0 = mi * 16;
    int n0w = nh * 32;
    float acc2[8][4];
#pragma unroll
    for (int t = 0; t < 8; t++)
#pragma unroll
        for (int j = 0; j < 4; j++) acc2[t][j] = 0.f;

    for (int ch = 0; ch < 8; ch++) {
        int cur = ch & 1, nxt = cur ^ 1;
        const unsigned* W1H = smu + K2W1 + cur * 8704;
        const unsigned* W1L = W1H + 4352;
        CP_WAIT0();
        __syncthreads();                    // W1[cur] ready; W2/H free
        // async-stage W2 k-slice [128][32] hi+lo (overlaps fc1)
#pragma unroll
        for (int it = 0; it < 2; it++) {
            int o = it * 512 + tid;         // 0..1023
            int r = o >> 3, cq = (o & 7) << 2;
            cpa16(&smu[K2W2H + r * 36 + cq], &g_f2h[r * 256 + ch * 32 + cq]);
            cpa16(&smu[K2W2L + r * 36 + cq], &g_f2l[r * 256 + ch * 32 + cq]);
        }
        CP_COMMIT();
        // fc1 chunk: warp m16 x n32
        float acc[4][4] = {};
#pragma unroll
        for (int ks = 0; ks < 8; ks++) {
            int kp = ks * 8;
            unsigned ah0, ah1, ah2, ah3, al0, al1, al2, al3;
            ldsm4(smu + K2XHI, 68, m0, kp, ah0, ah1, ah2, ah3);
            ldsm4(smu + K2XLO, 68, m0, kp, al0, al1, al2, al3);
#pragma unroll
            for (int hf = 0; hf < 2; hf++) {
                unsigned bh0, bh1, bh2, bh3, bl0, bl1, bl2, bl3;
                ldsm4(W1H, 68, n0w + 16 * hf, kp, bh0, bh1, bh2, bh3);
                ldsm4(W1L, 68, n0w + 16 * hf, kp, bl0, bl1, bl2, bl3);
                mma_bf16(acc[2 * hf],     ah0, ah1, ah2, ah3, bh0, bh2);
                mma_bf16(acc[2 * hf],     ah0, ah1, ah2, ah3, bl0, bl2);
                mma_bf16(acc[2 * hf],     al0, al1, al2, al3, bh0, bh2);
                mma_bf16(acc[2 * hf + 1], ah0, ah1, ah2, ah3, bh1, bh3);
                mma_bf16(acc[2 * hf + 1], ah0, ah1, ah2, ah3, bl1, bl3);
                mma_bf16(acc[2 * hf + 1], al0, al1, al2, al3, bh1, bh3);
            }
        }
        // silu + split -> H [t][hpair] pitch 36
#pragma unroll
        for (int nt = 0; nt < 4; nt++) {
            int c0 = n0w + nt * 8 + 2 * q;
            int col = ch * 64 + c0;
            float v0 = acc[nt][0] + b1[col],     v1 = acc[nt][1] + b1[col + 1];
            float v2 = acc[nt][2] + b1[col],     v3 = acc[nt][3] + b1[col + 1];
            v0 = v0 / (1.0f + __expf(-v0));
            v1 = v1 / (1.0f + __expf(-v1));
            v2 = v2 / (1.0f + __expf(-v2));
            v3 = v3 / (1.0f + __expf(-v3));
            int pp = (c0 >> 1);
            split2(v0, v1, smu[K2HH + (m0 + g) * 36 + pp], smu[K2HL + (m0 + g) * 36 + pp]);
            split2(v2, v3, smu[K2HH + (m0 + g + 8) * 36 + pp], smu[K2HL + (m0 + g + 8) * 36 + pp]);
        }
        CP_WAIT0();
        __syncthreads();                    // W2 + H ready
        // async-stage W1 for next chunk (overlaps fc2)
        if (ch < 7) {
#pragma unroll
            for (int it = 0; it < 2; it++) {
                int o = it * 512 + tid;
                int r = o >> 4, cq = (o & 15) << 2;
                cpa16(&smu[K2W1 + nxt * 8704 + r * 68 + cq],
                      &g_f1h[((ch + 1) * 64 + r) * 64 + cq]);
                cpa16(&smu[K2W1 + nxt * 8704 + 4352 + r * 68 + cq],
                      &g_f1l[((ch + 1) * 64 + r) * 64 + cq]);
            }
        }
        CP_COMMIT();
        // fc2 partial: warp m16 x n64
#pragma unroll
        for (int ks = 0; ks < 4; ks++) {
            int kp = ks * 8;
            unsigned ah0, ah1, ah2, ah3, al0, al1, al2, al3;
            ldsm4(smu + K2HH, 36, m0, kp, ah0, ah1, ah2, ah3);
            ldsm4(smu + K2HL, 36, m0, kp, al0, al1, al2, al3);
#pragma unroll
            for (int tp = 0; tp < 4; tp++) {
                unsigned bh0, bh1, bh2, bh3, bl0, bl1, bl2, bl3;
                ldsm4(smu + K2W2H, 36, nh * 64 + 16 * tp, kp, bh0, bh1, bh2, bh3);
                ldsm4(smu + K2W2L, 36, nh * 64 + 16 * tp, kp, bl0, bl1, bl2, bl3);
                mma_bf16(acc2[2 * tp],     ah0, ah1, ah2, ah3, bh0, bh2);
                mma_bf16(acc2[2 * tp],     ah0, ah1, ah2, ah3, bl0, bl2);
                mma_bf16(acc2[2 * tp],     al0, al1, al2, al3, bh0, bh2);
                mma_bf16(acc2[2 * tp + 1], ah0, ah1, ah2, ah3, bh1, bh3);
                mma_bf16(acc2[2 * tp + 1], ah0, ah1, ah2, ah3, bl1, bl3);
                mma_bf16(acc2[2 * tp + 1], al0, al1, al2, al3, bh1, bh3);
            }
        }
    }
    CP_WAIT0();
    __syncthreads();   // W1/W2/H dead; Y aliases W1 bufs
    // Y = fc2 out + bias
#pragma unroll
    for (int t = 0; t < 8; t++) {
        int col = nh * 64 + t * 8 + 2 * q;
        sm[K2Y + (m0 + g) * 133 + col]         = acc2[t][0] + b2[col];
        sm[K2Y + (m0 + g) * 133 + col + 1]     = acc2[t][1] + b2[col + 1];
        sm[K2Y + (m0 + g + 8) * 133 + col]     = acc2[t][2] + b2[col];
        sm[K2Y + (m0 + g + 8) * 133 + col + 1] = acc2[t][3] + b2[col + 1];
    }
    __syncthreads();
    // LN + residual (x1 = hi + lo), 4 threads/row
    {
        int t = tid >> 2, ln = tid & 3;
        float* yrow = &sm[K2Y + t * 133];
        int cb = ln * 32;
        float s1 = 0.f, s2 = 0.f;
#pragma unroll 8
        for (int c = 0; c < 32; c++) {
            float v = yrow[cb + c];
            s1 += v; s2 += v * v;
        }
        s1 += __shfl_xor_sync(0xffffffffu, s1, 1);
        s2 += __shfl_xor_sync(0xffffffffu, s2, 1);
        s1 += __shfl_xor_sync(0xffffffffu, s1, 2);
        s2 += __shfl_xor_sync(0xffffffffu, s2, 2);
        float mu = s1 * (1.0f / 128.0f);
        float var = fmaxf(s2 * (1.0f / 128.0f) - mu * mu, 0.0f);
        float rs = rsqrtf(var + 1e-5f);
#pragma unroll 8
        for (int cp = 0; cp < 16; cp++) {
            unsigned uh = smu[K2XHI + t * 68 + (cb >> 1) + cp];
            unsigned ul = smu[K2XLO + t * 68 + (cb >> 1) + cp];
            float2 fh = unpack2(uh), fl = unpack2(ul);
            int cc = cb + 2 * cp;
            float l0 = (yrow[cc] - mu) * rs * n2w[cc] + n2b[cc];
            float l1 = (yrow[cc + 1] - mu) * rs * n2w[cc + 1] + n2b[cc + 1];
            yrow[cc]     = fh.x + fl.x + l0;
            yrow[cc + 1] = fh.y + fl.y + l1;
        }
    }
    __syncthreads();
    // transposed store -> NCHW (128 tokens = full image row h)
    {
        float* ob = out + (size_t)b * 128 * HW + h * 128;
#pragma unroll
        for (int it = 0; it < 32; it++) {
            int idx = it * 512 + tid;
            int c = idx >> 7, w = idx & 127;
            ob[(size_t)c * HW + w] = sm[K2Y + w * 133 + c];
        }
    }
}

// ------------------------------ launch --------------------------------------
extern "C" void kernel_launch(void* const* d_in, const int* in_sizes, int n_in,
                              void* d_out, int out_size) {
    const float* x    = (const float*)d_in[0];
    const float* n1w  = (const float*)d_in[1];
    const float* n1b  = (const float*)d_in[2];
    const float* qkvw = (const float*)d_in[3];
    const float* qb   = (const float*)d_in[4];
    const float* vb   = (const float*)d_in[5];
    const float* ls   = (const float*)d_in[6];
    const float* cw1  = (const float*)d_in[7];
    const float* cb1  = (const float*)d_in[8];
    const float* cw2  = (const float*)d_in[9];
    const float* pw   = (const float*)d_in[10];
    const float* pb   = (const float*)d_in[11];
    const float* n2w  = (const float*)d_in[12];
    const float* n2b  = (const float*)d_in[13];
    const float* f1w  = (const float*)d_in[14];
    const float* f1b  = (const float*)d_in[15];
    const float* f2w  = (const float*)d_in[16];
    const float* f2b  = (const float*)d_in[17];
    float* out = (float*)d_out;

    cudaFuncSetAttribute(k1_attn, cudaFuncAttributeMaxDynamicSharedMemorySize, K1_SMEM);
    cudaFuncSetAttribute(k2_mlp,  cudaFuncAttributeMaxDynamicSharedMemorySize, K2_SMEM);

    k0_bias<<<1, 256>>>(cw1, cb1, cw2);
    k0_wsplit<<<384, 256>>>(qkvw, pw, f1w, f2w);
    k1_attn<<<4096, 512, K1_SMEM>>>(x, n1w, n1b, qb, vb, ls, pb);
    k2_mlp<<<2048, 512, K2_SMEM>>>(n2w, n2b, f1b, f2b, out);
}

// round 12
// speedup vs baseline: 1.0715x; 1.0424x over previous
#include <cuda_runtime.h>
#include <cuda_bf16.h>
#include <math.h>

#define HW 16384
#define LOG100f 4.605170185988092f

__device__ float g_x1[16u * HW * 128u];
__device__ float g_bias16[4 * 64 * 64];
__device__ unsigned g_qkvh[24576], g_qkvl[24576];   // [384][64]
__device__ unsigned g_pwh[8192],   g_pwl[8192];     // [128][64]
__device__ unsigned g_f1h[32768],  g_f1l[32768];    // [512][64]
__device__ unsigned g_f2h[32768],  g_f2l[32768];    // [128][256]

// ---------------------------------------------------------------------------
__device__ __forceinline__ void mma_bf16(float d[4], unsigned a0, unsigned a1,
                                         unsigned a2, unsigned a3,
                                         unsigned b0, unsigned b1) {
    asm volatile(
        "mma.sync.aligned.m16n8k16.row.col.f32.bf16.bf16.f32 "
        "{%0,%1,%2,%3},{%4,%5,%6,%7},{%8,%9},{%0,%1,%2,%3};"
        : "+f"(d[0]), "+f"(d[1]), "+f"(d[2]), "+f"(d[3])
        : "r"(a0), "r"(a1), "r"(a2), "r"(a3), "r"(b0), "r"(b1));
}

__device__ __forceinline__ void ldsm4(const unsigned* base, int P, int r0, int kp,
                                      unsigned& o0, unsigned& o1, unsigned& o2, unsigned& o3) {
    int lane = threadIdx.x & 31;
    const unsigned* p = base + (r0 + (lane & 15)) * P + kp + ((lane >> 4) << 2);
    unsigned a = (unsigned)__cvta_generic_to_shared(p);
    asm volatile("ldmatrix.sync.aligned.m8n8.x4.shared.b16 {%0,%1,%2,%3}, [%4];"
                 : "=r"(o0), "=r"(o1), "=r"(o2), "=r"(o3) : "r"(a));
}

__device__ __forceinline__ void cpa16(unsigned* dst, const unsigned* src) {
    unsigned d = (unsigned)__cvta_generic_to_shared(dst);
    asm volatile("cp.async.cg.shared.global [%0], [%1], 16;" :: "r"(d), "l"(src));
}
#define CP_COMMIT() asm volatile("cp.async.commit_group;" ::: "memory")
#define CP_WAIT0()  asm volatile("cp.async.wait_group 0;" ::: "memory")

__device__ __forceinline__ void split2(float v0, float v1, unsigned& hi, unsigned& lo) {
    __nv_bfloat16 h0 = __float2bfloat16(v0);
    __nv_bfloat16 h1 = __float2bfloat16(v1);
    float r0 = v0 - __bfloat162float(h0);
    float r1 = v1 - __bfloat162float(h1);
    __nv_bfloat16 l0 = __float2bfloat16(r0);
    __nv_bfloat16 l1 = __float2bfloat16(r1);
    hi = (unsigned)__bfloat16_as_ushort(h0) | ((unsigned)__bfloat16_as_ushort(h1) << 16);
    lo = (unsigned)__bfloat16_as_ushort(l0) | ((unsigned)__bfloat16_as_ushort(l1) << 16);
}

__device__ __forceinline__ float2 unpack2(unsigned u) {
    __nv_bfloat162 b = *reinterpret_cast<__nv_bfloat162*>(&u);
    return __bfloat1622float2(b);
}

// ------------------------------ K0 ------------------------------------------
__global__ void k0_bias(const float* __restrict__ w1, const float* __restrict__ b1,
                        const float* __restrict__ w2) {
    __shared__ float tab[225][4];
    int tid = threadIdx.x;
    if (tid < 225) {
        int a = tid / 15, bb = tid % 15;
        float v0 = (a - 7) * (8.0f / 7.0f), v1 = (bb - 7) * (8.0f / 7.0f);
        float g0 = copysignf(log2f(fabsf(v0) + 1.0f) * (1.0f / 3.0f), v0);
        float g1 = copysignf(log2f(fabsf(v1) + 1.0f) * (1.0f / 3.0f), v1);
        float o0 = 0, o1 = 0, o2 = 0, o3 = 0;
        for (int j = 0; j < 512; j++) {
            float hv = fmaxf(w1[2 * j] * g0 + w1[2 * j + 1] * g1 + b1[j], 0.0f);
            o0 += hv * w2[j];        o1 += hv * w2[512 + j];
            o2 += hv * w2[1024 + j]; o3 += hv * w2[1536 + j];
        }
        tab[tid][0] = o0; tab[tid][1] = o1; tab[tid][2] = o2; tab[tid][3] = o3;
    }
    __syncthreads();
    for (int e = tid; e < 4 * 64 * 64; e += blockDim.x) {
        int h = e >> 12, i = (e >> 6) & 63, j = e & 63;
        int dy = (i >> 3) - (j >> 3) + 7, dx = (i & 7) - (j & 7) + 7;
        float v = tab[dy * 15 + dx][h];
        g_bias16[e] = 16.0f / (1.0f + expf(-v));
    }
}

__device__ __forceinline__ void splitpair(const float* w, unsigned* hi, unsigned* lo, int i) {
    split2(w[2 * i], w[2 * i + 1], hi[i], lo[i]);
}

__global__ void k0_wsplit(const float* __restrict__ qkvw, const float* __restrict__ pw,
                          const float* __restrict__ f1w, const float* __restrict__ f2w) {
    int i = blockIdx.x * 256 + threadIdx.x;
    if (i < 24576)       splitpair(qkvw, g_qkvh, g_qkvl, i);
    else if (i < 32768)  splitpair(pw,  g_pwh,  g_pwl,  i - 24576);
    else if (i < 65536)  splitpair(f1w, g_f1h,  g_f1l,  i - 32768);
    else if (i < 98304)  splitpair(f2w, g_f2h,  g_f2l,  i - 65536);
}

// ------------------------------ K1: attention (1024 thr) --------------------
#define XHI   0        // [64][68]
#define XLO   4352
#define QSPH  8704     // [64][68]
#define QSPL  13056
#define KSPH  17408
#define KSPL  21760    // ends 26112
#define PHI_  8704     // P [4][64][36] = 9216 over dead QSP
#define PLO_  17920    // ends 27136
#define WPH   8704     // proj wstage [128][68] over dead P
#define WPL   17408    // ends 26112
#define VSPH  27136    // [128][36]
#define VSPL  31744    // ends 36352
#define WQH   36352    // qkv wstage [128][68]
#define WQL   45056    // ends 53760
#define ATTN_ 36352    // [4][64][68] = 17408 over dead WQ, ends 53760
#define OHI_  36352    // [64][68] over dead ATTN h0-1
#define OLO_  40704    // ends 45056
#define POUT  45056    // [64][132] = 8448 over dead ATTN h2-3 / WQL
#define RG_   53760
#define IQ_   53824
#define IK_   54080
#define K1_SMEM (54336 * 4)

__global__ void __launch_bounds__(1024, 1)
k1_attn(const float* __restrict__ x,
        const float* __restrict__ n1w, const float* __restrict__ n1b,
        const float* __restrict__ qb, const float* __restrict__ vb,
        const float* __restrict__ ls, const float* __restrict__ pb) {
    extern __shared__ float sm[];
    unsigned* smu = (unsigned*)sm;
    int tid = threadIdx.x;
    int wid = tid >> 5, lane = tid & 31;
    int g = lane >> 2, q = lane & 3;
    int b = blockIdx.x >> 8, widx = blockIdx.x & 255;
    int wy = widx >> 4, wx = widx & 15;

    // phase 0: gather shifted window -> split [t][cpair]
    {
        const float* xb = x + (size_t)b * 128 * HW;
#pragma unroll
        for (int it = 0; it < 4; it++) {              // 4*1024 = 4096
            int idx = it * 1024 + tid;
            int t = idx & 63, cp = idx >> 6;
            int ti = t >> 3, tj = t & 7;
            int hh = (wy * 8 + ti + 4) & 127;
            int ww = (wx * 8 + tj + 4) & 127;
            const float* p = xb + (size_t)(2 * cp) * HW + hh * 128 + ww;
            float v0 = p[0], v1 = p[HW];
            split2(v0, v1, smu[XHI + t * 68 + cp], smu[XLO + t * 68 + cp]);
        }
        if (tid < 64) {
            int ti = tid >> 3, tj = tid & 7;
            int hs = wy * 8 + ti, ws = wx * 8 + tj;
            int hr = hs < 120 ? 0 : (hs < 124 ? 1 : 2);
            int wr = ws < 120 ? 0 : (ws < 124 ? 1 : 2);
            sm[RG_ + tid] = (float)(hr * 3 + wr);
        }
    }

    int mi = wid & 3;
    int m0 = mi * 16;

    // phase 1: QKV GEMM, 3 chunks of 128 cols, 4 mi x 8 nw warps
    {
        int nw = wid >> 2;
        int n0 = nw * 16;
        for (int ch = 0; ch < 3; ch++) {
            __syncthreads();
#pragma unroll
            for (int it = 0; it < 8; it++) {          // 8*1024 = 8192 = 128*64
                int p = it * 1024 + tid;
                int r = p >> 6, c = p & 63;
                smu[WQH + r * 68 + c] = g_qkvh[(ch * 128 + r) * 64 + c];
                smu[WQL + r * 68 + c] = g_qkvl[(ch * 128 + r) * 64 + c];
            }
            __syncthreads();
            float acc[2][4] = {};
#pragma unroll
            for (int ks = 0; ks < 8; ks++) {
                int kp = ks * 8;
                unsigned ah0, ah1, ah2, ah3, al0, al1, al2, al3;
                ldsm4(smu + XHI, 68, m0, kp, ah0, ah1, ah2, ah3);
                ldsm4(smu + XLO, 68, m0, kp, al0, al1, al2, al3);
                unsigned bh0, bh1, bh2, bh3, bl0, bl1, bl2, bl3;
                ldsm4(smu + WQH, 68, n0, kp, bh0, bh1, bh2, bh3);
                ldsm4(smu + WQL, 68, n0, kp, bl0, bl1, bl2, bl3);
                mma_bf16(acc[0], ah0, ah1, ah2, ah3, bh0, bh2);
                mma_bf16(acc[0], ah0, ah1, ah2, ah3, bl0, bl2);
                mma_bf16(acc[0], al0, al1, al2, al3, bh0, bh2);
                mma_bf16(acc[1], ah0, ah1, ah2, ah3, bh1, bh3);
                mma_bf16(acc[1], ah0, ah1, ah2, ah3, bl1, bl3);
                mma_bf16(acc[1], al0, al1, al2, al3, bh1, bh3);
            }
            int r0 = m0 + g, r1 = r0 + 8;
            if (ch == 0) {          // Q
#pragma unroll
                for (int nt = 0; nt < 2; nt++) {
                    int col0 = n0 + nt * 8 + 2 * q;
                    float b0c = qb[col0], b1c = qb[col0 + 1];
                    int dp = col0 >> 1;
                    split2(acc[nt][0] + b0c, acc[nt][1] + b1c,
                           smu[QSPH + r0 * 68 + dp], smu[QSPL + r0 * 68 + dp]);
                    split2(acc[nt][2] + b0c, acc[nt][3] + b1c,
                           smu[QSPH + r1 * 68 + dp], smu[QSPL + r1 * 68 + dp]);
                }
            } else if (ch == 1) {   // K
#pragma unroll
                for (int nt = 0; nt < 2; nt++) {
                    int col0 = n0 + nt * 8 + 2 * q;
                    int dp = col0 >> 1;
                    split2(acc[nt][0], acc[nt][1],
                           smu[KSPH + r0 * 68 + dp], smu[KSPL + r0 * 68 + dp]);
                    split2(acc[nt][2], acc[nt][3],
                           smu[KSPH + r1 * 68 + dp], smu[KSPL + r1 * 68 + dp]);
                }
            } else {                // V -> [d][upair] via lane exchange
#pragma unroll
                for (int nt = 0; nt < 2; nt++) {
                    int d0 = n0 + nt * 8 + 2 * q;
                    float v0 = acc[nt][0] + vb[d0], v1 = acc[nt][1] + vb[d0 + 1];
                    float v2 = acc[nt][2] + vb[d0], v3 = acc[nt][3] + vb[d0 + 1];
                    float p0 = __shfl_xor_sync(0xffffffffu, v0, 4);
                    float p1 = __shfl_xor_sync(0xffffffffu, v1, 4);
                    float p2 = __shfl_xor_sync(0xffffffffu, v2, 4);
                    float p3 = __shfl_xor_sync(0xffffffffu, v3, 4);
                    if (!(g & 1)) {
                        int up = (m0 + g) >> 1;
                        split2(v0, p0, smu[VSPH + d0 * 36 + up], smu[VSPL + d0 * 36 + up]);
                        split2(v1, p1, smu[VSPH + (d0 + 1) * 36 + up], smu[VSPL + (d0 + 1) * 36 + up]);
                    } else {
                        int up = (m0 + g + 7) >> 1;
                        split2(p2, v2, smu[VSPH + d0 * 36 + up], smu[VSPL + d0 * 36 + up]);
                        split2(p3, v3, smu[VSPH + (d0 + 1) * 36 + up], smu[VSPL + (d0 + 1) * 36 + up]);
                    }
                }
            }
        }
    }
    __syncthreads();

    // phase 2: inverse norms (1024 = 2 qk * 4 h * 64 t * 2 half)
    {
        int qk = tid >> 9, rem = tid & 511;
        int h = rem >> 7, sub = rem & 127;
        int t = sub >> 1, half = sub & 1;
        int base = (qk ? KSPH : QSPH) + t * 68 + h * 16 + half * 8;
        int baseL = base + 4352;
        float s = 0.f;
#pragma unroll
        for (int i = 0; i < 8; i++) {
            float2 fh = unpack2(smu[base + i]);
            float2 fl = unpack2(smu[baseL + i]);
            float a0 = fh.x + fl.x, a1 = fh.y + fl.y;
            s += a0 * a0 + a1 * a1;
        }
        s += __shfl_xor_sync(0xffffffffu, s, 1);
        if (half == 0)
            sm[(qk ? IK_ : IQ_) + h * 64 + t] = 1.0f / fmaxf(sqrtf(s), 1e-12f);
    }
    __syncthreads();

    // phase 3: logits MMA. 32 warps = 4 hw * 2 nhalf * 4 mi
    {
        int hw = wid >> 3, nhalf = (wid >> 2) & 1;
        float scale = __expf(fminf(ls[hw], LOG100f));
        float acc[2][2][4];
#pragma unroll
        for (int i = 0; i < 2; i++)
#pragma unroll
            for (int j = 0; j < 2; j++)
#pragma unroll
                for (int k = 0; k < 4; k++) acc[i][j][k] = 0.f;
#pragma unroll
        for (int ks = 0; ks < 2; ks++) {
            int kp = hw * 16 + ks * 8;
            unsigned ah0, ah1, ah2, ah3, al0, al1, al2, al3;
            ldsm4(smu + QSPH, 68, m0, kp, ah0, ah1, ah2, ah3);
            ldsm4(smu + QSPL, 68, m0, kp, al0, al1, al2, al3);
#pragma unroll
            for (int nh = 0; nh < 2; nh++) {
                int nr = nhalf * 32 + nh * 16;
                unsigned bh0, bh1, bh2, bh3, bl0, bl1, bl2, bl3;
                ldsm4(smu + KSPH, 68, nr, kp, bh0, bh1, bh2, bh3);
                ldsm4(smu + KSPL, 68, nr, kp, bl0, bl1, bl2, bl3);
                mma_bf16(acc[nh][0], ah0, ah1, ah2, ah3, bh0, bh2);
                mma_bf16(acc[nh][0], ah0, ah1, ah2, ah3, bl0, bl2);
                mma_bf16(acc[nh][0], al0, al1, al2, al3, bh0, bh2);
                mma_bf16(acc[nh][1], ah0, ah1, ah2, ah3, bh1, bh3);
                mma_bf16(acc[nh][1], ah0, ah1, ah2, ah3, bl1, bl3);
                mma_bf16(acc[nh][1], al0, al1, al2, al3, bh1, bh3);
            }
        }
        int r0 = m0 + g, r1 = r0 + 8;
        float iq0 = sm[IQ_ + hw * 64 + r0] * scale;
        float iq1 = sm[IQ_ + hw * 64 + r1] * scale;
        float rt0 = sm[RG_ + r0], rt1 = sm[RG_ + r1];
        float* A = &sm[ATTN_ + hw * 4352];
#pragma unroll
        for (int nh = 0; nh < 2; nh++)
#pragma unroll
            for (int nt = 0; nt < 2; nt++) {
                int col = nhalf * 32 + nh * 16 + nt * 8 + 2 * q;
                float ik0 = sm[IK_ + hw * 64 + col], ik1 = sm[IK_ + hw * 64 + col + 1];
                float ru0 = sm[RG_ + col], ru1 = sm[RG_ + col + 1];
                float2 b0v = *(const float2*)&g_bias16[(hw * 64 + r0) * 64 + col];
                float2 b1v = *(const float2*)&g_bias16[(hw * 64 + r1) * 64 + col];
                A[r0 * 68 + col]     = acc[nh][nt][0] * iq0 * ik0 + b0v.x + (rt0 != ru0 ? -100.f : 0.f);
                A[r0 * 68 + col + 1] = acc[nh][nt][1] * iq0 * ik1 + b0v.y + (rt0 != ru1 ? -100.f : 0.f);
                A[r1 * 68 + col]     = acc[nh][nt][2] * iq1 * ik0 + b1v.x + (rt1 != ru0 ? -100.f : 0.f);
                A[r1 * 68 + col + 1] = acc[nh][nt][3] * iq1 * ik1 + b1v.y + (rt1 != ru1 ? -100.f : 0.f);
            }
    }
    __syncthreads();

    // phase 4: softmax, 256 rows, 4 threads/row -> P splits [h][t][upair]
    {
        int r = tid >> 2, qt = tid & 3;
        int hw = r >> 6, t = r & 63;
        const float* row = &sm[ATTN_ + hw * 4352 + t * 68 + qt * 16];
        float e[16];
        float mx = -1e30f;
#pragma unroll
        for (int i = 0; i < 16; i++) { e[i] = row[i]; mx = fmaxf(mx, e[i]); }
        mx = fmaxf(mx, __shfl_xor_sync(0xffffffffu, mx, 1));
        mx = fmaxf(mx, __shfl_xor_sync(0xffffffffu, mx, 2));
        float s = 0.f;
#pragma unroll
        for (int i = 0; i < 16; i++) { e[i] = __expf(e[i] - mx); s += e[i]; }
        s += __shfl_xor_sync(0xffffffffu, s, 1);
        s += __shfl_xor_sync(0xffffffffu, s, 2);
        float inv = 1.0f / s;
        int pb_ = hw * 2304 + t * 36 + qt * 8;
#pragma unroll
        for (int i = 0; i < 8; i++)
            split2(e[2 * i] * inv, e[2 * i + 1] * inv,
                   smu[PHI_ + pb_ + i], smu[PLO_ + pb_ + i]);
    }
    __syncthreads();

    // phase 5: PV MMA. 32 warps = 4 hw * 2 nd * 4 mi, m16 x n16 each
    {
        int hw = wid >> 3, nd = (wid >> 2) & 1;
        const unsigned* PH = smu + PHI_ + hw * 2304;
        const unsigned* PL = smu + PLO_ + hw * 2304;
        float acc[2][4] = {};
#pragma unroll
        for (int ks = 0; ks < 4; ks++) {
            int kp = ks * 8;
            unsigned ah0, ah1, ah2, ah3, al0, al1, al2, al3;
            ldsm4(PH, 36, m0, kp, ah0, ah1, ah2, ah3);
            ldsm4(PL, 36, m0, kp, al0, al1, al2, al3);
            int n0v = hw * 32 + nd * 16;
            unsigned bh0, bh1, bh2, bh3, bl0, bl1, bl2, bl3;
            ldsm4(smu + VSPH, 36, n0v, kp, bh0, bh1, bh2, bh3);
            ldsm4(smu + VSPL, 36, n0v, kp, bl0, bl1, bl2, bl3);
            mma_bf16(acc[0], ah0, ah1, ah2, ah3, bh0, bh2);
            mma_bf16(acc[0], ah0, ah1, ah2, ah3, bl0, bl2);
            mma_bf16(acc[0], al0, al1, al2, al3, bh0, bh2);
            mma_bf16(acc[1], ah0, ah1, ah2, ah3, bh1, bh3);
            mma_bf16(acc[1], ah0, ah1, ah2, ah3, bl1, bl3);
            mma_bf16(acc[1], al0, al1, al2, al3, bh1, bh3);
        }
        int r0 = m0 + g, r1 = r0 + 8;
#pragma unroll
        for (int nt = 0; nt < 2; nt++) {
            int dglob = hw * 32 + nd * 16 + nt * 8 + 2 * q;
            int dp = dglob >> 1;
            split2(acc[nt][0], acc[nt][1],
                   smu[OHI_ + r0 * 68 + dp], smu[OLO_ + r0 * 68 + dp]);
            split2(acc[nt][2], acc[nt][3],
                   smu[OHI_ + r1 * 68 + dp], smu[OLO_ + r1 * 68 + dp]);
        }
    }

    // phase 6: proj GEMM, single 128-col chunk, 4 mi x 8 nw
    {
        int nw = wid >> 2;
        int n0 = nw * 16;
        __syncthreads();
#pragma unroll
        for (int it = 0; it < 8; it++) {
            int p = it * 1024 + tid;
            int r = p >> 6, c = p & 63;
            smu[WPH + r * 68 + c] = g_pwh[r * 64 + c];
            smu[WPL + r * 68 + c] = g_pwl[r * 64 + c];
        }
        __syncthreads();
        float acc[2][4] = {};
#pragma unroll
        for (int ks = 0; ks < 8; ks++) {
            int kp = ks * 8;
            unsigned ah0, ah1, ah2, ah3, al0, al1, al2, al3;
            ldsm4(smu + OHI_, 68, m0, kp, ah0, ah1, ah2, ah3);
            ldsm4(smu + OLO_, 68, m0, kp, al0, al1, al2, al3);
            unsigned bh0, bh1, bh2, bh3, bl0, bl1, bl2, bl3;
            ldsm4(smu + WPH, 68, n0, kp, bh0, bh1, bh2, bh3);
            ldsm4(smu + WPL, 68, n0, kp, bl0, bl1, bl2, bl3);
            mma_bf16(acc[0], ah0, ah1, ah2, ah3, bh0, bh2);
            mma_bf16(acc[0], ah0, ah1, ah2, ah3, bl0, bl2);
            mma_bf16(acc[0], al0, al1, al2, al3, bh0, bh2);
            mma_bf16(acc[1], ah0, ah1, ah2, ah3, bh1, bh3);
            mma_bf16(acc[1], ah0, ah1, ah2, ah3, bl1, bl3);
            mma_bf16(acc[1], al0, al1, al2, al3, bh1, bh3);
        }
        int r0 = m0 + g, r1 = r0 + 8;
#pragma unroll
        for (int nt = 0; nt < 2; nt++) {
            int col0 = n0 + nt * 8 + 2 * q;
            sm[POUT + r0 * 132 + col0]     = acc[nt][0] + pb[col0];
            sm[POUT + r0 * 132 + col0 + 1] = acc[nt][1] + pb[col0 + 1];
            sm[POUT + r1 * 132 + col0]     = acc[nt][2] + pb[col0];
            sm[POUT + r1 * 132 + col0 + 1] = acc[nt][3] + pb[col0 + 1];
        }
    }
    __syncthreads();

    // phase 7: LN + residual -> g_x1 (16 threads/row)
    {
        int t = tid >> 4, ln = tid & 15;
        const float* prow = &sm[POUT + t * 132];
        int cb = ln * 8;
        float s1 = 0.f, s2 = 0.f;
#pragma unroll
        for (int c = 0; c < 8; c++) {
            float v = prow[cb + c];
            s1 += v; s2 += v * v;
        }
        s1 += __shfl_xor_sync(0xffffffffu, s1, 1);
        s2 += __shfl_xor_sync(0xffffffffu, s2, 1);
        s1 += __shfl_xor_sync(0xffffffffu, s1, 2);
        s2 += __shfl_xor_sync(0xffffffffu, s2, 2);
        s1 += __shfl_xor_sync(0xffffffffu, s1, 4);
        s2 += __shfl_xor_sync(0xffffffffu, s2, 4);
        s1 += __shfl_xor_sync(0xffffffffu, s1, 8);
        s2 += __shfl_xor_sync(0xffffffffu, s2, 8);
        float mu = s1 * (1.0f / 128.0f);
        float var = fmaxf(s2 * (1.0f / 128.0f) - mu * mu, 0.0f);
        float rs = rsqrtf(var + 1e-5f);
        int ti = t >> 3, tj = t & 7;
        int hh = (wy * 8 + ti + 4) & 127;
        int ww = (wx * 8 + tj + 4) & 127;
        float* dst = &g_x1[((size_t)b * HW + hh * 128 + ww) * 128];
#pragma unroll
        for (int cp = 0; cp < 4; cp++) {
            unsigned uh = smu[XHI + t * 68 + ln * 4 + cp];
            unsigned ul = smu[XLO + t * 68 + ln * 4 + cp];
            float2 fh = unpack2(uh), fl = unpack2(ul);
            int cc = cb + 2 * cp;
            float l0 = (prow[cc] - mu) * rs * n1w[cc] + n1b[cc];
            float l1 = (prow[cc + 1] - mu) * rs * n1w[cc + 1] + n1b[cc + 1];
            dst[cc]     = fh.x + fl.x + l0;
            dst[cc + 1] = fh.y + fl.y + l1;
        }
    }
}

// ------------------- K2: MLP (1024 thr, cp.async pipeline) ------------------
#define K2XHI 0
#define K2XLO 8704
#define K2W1  17408    // 2 bufs * 8704
#define K2W2H 34816
#define K2W2L 39424
#define K2HH  44032
#define K2HL  48640
#define K2Y   17408
#define K2_SMEM (53248 * 4)

__global__ void __launch_bounds__(1024, 1)
k2_mlp(const float* __restrict__ n2w, const float* __restrict__ n2b,
       const float* __restrict__ b1, const float* __restrict__ b2,
       float* __restrict__ out) {
    extern __shared__ float sm[];
    unsigned* smu = (unsigned*)sm;
    int tid = threadIdx.x;
    int wid = tid >> 5, lane = tid & 31;
    int g = lane >> 2, q = lane & 3;
    int p0 = blockIdx.x * 128;
    int b = p0 >> 14, h = (p0 >> 7) & 127;

    // prologue: async-stage W1 chunk 0 into buf 0 (1024 quads hi + 1024 lo)
    {
        int r = tid >> 4, cq = (tid & 15) << 2;
        cpa16(&smu[K2W1 + r * 68 + cq], &g_f1h[r * 64 + cq]);
        cpa16(&smu[K2W1 + 4352 + r * 68 + cq], &g_f1l[r * 64 + cq]);
        CP_COMMIT();
    }

    // load + split x1 (128 tokens) — overlaps the W1 prefetch
#pragma unroll
    for (int it = 0; it < 8; it++) {                  // 8*1024 = 8192
        int idx = it * 1024 + tid;
        int cp = idx & 63, t = idx >> 6;
        float2 v = *(const float2*)&g_x1[((size_t)p0 + t) * 128 + 2 * cp];
        split2(v.x, v.y, smu[K2XHI + t * 68 + cp], smu[K2XLO + t * 68 + cp]);
    }

    int mi = wid & 7, nh = wid >> 3;   // 8 mi x 4 nh
    int m0 = mi * 16;
    float acc2[2][2][4];               // fc2 persistent: n32 = 2 n16 x 2 n8
#pragma unroll
    for (int t = 0; t < 2; t++)
#pragma unroll
        for (int u = 0; u < 2; u++)
#pragma unroll
            for (int j = 0; j < 4; j++) acc2[t][u][j] = 0.f;

    for (int ch = 0; ch < 8; ch++) {
        int cur = ch & 1, nxt = cur ^ 1;
        const unsigned* W1H = smu + K2W1 + cur * 8704;
        const unsigned* W1L = W1H + 4352;
        CP_WAIT0();
        __syncthreads();
        // async-stage W2 k-slice [128][32] hi+lo
        {
            int r = tid >> 3, cq = (tid & 7) << 2;
            cpa16(&smu[K2W2H + r * 36 + cq], &g_f2h[r * 256 + ch * 32 + cq]);
            cpa16(&smu[K2W2L + r * 36 + cq], &g_f2l[r * 256 + ch * 32 + cq]);
        }
        CP_COMMIT();
        // fc1: warp m16 x n16
        float acc[2][4] = {};
        int n0f = nh * 16;
#pragma unroll
        for (int ks = 0; ks < 8; ks++) {
            int kp = ks * 8;
            unsigned ah0, ah1, ah2, ah3, al0, al1, al2, al3;
            ldsm4(smu + K2XHI, 68, m0, kp, ah0, ah1, ah2, ah3);
            ldsm4(smu + K2XLO, 68, m0, kp, al0, al1, al2, al3);
            unsigned bh0, bh1, bh2, bh3, bl0, bl1, bl2, bl3;
            ldsm4(W1H, 68, n0f, kp, bh0, bh1, bh2, bh3);
            ldsm4(W1L, 68, n0f, kp, bl0, bl1, bl2, bl3);
            mma_bf16(acc[0], ah0, ah1, ah2, ah3, bh0, bh2);
            mma_bf16(acc[0], ah0, ah1, ah2, ah3, bl0, bl2);
            mma_bf16(acc[0], al0, al1, al2, al3, bh0, bh2);
            mma_bf16(acc[1], ah0, ah1, ah2, ah3, bh1, bh3);
            mma_bf16(acc[1], ah0, ah1, ah2, ah3, bl1, bl3);
            mma_bf16(acc[1], al0, al1, al2, al3, bh1, bh3);
        }
        // silu + split -> H [t][hpair] pitch 36
#pragma unroll
        for (int nt = 0; nt < 2; nt++) {
            int c0 = n0f + nt * 8 + 2 * q;
            int col = ch * 64 + c0;
            float v0 = acc[nt][0] + b1[col],     v1 = acc[nt][1] + b1[col + 1];
            float v2 = acc[nt][2] + b1[col],     v3 = acc[nt][3] + b1[col + 1];
            v0 = v0 / (1.0f + __expf(-v0));
            v1 = v1 / (1.0f + __expf(-v1));
            v2 = v2 / (1.0f + __expf(-v2));
            v3 = v3 / (1.0f + __expf(-v3));
            int pp = (c0 >> 1);
            split2(v0, v1, smu[K2HH + (m0 + g) * 36 + pp], smu[K2HL + (m0 + g) * 36 + pp]);
            split2(v2, v3, smu[K2HH + (m0 + g + 8) * 36 + pp], smu[K2HL + (m0 + g + 8) * 36 + pp]);
        }
        CP_WAIT0();
        __syncthreads();
        // async-stage next W1 (overlaps fc2)
        if (ch < 7) {
            int r = tid >> 4, cq = (tid & 15) << 2;
            cpa16(&smu[K2W1 + nxt * 8704 + r * 68 + cq],
                  &g_f1h[((ch + 1) * 64 + r) * 64 + cq]);
            cpa16(&smu[K2W1 + nxt * 8704 + 4352 + r * 68 + cq],
                  &g_f1l[((ch + 1) * 64 + r) * 64 + cq]);
        }
        CP_COMMIT();
        // fc2 partial: warp m16 x n32 (rows nh*32 .. +31 of W2)
#pragma unroll
        for (int ks = 0; ks < 4; ks++) {
            int kp = ks * 8;
            unsigned ah0, ah1, ah2, ah3, al0, al1, al2, al3;
            ldsm4(smu + K2HH, 36, m0, kp, ah0, ah1, ah2, ah3);
            ldsm4(smu + K2HL, 36, m0, kp, al0, al1, al2, al3);
#pragma unroll
            for (int tp = 0; tp < 2; tp++) {
                unsigned bh0, bh1, bh2, bh3, bl0, bl1, bl2, bl3;
                ldsm4(smu + K2W2H, 36, nh * 32 + 16 * tp, kp, bh0, bh1, bh2, bh3);
                ldsm4(smu + K2W2L, 36, nh * 32 + 16 * tp, kp, bl0, bl1, bl2, bl3);
                mma_bf16(acc2[tp][0], ah0, ah1, ah2, ah3, bh0, bh2);
                mma_bf16(acc2[tp][0], ah0, ah1, ah2, ah3, bl0, bl2);
                mma_bf16(acc2[tp][0], al0, al1, al2, al3, bh0, bh2);
                mma_bf16(acc2[tp][1], ah0, ah1, ah2, ah3, bh1, bh3);
                mma_bf16(acc2[tp][1], ah0, ah1, ah2, ah3, bl1, bl3);
                mma_bf16(acc2[tp][1], al0, al1, al2, al3, bh1, bh3);
            }
        }
    }
    CP_WAIT0();
    __syncthreads();   // W1/W2/H dead; Y aliases W1 bufs
    // Y = fc2 out + bias
#pragma unroll
    for (int tp = 0; tp < 2; tp++)
#pragma unroll
        for (int u = 0; u < 2; u++) {
            int col = nh * 32 + tp * 16 + u * 8 + 2 * q;
            sm[K2Y + (m0 + g) * 133 + col]         = acc2[tp][u][0] + b2[col];
            sm[K2Y + (m0 + g) * 133 + col + 1]     = acc2[tp][u][1] + b2[col + 1];
            sm[K2Y + (m0 + g + 8) * 133 + col]     = acc2[tp][u][2] + b2[col];
            sm[K2Y + (m0 + g + 8) * 133 + col + 1] = acc2[tp][u][3] + b2[col + 1];
        }
    __syncthreads();
    // LN + residual, 8 threads/row
    {
        int t = tid >> 3, ln = tid & 7;
        float* yrow = &sm[K2Y + t * 133];
        int cb = ln * 16;
        float s1 = 0.f, s2 = 0.f;
#pragma unroll
        for (int c = 0; c < 16; c++) {
            float v = yrow[cb + c];
            s1 += v; s2 += v * v;
        }
        s1 += __shfl_xor_sync(0xffffffffu, s1, 1);
        s2 += __shfl_xor_sync(0xffffffffu, s2, 1);
        s1 += __shfl_xor_sync(0xffffffffu, s1, 2);
        s2 += __shfl_xor_sync(0xffffffffu, s2, 2);
        s1 += __shfl_xor_sync(0xffffffffu, s1, 4);
        s2 += __shfl_xor_sync(0xffffffffu, s2, 4);
        float mu = s1 * (1.0f / 128.0f);
        float var = fmaxf(s2 * (1.0f / 128.0f) - mu * mu, 0.0f);
        float rs = rsqrtf(var + 1e-5f);
#pragma unroll
        for (int cp = 0; cp < 8; cp++) {
            unsigned uh = smu[K2XHI + t * 68 + (cb >> 1) + cp];
            unsigned ul = smu[K2XLO + t * 68 + (cb >> 1) + cp];
            float2 fh = unpack2(uh), fl = unpack2(ul);
            int cc = cb + 2 * cp;
            float l0 = (yrow[cc] - mu) * rs * n2w[cc] + n2b[cc];
            float l1 = (yrow[cc + 1] - mu) * rs * n2w[cc + 1] + n2b[cc + 1];
            yrow[cc]     = fh.x + fl.x + l0;
            yrow[cc + 1] = fh.y + fl.y + l1;
        }
    }
    __syncthreads();
    // transposed store -> NCHW
    {
        float* ob = out + (size_t)b * 128 * HW + h * 128;
#pragma unroll
        for (int it = 0; it < 16; it++) {
            int idx = it * 1024 + tid;
            int c = idx >> 7, w = idx & 127;
            ob[(size_t)c * HW + w] = sm[K2Y + w * 133 + c];
        }
    }
}

// ------------------------------ launch --------------------------------------
extern "C" void kernel_launch(void* const* d_in, const int* in_sizes, int n_in,
                              void* d_out, int out_size) {
    const float* x    = (const float*)d_in[0];
    const float* n1w  = (const float*)d_in[1];
    const float* n1b  = (const float*)d_in[2];
    const float* qkvw = (const float*)d_in[3];
    const float* qb   = (const float*)d_in[4];
    const float* vb   = (const float*)d_in[5];
    const float* ls   = (const float*)d_in[6];
    const float* cw1  = (const float*)d_in[7];
    const float* cb1  = (const float*)d_in[8];
    const float* cw2  = (const float*)d_in[9];
    const float* pw   = (const float*)d_in[10];
    const float* pb   = (const float*)d_in[11];
    const float* n2w  = (const float*)d_in[12];
    const float* n2b  = (const float*)d_in[13];
    const float* f1w  = (const float*)d_in[14];
    const float* f1b  = (const float*)d_in[15];
    const float* f2w  = (const float*)d_in[16];
    const float* f2b  = (const float*)d_in[17];
    float* out = (float*)d_out;

    cudaFuncSetAttribute(k1_attn, cudaFuncAttributeMaxDynamicSharedMemorySize, K1_SMEM);
    cudaFuncSetAttribute(k2_mlp,  cudaFuncAttributeMaxDynamicSharedMemorySize, K2_SMEM);

    k0_bias<<<1, 256>>>(cw1, cb1, cw2);
    k0_wsplit<<<384, 256>>>(qkvw, pw, f1w, f2w);
    k1_attn<<<4096, 1024, K1_SMEM>>>(x, n1w, n1b, qb, vb, ls, pb);
    k2_mlp<<<2048, 1024, K2_SMEM>>>(n2w, n2b, f1b, f2b, out);
}

// round 14
// speedup vs baseline: 1.0768x; 1.0050x over previous
#include <cuda_runtime.h>
#include <cuda_bf16.h>
#include <math.h>

#define HW 16384
#define LOG100f 4.605170185988092f

__device__ float g_x1[16u * HW * 128u];
__device__ float g_bias16[4 * 64 * 64];
__device__ unsigned g_qkvh[24576], g_qkvl[24576];   // [384][64]
__device__ unsigned g_pwh[8192],   g_pwl[8192];     // [128][64]
__device__ unsigned g_f1h[32768],  g_f1l[32768];    // [512][64]
__device__ unsigned g_f2h[32768],  g_f2l[32768];    // [128][256]

// ---------------------------------------------------------------------------
__device__ __forceinline__ void mma_bf16(float d[4], unsigned a0, unsigned a1,
                                         unsigned a2, unsigned a3,
                                         unsigned b0, unsigned b1) {
    asm volatile(
        "mma.sync.aligned.m16n8k16.row.col.f32.bf16.bf16.f32 "
        "{%0,%1,%2,%3},{%4,%5,%6,%7},{%8,%9},{%0,%1,%2,%3};"
        : "+f"(d[0]), "+f"(d[1]), "+f"(d[2]), "+f"(d[3])
        : "r"(a0), "r"(a1), "r"(a2), "r"(a3), "r"(b0), "r"(b1));
}

__device__ __forceinline__ void ldsm4(const unsigned* base, int P, int r0, int kp,
                                      unsigned& o0, unsigned& o1, unsigned& o2, unsigned& o3) {
    int lane = threadIdx.x & 31;
    const unsigned* p = base + (r0 + (lane & 15)) * P + kp + ((lane >> 4) << 2);
    unsigned a = (unsigned)__cvta_generic_to_shared(p);
    asm volatile("ldmatrix.sync.aligned.m8n8.x4.shared.b16 {%0,%1,%2,%3}, [%4];"
                 : "=r"(o0), "=r"(o1), "=r"(o2), "=r"(o3) : "r"(a));
}

__device__ __forceinline__ void cpa16(unsigned* dst, const unsigned* src) {
    unsigned d = (unsigned)__cvta_generic_to_shared(dst);
    asm volatile("cp.async.cg.shared.global [%0], [%1], 16;" :: "r"(d), "l"(src));
}
#define CP_COMMIT() asm volatile("cp.async.commit_group;" ::: "memory")
#define CP_WAIT0()  asm volatile("cp.async.wait_group 0;" ::: "memory")

__device__ __forceinline__ void split2(float v0, float v1, unsigned& hi, unsigned& lo) {
    __nv_bfloat16 h0 = __float2bfloat16(v0);
    __nv_bfloat16 h1 = __float2bfloat16(v1);
    float r0 = v0 - __bfloat162float(h0);
    float r1 = v1 - __bfloat162float(h1);
    __nv_bfloat16 l0 = __float2bfloat16(r0);
    __nv_bfloat16 l1 = __float2bfloat16(r1);
    hi = (unsigned)__bfloat16_as_ushort(h0) | ((unsigned)__bfloat16_as_ushort(h1) << 16);
    lo = (unsigned)__bfloat16_as_ushort(l0) | ((unsigned)__bfloat16_as_ushort(l1) << 16);
}

__device__ __forceinline__ float2 unpack2(unsigned u) {
    __nv_bfloat162 b = *reinterpret_cast<__nv_bfloat162*>(&u);
    return __bfloat1622float2(b);
}

// ------------------------------ K0 ------------------------------------------
__global__ void k0_bias(const float* __restrict__ w1, const float* __restrict__ b1,
                        const float* __restrict__ w2) {
    __shared__ float tab[225][4];
    int tid = threadIdx.x;
    if (tid < 225) {
        int a = tid / 15, bb = tid % 15;
        float v0 = (a - 7) * (8.0f / 7.0f), v1 = (bb - 7) * (8.0f / 7.0f);
        float g0 = copysignf(log2f(fabsf(v0) + 1.0f) * (1.0f / 3.0f), v0);
        float g1 = copysignf(log2f(fabsf(v1) + 1.0f) * (1.0f / 3.0f), v1);
        float o0 = 0, o1 = 0, o2 = 0, o3 = 0;
        for (int j = 0; j < 512; j++) {
            float hv = fmaxf(w1[2 * j] * g0 + w1[2 * j + 1] * g1 + b1[j], 0.0f);
            o0 += hv * w2[j];        o1 += hv * w2[512 + j];
            o2 += hv * w2[1024 + j]; o3 += hv * w2[1536 + j];
        }
        tab[tid][0] = o0; tab[tid][1] = o1; tab[tid][2] = o2; tab[tid][3] = o3;
    }
    __syncthreads();
    for (int e = tid; e < 4 * 64 * 64; e += blockDim.x) {
        int h = e >> 12, i = (e >> 6) & 63, j = e & 63;
        int dy = (i >> 3) - (j >> 3) + 7, dx = (i & 7) - (j & 7) + 7;
        float v = tab[dy * 15 + dx][h];
        g_bias16[e] = 16.0f / (1.0f + expf(-v));
    }
}

__device__ __forceinline__ void splitpair(const float* w, unsigned* hi, unsigned* lo, int i) {
    split2(w[2 * i], w[2 * i + 1], hi[i], lo[i]);
}

__global__ void k0_wsplit(const float* __restrict__ qkvw, const float* __restrict__ pw,
                          const float* __restrict__ f1w, const float* __restrict__ f2w) {
    int i = blockIdx.x * 256 + threadIdx.x;
    if (i < 24576)       splitpair(qkvw, g_qkvh, g_qkvl, i);
    else if (i < 32768)  splitpair(pw,  g_pwh,  g_pwl,  i - 24576);
    else if (i < 65536)  splitpair(f1w, g_f1h,  g_f1l,  i - 32768);
    else if (i < 98304)  splitpair(f2w, g_f2h,  g_f2l,  i - 65536);
}

// ------------------------------ K1: attention (1024 thr) --------------------
#define XHI   0
#define XLO   4352
#define QSPH  8704
#define QSPL  13056
#define KSPH  17408
#define KSPL  21760
#define PHI_  8704
#define PLO_  17920
#define WPH   8704
#define WPL   17408
#define VSPH  27136
#define VSPL  31744
#define WQH   36352
#define WQL   45056
#define ATTN_ 36352
#define OHI_  36352
#define OLO_  40704
#define POUT  45056
#define RG_   53760
#define IQ_   53824
#define IK_   54080
#define K1_SMEM (54336 * 4)

__global__ void __launch_bounds__(1024, 1)
k1_attn(const float* __restrict__ x,
        const float* __restrict__ n1w, const float* __restrict__ n1b,
        const float* __restrict__ qb, const float* __restrict__ vb,
        const float* __restrict__ ls, const float* __restrict__ pb) {
    extern __shared__ float sm[];
    unsigned* smu = (unsigned*)sm;
    int tid = threadIdx.x;
    int wid = tid >> 5, lane = tid & 31;
    int g = lane >> 2, q = lane & 3;
    int b = blockIdx.x >> 8, widx = blockIdx.x & 255;
    int wy = widx >> 4, wx = widx & 15;

    // prologue: prefetch QKV chunk-0 weights (WQ region untouched)
    {
#pragma unroll
        for (int it = 0; it < 2; it++) {
            int j = it * 1024 + tid;              // 0..2047
            int r = j >> 4, cq = (j & 15) << 2;
            cpa16(&smu[WQH + r * 68 + cq], &g_qkvh[r * 64 + cq]);
            cpa16(&smu[WQL + r * 68 + cq], &g_qkvl[r * 64 + cq]);
        }
        CP_COMMIT();
    }

    // phase 0: gather shifted window -> split [t][cpair]  (overlaps prefetch)
    {
        const float* xb = x + (size_t)b * 128 * HW;
#pragma unroll
        for (int it = 0; it < 4; it++) {
            int idx = it * 1024 + tid;
            int t = idx & 63, cp = idx >> 6;
            int ti = t >> 3, tj = t & 7;
            int hh = (wy * 8 + ti + 4) & 127;
            int ww = (wx * 8 + tj + 4) & 127;
            const float* p = xb + (size_t)(2 * cp) * HW + hh * 128 + ww;
            float v0 = p[0], v1 = p[HW];
            split2(v0, v1, smu[XHI + t * 68 + cp], smu[XLO + t * 68 + cp]);
        }
        if (tid < 64) {
            int ti = tid >> 3, tj = tid & 7;
            int hs = wy * 8 + ti, ws = wx * 8 + tj;
            int hr = hs < 120 ? 0 : (hs < 124 ? 1 : 2);
            int wr = ws < 120 ? 0 : (ws < 124 ? 1 : 2);
            sm[RG_ + tid] = (float)(hr * 3 + wr);
        }
    }

    int mi = wid & 3;
    int m0 = mi * 16;

    // phase 1: QKV GEMM, 3 chunks of 128 cols, 4 mi x 8 nw warps
    {
        int nw = wid >> 2;
        int n0 = nw * 16;
        for (int ch = 0; ch < 3; ch++) {
            if (ch > 0) {
                __syncthreads();                  // prior MMA reads of WQ done
#pragma unroll
                for (int it = 0; it < 2; it++) {
                    int j = it * 1024 + tid;
                    int r = j >> 4, cq = (j & 15) << 2;
                    cpa16(&smu[WQH + r * 68 + cq], &g_qkvh[(ch * 128 + r) * 64 + cq]);
                    cpa16(&smu[WQL + r * 68 + cq], &g_qkvl[(ch * 128 + r) * 64 + cq]);
                }
                CP_COMMIT();
            }
            CP_WAIT0();
            __syncthreads();
            float acc[2][4] = {};
#pragma unroll
            for (int ks = 0; ks < 8; ks++) {
                int kp = ks * 8;
                unsigned ah0, ah1, ah2, ah3, al0, al1, al2, al3;
                ldsm4(smu + XHI, 68, m0, kp, ah0, ah1, ah2, ah3);
                ldsm4(smu + XLO, 68, m0, kp, al0, al1, al2, al3);
                unsigned bh0, bh1, bh2, bh3, bl0, bl1, bl2, bl3;
                ldsm4(smu + WQH, 68, n0, kp, bh0, bh1, bh2, bh3);
                ldsm4(smu + WQL, 68, n0, kp, bl0, bl1, bl2, bl3);
                mma_bf16(acc[0], ah0, ah1, ah2, ah3, bh0, bh2);
                mma_bf16(acc[0], ah0, ah1, ah2, ah3, bl0, bl2);
                mma_bf16(acc[0], al0, al1, al2, al3, bh0, bh2);
                mma_bf16(acc[1], ah0, ah1, ah2, ah3, bh1, bh3);
                mma_bf16(acc[1], ah0, ah1, ah2, ah3, bl1, bl3);
                mma_bf16(acc[1], al0, al1, al2, al3, bh1, bh3);
            }
            int r0 = m0 + g, r1 = r0 + 8;
            if (ch == 0) {          // Q
#pragma unroll
                for (int nt = 0; nt < 2; nt++) {
                    int col0 = n0 + nt * 8 + 2 * q;
                    float b0c = qb[col0], b1c = qb[col0 + 1];
                    int dp = col0 >> 1;
                    split2(acc[nt][0] + b0c, acc[nt][1] + b1c,
                           smu[QSPH + r0 * 68 + dp], smu[QSPL + r0 * 68 + dp]);
                    split2(acc[nt][2] + b0c, acc[nt][3] + b1c,
                           smu[QSPH + r1 * 68 + dp], smu[QSPL + r1 * 68 + dp]);
                }
            } else if (ch == 1) {   // K
#pragma unroll
                for (int nt = 0; nt < 2; nt++) {
                    int col0 = n0 + nt * 8 + 2 * q;
                    int dp = col0 >> 1;
                    split2(acc[nt][0], acc[nt][1],
                           smu[KSPH + r0 * 68 + dp], smu[KSPL + r0 * 68 + dp]);
                    split2(acc[nt][2], acc[nt][3],
                           smu[KSPH + r1 * 68 + dp], smu[KSPL + r1 * 68 + dp]);
                }
            } else {                // V -> [d][upair] via lane exchange
#pragma unroll
                for (int nt = 0; nt < 2; nt++) {
                    int d0 = n0 + nt * 8 + 2 * q;
                    float v0 = acc[nt][0] + vb[d0], v1 = acc[nt][1] + vb[d0 + 1];
                    float v2 = acc[nt][2] + vb[d0], v3 = acc[nt][3] + vb[d0 + 1];
                    float p0 = __shfl_xor_sync(0xffffffffu, v0, 4);
                    float p1 = __shfl_xor_sync(0xffffffffu, v1, 4);
                    float p2 = __shfl_xor_sync(0xffffffffu, v2, 4);
                    float p3 = __shfl_xor_sync(0xffffffffu, v3, 4);
                    if (!(g & 1)) {
                        int up = (m0 + g) >> 1;
                        split2(v0, p0, smu[VSPH + d0 * 36 + up], smu[VSPL + d0 * 36 + up]);
                        split2(v1, p1, smu[VSPH + (d0 + 1) * 36 + up], smu[VSPL + (d0 + 1) * 36 + up]);
                    } else {
                        int up = (m0 + g + 7) >> 1;
                        split2(p2, v2, smu[VSPH + d0 * 36 + up], smu[VSPL + d0 * 36 + up]);
                        split2(p3, v3, smu[VSPH + (d0 + 1) * 36 + up], smu[VSPL + (d0 + 1) * 36 + up]);
                    }
                }
            }
        }
    }
    __syncthreads();

    // phase 2: inverse norms
    {
        int qk = tid >> 9, rem = tid & 511;
        int h = rem >> 7, sub = rem & 127;
        int t = sub >> 1, half = sub & 1;
        int base = (qk ? KSPH : QSPH) + t * 68 + h * 16 + half * 8;
        int baseL = base + 4352;
        float s = 0.f;
#pragma unroll
        for (int i = 0; i < 8; i++) {
            float2 fh = unpack2(smu[base + i]);
            float2 fl = unpack2(smu[baseL + i]);
            float a0 = fh.x + fl.x, a1 = fh.y + fl.y;
            s += a0 * a0 + a1 * a1;
        }
        s += __shfl_xor_sync(0xffffffffu, s, 1);
        if (half == 0)
            sm[(qk ? IK_ : IQ_) + h * 64 + t] = 1.0f / fmaxf(sqrtf(s), 1e-12f);
    }
    __syncthreads();

    // phase 3: logits MMA. 32 warps = 4 hw * 2 nhalf * 4 mi
    {
        int hw = wid >> 3, nhalf = (wid >> 2) & 1;
        float scale = __expf(fminf(ls[hw], LOG100f));
        float acc[2][2][4];
#pragma unroll
        for (int i = 0; i < 2; i++)
#pragma unroll
            for (int j = 0; j < 2; j++)
#pragma unroll
                for (int k = 0; k < 4; k++) acc[i][j][k] = 0.f;
#pragma unroll
        for (int ks = 0; ks < 2; ks++) {
            int kp = hw * 16 + ks * 8;
            unsigned ah0, ah1, ah2, ah3, al0, al1, al2, al3;
            ldsm4(smu + QSPH, 68, m0, kp, ah0, ah1, ah2, ah3);
            ldsm4(smu + QSPL, 68, m0, kp, al0, al1, al2, al3);
#pragma unroll
            for (int nh = 0; nh < 2; nh++) {
                int nr = nhalf * 32 + nh * 16;
                unsigned bh0, bh1, bh2, bh3, bl0, bl1, bl2, bl3;
                ldsm4(smu + KSPH, 68, nr, kp, bh0, bh1, bh2, bh3);
                ldsm4(smu + KSPL, 68, nr, kp, bl0, bl1, bl2, bl3);
                mma_bf16(acc[nh][0], ah0, ah1, ah2, ah3, bh0, bh2);
                mma_bf16(acc[nh][0], ah0, ah1, ah2, ah3, bl0, bl2);
                mma_bf16(acc[nh][0], al0, al1, al2, al3, bh0, bh2);
                mma_bf16(acc[nh][1], ah0, ah1, ah2, ah3, bh1, bh3);
                mma_bf16(acc[nh][1], ah0, ah1, ah2, ah3, bl1, bl3);
                mma_bf16(acc[nh][1], al0, al1, al2, al3, bh1, bh3);
            }
        }
        int r0 = m0 + g, r1 = r0 + 8;
        float iq0 = sm[IQ_ + hw * 64 + r0] * scale;
        float iq1 = sm[IQ_ + hw * 64 + r1] * scale;
        float rt0 = sm[RG_ + r0], rt1 = sm[RG_ + r1];
        float* A = &sm[ATTN_ + hw * 4352];
#pragma unroll
        for (int nh = 0; nh < 2; nh++)
#pragma unroll
            for (int nt = 0; nt < 2; nt++) {
                int col = nhalf * 32 + nh * 16 + nt * 8 + 2 * q;
                float ik0 = sm[IK_ + hw * 64 + col], ik1 = sm[IK_ + hw * 64 + col + 1];
                float ru0 = sm[RG_ + col], ru1 = sm[RG_ + col + 1];
                float2 b0v = *(const float2*)&g_bias16[(hw * 64 + r0) * 64 + col];
                float2 b1v = *(const float2*)&g_bias16[(hw * 64 + r1) * 64 + col];
                A[r0 * 68 + col]     = acc[nh][nt][0] * iq0 * ik0 + b0v.x + (rt0 != ru0 ? -100.f : 0.f);
                A[r0 * 68 + col + 1] = acc[nh][nt][1] * iq0 * ik1 + b0v.y + (rt0 != ru1 ? -100.f : 0.f);
                A[r1 * 68 + col]     = acc[nh][nt][2] * iq1 * ik0 + b1v.x + (rt1 != ru0 ? -100.f : 0.f);
                A[r1 * 68 + col + 1] = acc[nh][nt][3] * iq1 * ik1 + b1v.y + (rt1 != ru1 ? -100.f : 0.f);
            }
    }
    __syncthreads();

    // phase 4: softmax, 256 rows, 4 threads/row -> P splits
    {
        int r = tid >> 2, qt = tid & 3;
        int hw = r >> 6, t = r & 63;
        const float* row = &sm[ATTN_ + hw * 4352 + t * 68 + qt * 16];
        float e[16];
        float mx = -1e30f;
#pragma unroll
        for (int i = 0; i < 16; i++) { e[i] = row[i]; mx = fmaxf(mx, e[i]); }
        mx = fmaxf(mx, __shfl_xor_sync(0xffffffffu, mx, 1));
        mx = fmaxf(mx, __shfl_xor_sync(0xffffffffu, mx, 2));
        float s = 0.f;
#pragma unroll
        for (int i = 0; i < 16; i++) { e[i] = __expf(e[i] - mx); s += e[i]; }
        s += __shfl_xor_sync(0xffffffffu, s, 1);
        s += __shfl_xor_sync(0xffffffffu, s, 2);
        float inv = 1.0f / s;
        int pb_ = hw * 2304 + t * 36 + qt * 8;
#pragma unroll
        for (int i = 0; i < 8; i++)
            split2(e[2 * i] * inv, e[2 * i + 1] * inv,
                   smu[PHI_ + pb_ + i], smu[PLO_ + pb_ + i]);
    }
    __syncthreads();

    // phase 5: PV MMA. 32 warps = 4 hw * 2 nd * 4 mi
    {
        int hw = wid >> 3, nd = (wid >> 2) & 1;
        const unsigned* PH = smu + PHI_ + hw * 2304;
        const unsigned* PL = smu + PLO_ + hw * 2304;
        float acc[2][4] = {};
#pragma unroll
        for (int ks = 0; ks < 4; ks++) {
            int kp = ks * 8;
            unsigned ah0, ah1, ah2, ah3, al0, al1, al2, al3;
            ldsm4(PH, 36, m0, kp, ah0, ah1, ah2, ah3);
            ldsm4(PL, 36, m0, kp, al0, al1, al2, al3);
            int n0v = hw * 32 + nd * 16;
            unsigned bh0, bh1, bh2, bh3, bl0, bl1, bl2, bl3;
            ldsm4(smu + VSPH, 36, n0v, kp, bh0, bh1, bh2, bh3);
            ldsm4(smu + VSPL, 36, n0v, kp, bl0, bl1, bl2, bl3);
            mma_bf16(acc[0], ah0, ah1, ah2, ah3, bh0, bh2);
            mma_bf16(acc[0], ah0, ah1, ah2, ah3, bl0, bl2);
            mma_bf16(acc[0], al0, al1, al2, al3, bh0, bh2);
            mma_bf16(acc[1], ah0, ah1, ah2, ah3, bh1, bh3);
            mma_bf16(acc[1], ah0, ah1, ah2, ah3, bl1, bl3);
            mma_bf16(acc[1], al0, al1, al2, al3, bh1, bh3);
        }
        int r0 = m0 + g, r1 = r0 + 8;
#pragma unroll
        for (int nt = 0; nt < 2; nt++) {
            int dglob = hw * 32 + nd * 16 + nt * 8 + 2 * q;
            int dp = dglob >> 1;
            split2(acc[nt][0], acc[nt][1],
                   smu[OHI_ + r0 * 68 + dp], smu[OLO_ + r0 * 68 + dp]);
            split2(acc[nt][2], acc[nt][3],
                   smu[OHI_ + r1 * 68 + dp], smu[OLO_ + r1 * 68 + dp]);
        }
    }

    // phase 6: proj GEMM, single 128-col chunk (cp.async staged)
    {
        int nw = wid >> 2;
        int n0 = nw * 16;
        __syncthreads();                          // P reads done; WP region free
#pragma unroll
        for (int it = 0; it < 2; it++) {
            int j = it * 1024 + tid;
            int r = j >> 4, cq = (j & 15) << 2;
            cpa16(&smu[WPH + r * 68 + cq], &g_pwh[r * 64 + cq]);
            cpa16(&smu[WPL + r * 68 + cq], &g_pwl[r * 64 + cq]);
        }
        CP_COMMIT();
        CP_WAIT0();
        __syncthreads();
        float acc[2][4] = {};
#pragma unroll
        for (int ks = 0; ks < 8; ks++) {
            int kp = ks * 8;
            unsigned ah0, ah1, ah2, ah3, al0, al1, al2, al3;
            ldsm4(smu + OHI_, 68, m0, kp, ah0, ah1, ah2, ah3);
            ldsm4(smu + OLO_, 68, m0, kp, al0, al1, al2, al3);
            unsigned bh0, bh1, bh2, bh3, bl0, bl1, bl2, bl3;
            ldsm4(smu + WPH, 68, n0, kp, bh0, bh1, bh2, bh3);
            ldsm4(smu + WPL, 68, n0, kp, bl0, bl1, bl2, bl3);
            mma_bf16(acc[0], ah0, ah1, ah2, ah3, bh0, bh2);
            mma_bf16(acc[0], ah0, ah1, ah2, ah3, bl0, bl2);
            mma_bf16(acc[0], al0, al1, al2, al3, bh0, bh2);
            mma_bf16(acc[1], ah0, ah1, ah2, ah3, bh1, bh3);
            mma_bf16(acc[1], ah0, ah1, ah2, ah3, bl1, bl3);
            mma_bf16(acc[1], al0, al1, al2, al3, bh1, bh3);
        }
        int r0 = m0 + g, r1 = r0 + 8;
#pragma unroll
        for (int nt = 0; nt < 2; nt++) {
            int col0 = n0 + nt * 8 + 2 * q;
            sm[POUT + r0 * 132 + col0]     = acc[nt][0] + pb[col0];
            sm[POUT + r0 * 132 + col0 + 1] = acc[nt][1] + pb[col0 + 1];
            sm[POUT + r1 * 132 + col0]     = acc[nt][2] + pb[col0];
            sm[POUT + r1 * 132 + col0 + 1] = acc[nt][3] + pb[col0 + 1];
        }
    }
    __syncthreads();

    // phase 7: LN + residual -> g_x1 (16 threads/row)
    {
        int t = tid >> 4, ln = tid & 15;
        const float* prow = &sm[POUT + t * 132];
        int cb = ln * 8;
        float s1 = 0.f, s2 = 0.f;
#pragma unroll
        for (int c = 0; c < 8; c++) {
            float v = prow[cb + c];
            s1 += v; s2 += v * v;
        }
        s1 += __shfl_xor_sync(0xffffffffu, s1, 1);
        s2 += __shfl_xor_sync(0xffffffffu, s2, 1);
        s1 += __shfl_xor_sync(0xffffffffu, s1, 2);
        s2 += __shfl_xor_sync(0xffffffffu, s2, 2);
        s1 += __shfl_xor_sync(0xffffffffu, s1, 4);
        s2 += __shfl_xor_sync(0xffffffffu, s2, 4);
        s1 += __shfl_xor_sync(0xffffffffu, s1, 8);
        s2 += __shfl_xor_sync(0xffffffffu, s2, 8);
        float mu = s1 * (1.0f / 128.0f);
        float var = fmaxf(s2 * (1.0f / 128.0f) - mu * mu, 0.0f);
        float rs = rsqrtf(var + 1e-5f);
        int ti = t >> 3, tj = t & 7;
        int hh = (wy * 8 + ti + 4) & 127;
        int ww = (wx * 8 + tj + 4) & 127;
        float* dst = &g_x1[((size_t)b * HW + hh * 128 + ww) * 128];
#pragma unroll
        for (int cp = 0; cp < 4; cp++) {
            unsigned uh = smu[XHI + t * 68 + ln * 4 + cp];
            unsigned ul = smu[XLO + t * 68 + ln * 4 + cp];
            float2 fh = unpack2(uh), fl = unpack2(ul);
            int cc = cb + 2 * cp;
            float l0 = (prow[cc] - mu) * rs * n1w[cc] + n1b[cc];
            float l1 = (prow[cc + 1] - mu) * rs * n1w[cc + 1] + n1b[cc + 1];
            dst[cc]     = fh.x + fl.x + l0;
            dst[cc + 1] = fh.y + fl.y + l1;
        }
    }
}

// ------------------- K2: MLP (1024 thr, cp.async pipeline) ------------------
#define K2XHI 0
#define K2XLO 8704
#define K2W1  17408    // 2 bufs * 8704
#define K2W2H 34816
#define K2W2L 39424
#define K2HH  44032
#define K2HL  48640
#define K2Y   17408
#define K2_SMEM (53248 * 4)

__global__ void __launch_bounds__(1024, 1)
k2_mlp(const float* __restrict__ n2w, const float* __restrict__ n2b,
       const float* __restrict__ b1, const float* __restrict__ b2,
       float* __restrict__ out) {
    extern __shared__ float sm[];
    unsigned* smu = (unsigned*)sm;
    int tid = threadIdx.x;
    int wid = tid >> 5, lane = tid & 31;
    int g = lane >> 2, q = lane & 3;
    int p0 = blockIdx.x * 128;
    int b = p0 >> 14, h = (p0 >> 7) & 127;

    // prologue: async-stage W1 chunk 0 into buf 0
    {
        int r = tid >> 4, cq = (tid & 15) << 2;
        cpa16(&smu[K2W1 + r * 68 + cq], &g_f1h[r * 64 + cq]);
        cpa16(&smu[K2W1 + 4352 + r * 68 + cq], &g_f1l[r * 64 + cq]);
        CP_COMMIT();
    }

    // load + split x1 (128 tokens) — overlaps the W1 prefetch
#pragma unroll
    for (int it = 0; it < 8; it++) {
        int idx = it * 1024 + tid;
        int cp = idx & 63, t = idx >> 6;
        float2 v = *(const float2*)&g_x1[((size_t)p0 + t) * 128 + 2 * cp];
        split2(v.x, v.y, smu[K2XHI + t * 68 + cp], smu[K2XLO + t * 68 + cp]);
    }

    int mi = wid & 7, nh = wid >> 3;   // 8 mi x 4 nh
    int m0 = mi * 16;
    float acc2[2][2][4];
#pragma unroll
    for (int t = 0; t < 2; t++)
#pragma unroll
        for (int u = 0; u < 2; u++)
#pragma unroll
            for (int j = 0; j < 4; j++) acc2[t][u][j] = 0.f;

    for (int ch = 0; ch < 8; ch++) {
        int cur = ch & 1, nxt = cur ^ 1;
        const unsigned* W1H = smu + K2W1 + cur * 8704;
        const unsigned* W1L = W1H + 4352;
        CP_WAIT0();
        __syncthreads();
        // async-stage W2 k-slice
        {
            int r = tid >> 3, cq = (tid & 7) << 2;
            cpa16(&smu[K2W2H + r * 36 + cq], &g_f2h[r * 256 + ch * 32 + cq]);
            cpa16(&smu[K2W2L + r * 36 + cq], &g_f2l[r * 256 + ch * 32 + cq]);
        }
        CP_COMMIT();
        // fc1: warp m16 x n16
        float acc[2][4] = {};
        int n0f = nh * 16;
#pragma unroll
        for (int ks = 0; ks < 8; ks++) {
            int kp = ks * 8;
            unsigned ah0, ah1, ah2, ah3, al0, al1, al2, al3;
            ldsm4(smu + K2XHI, 68, m0, kp, ah0, ah1, ah2, ah3);
            ldsm4(smu + K2XLO, 68, m0, kp, al0, al1, al2, al3);
            unsigned bh0, bh1, bh2, bh3, bl0, bl1, bl2, bl3;
            ldsm4(W1H, 68, n0f, kp, bh0, bh1, bh2, bh3);
            ldsm4(W1L, 68, n0f, kp, bl0, bl1, bl2, bl3);
            mma_bf16(acc[0], ah0, ah1, ah2, ah3, bh0, bh2);
            mma_bf16(acc[0], ah0, ah1, ah2, ah3, bl0, bl2);
            mma_bf16(acc[0], al0, al1, al2, al3, bh0, bh2);
            mma_bf16(acc[1], ah0, ah1, ah2, ah3, bh1, bh3);
            mma_bf16(acc[1], ah0, ah1, ah2, ah3, bl1, bl3);
            mma_bf16(acc[1], al0, al1, al2, al3, bh1, bh3);
        }
        // silu + split -> H
#pragma unroll
        for (int nt = 0; nt < 2; nt++) {
            int c0 = n0f + nt * 8 + 2 * q;
            int col = ch * 64 + c0;
            float v0 = acc[nt][0] + b1[col],     v1 = acc[nt][1] + b1[col + 1];
            float v2 = acc[nt][2] + b1[col],     v3 = acc[nt][3] + b1[col + 1];
            v0 = v0 / (1.0f + __expf(-v0));
            v1 = v1 / (1.0f + __expf(-v1));
            v2 = v2 / (1.0f + __expf(-v2));
            v3 = v3 / (1.0f + __expf(-v3));
            int pp = (c0 >> 1);
            split2(v0, v1, smu[K2HH + (m0 + g) * 36 + pp], smu[K2HL + (m0 + g) * 36 + pp]);
            split2(v2, v3, smu[K2HH + (m0 + g + 8) * 36 + pp], smu[K2HL + (m0 + g + 8) * 36 + pp]);
        }
        CP_WAIT0();
        __syncthreads();
        // async-stage next W1 (overlaps fc2)
        if (ch < 7) {
            int r = tid >> 4, cq = (tid & 15) << 2;
            cpa16(&smu[K2W1 + nxt * 8704 + r * 68 + cq],
                  &g_f1h[((ch + 1) * 64 + r) * 64 + cq]);
            cpa16(&smu[K2W1 + nxt * 8704 + 4352 + r * 68 + cq],
                  &g_f1l[((ch + 1) * 64 + r) * 64 + cq]);
        }
        CP_COMMIT();
        // fc2 partial: warp m16 x n32
#pragma unroll
        for (int ks = 0; ks < 4; ks++) {
            int kp = ks * 8;
            unsigned ah0, ah1, ah2, ah3, al0, al1, al2, al3;
            ldsm4(smu + K2HH, 36, m0, kp, ah0, ah1, ah2, ah3);
            ldsm4(smu + K2HL, 36, m0, kp, al0, al1, al2, al3);
#pragma unroll
            for (int tp = 0; tp < 2; tp++) {
                unsigned bh0, bh1, bh2, bh3, bl0, bl1, bl2, bl3;
                ldsm4(smu + K2W2H, 36, nh * 32 + 16 * tp, kp, bh0, bh1, bh2, bh3);
                ldsm4(smu + K2W2L, 36, nh * 32 + 16 * tp, kp, bl0, bl1, bl2, bl3);
                mma_bf16(acc2[tp][0], ah0, ah1, ah2, ah3, bh0, bh2);
                mma_bf16(acc2[tp][0], ah0, ah1, ah2, ah3, bl0, bl2);
                mma_bf16(acc2[tp][0], al0, al1, al2, al3, bh0, bh2);
                mma_bf16(acc2[tp][1], ah0, ah1, ah2, ah3, bh1, bh3);
                mma_bf16(acc2[tp][1], ah0, ah1, ah2, ah3, bl1, bl3);
                mma_bf16(acc2[tp][1], al0, al1, al2, al3, bh1, bh3);
            }
        }
    }
    CP_WAIT0();
    __syncthreads();
    // Y = fc2 out + bias
#pragma unroll
    for (int tp = 0; tp < 2; tp++)
#pragma unroll
        for (int u = 0; u < 2; u++) {
            int col = nh * 32 + tp * 16 + u * 8 + 2 * q;
            sm[K2Y + (m0 + g) * 133 + col]         = acc2[tp][u][0] + b2[col];
            sm[K2Y + (m0 + g) * 133 + col + 1]     = acc2[tp][u][1] + b2[col + 1];
            sm[K2Y + (m0 + g + 8) * 133 + col]     = acc2[tp][u][2] + b2[col];
            sm[K2Y + (m0 + g + 8) * 133 + col + 1] = acc2[tp][u][3] + b2[col + 1];
        }
    __syncthreads();
    // LN + residual, 8 threads/row
    {
        int t = tid >> 3, ln = tid & 7;
        float* yrow = &sm[K2Y + t * 133];
        int cb = ln * 16;
        float s1 = 0.f, s2 = 0.f;
#pragma unroll
        for (int c = 0; c < 16; c++) {
            float v = yrow[cb + c];
            s1 += v; s2 += v * v;
        }
        s1 += __shfl_xor_sync(0xffffffffu, s1, 1);
        s2 += __shfl_xor_sync(0xffffffffu, s2, 1);
        s1 += __shfl_xor_sync(0xffffffffu, s1, 2);
        s2 += __shfl_xor_sync(0xffffffffu, s2, 2);
        s1 += __shfl_xor_sync(0xffffffffu, s1, 4);
        s2 += __shfl_xor_sync(0xffffffffu, s2, 4);
        float mu = s1 * (1.0f / 128.0f);
        float var = fmaxf(s2 * (1.0f / 128.0f) - mu * mu, 0.0f);
        float rs = rsqrtf(var + 1e-5f);
#pragma unroll
        for (int cp = 0; cp < 8; cp++) {
            unsigned uh = smu[K2XHI + t * 68 + (cb >> 1) + cp];
            unsigned ul = smu[K2XLO + t * 68 + (cb >> 1) + cp];
            float2 fh = unpack2(uh), fl = unpack2(ul);
            int cc = cb + 2 * cp;
            float l0 = (yrow[cc] - mu) * rs * n2w[cc] + n2b[cc];
            float l1 = (yrow[cc + 1] - mu) * rs * n2w[cc + 1] + n2b[cc + 1];
            yrow[cc]     = fh.x + fl.x + l0;
            yrow[cc + 1] = fh.y + fl.y + l1;
        }
    }
    __syncthreads();
    // transposed store -> NCHW
    {
        float* ob = out + (size_t)b * 128 * HW + h * 128;
#pragma unroll
        for (int it = 0; it < 16; it++) {
            int idx = it * 1024 + tid;
            int c = idx >> 7, w = idx & 127;
            ob[(size_t)c * HW + w] = sm[K2Y + w * 133 + c];
        }
    }
}

// ------------------------------ launch --------------------------------------
extern "C" void kernel_launch(void* const* d_in, const int* in_sizes, int n_in,
                              void* d_out, int out_size) {
    const float* x    = (const float*)d_in[0];
    const float* n1w  = (const float*)d_in[1];
    const float* n1b  = (const float*)d_in[2];
    const float* qkvw = (const float*)d_in[3];
    const float* qb   = (const float*)d_in[4];
    const float* vb   = (const float*)d_in[5];
    const float* ls   = (const float*)d_in[6];
    const float* cw1  = (const float*)d_in[7];
    const float* cb1  = (const float*)d_in[8];
    const float* cw2  = (const float*)d_in[9];
    const float* pw   = (const float*)d_in[10];
    const float* pb   = (const float*)d_in[11];
    const float* n2w  = (const float*)d_in[12];
    const float* n2b  = (const float*)d_in[13];
    const float* f1w  = (const float*)d_in[14];
    const float* f1b  = (const float*)d_in[15];
    const float* f2w  = (const float*)d_in[16];
    const float* f2b  = (const float*)d_in[17];
    float* out = (float*)d_out;

    cudaFuncSetAttribute(k1_attn, cudaFuncAttributeMaxDynamicSharedMemorySize, K1_SMEM);
    cudaFuncSetAttribute(k2_mlp,  cudaFuncAttributeMaxDynamicSharedMemorySize, K2_SMEM);

    k0_bias<<<1, 256>>>(cw1, cb1, cw2);
    k0_wsplit<<<384, 256>>>(qkvw, pw, f1w, f2w);
    k1_attn<<<4096, 1024, K1_SMEM>>>(x, n1w, n1b, qb, vb, ls, pb);
    k2_mlp<<<2048, 1024, K2_SMEM>>>(n2w, n2b, f1b, f2b, out);
}

// round 15
// speedup vs baseline: 1.0823x; 1.0051x over previous
#include <cuda_runtime.h>
#include <cuda_bf16.h>
#include <math.h>

#define HW 16384
#define LOG100f 4.605170185988092f

__device__ float g_bias16[4 * 64 * 64];
__device__ unsigned g_qkvh[24576], g_qkvl[24576];   // [384][64]
__device__ unsigned g_pwh[8192],   g_pwl[8192];     // [128][64]
__device__ unsigned g_f1h[32768],  g_f1l[32768];    // [512][64]
__device__ unsigned g_f2h[32768],  g_f2l[32768];    // [128][256]

// ---------------------------------------------------------------------------
__device__ __forceinline__ void mma_bf16(float d[4], unsigned a0, unsigned a1,
                                         unsigned a2, unsigned a3,
                                         unsigned b0, unsigned b1) {
    asm volatile(
        "mma.sync.aligned.m16n8k16.row.col.f32.bf16.bf16.f32 "
        "{%0,%1,%2,%3},{%4,%5,%6,%7},{%8,%9},{%0,%1,%2,%3};"
        : "+f"(d[0]), "+f"(d[1]), "+f"(d[2]), "+f"(d[3])
        : "r"(a0), "r"(a1), "r"(a2), "r"(a3), "r"(b0), "r"(b1));
}

__device__ __forceinline__ void ldsm4(const unsigned* base, int P, int r0, int kp,
                                      unsigned& o0, unsigned& o1, unsigned& o2, unsigned& o3) {
    int lane = threadIdx.x & 31;
    const unsigned* p = base + (r0 + (lane & 15)) * P + kp + ((lane >> 4) << 2);
    unsigned a = (unsigned)__cvta_generic_to_shared(p);
    asm volatile("ldmatrix.sync.aligned.m8n8.x4.shared.b16 {%0,%1,%2,%3}, [%4];"
                 : "=r"(o0), "=r"(o1), "=r"(o2), "=r"(o3) : "r"(a));
}

__device__ __forceinline__ void cpa16(unsigned* dst, const unsigned* src) {
    unsigned d = (unsigned)__cvta_generic_to_shared(dst);
    asm volatile("cp.async.cg.shared.global [%0], [%1], 16;" :: "r"(d), "l"(src));
}
#define CP_COMMIT() asm volatile("cp.async.commit_group;" ::: "memory")
#define CP_WAIT0()  asm volatile("cp.async.wait_group 0;" ::: "memory")

__device__ __forceinline__ void split2(float v0, float v1, unsigned& hi, unsigned& lo) {
    __nv_bfloat16 h0 = __float2bfloat16(v0);
    __nv_bfloat16 h1 = __float2bfloat16(v1);
    float r0 = v0 - __bfloat162float(h0);
    float r1 = v1 - __bfloat162float(h1);
    __nv_bfloat16 l0 = __float2bfloat16(r0);
    __nv_bfloat16 l1 = __float2bfloat16(r1);
    hi = (unsigned)__bfloat16_as_ushort(h0) | ((unsigned)__bfloat16_as_ushort(h1) << 16);
    lo = (unsigned)__bfloat16_as_ushort(l0) | ((unsigned)__bfloat16_as_ushort(l1) << 16);
}

__device__ __forceinline__ float2 unpack2(unsigned u) {
    __nv_bfloat162 b = *reinterpret_cast<__nv_bfloat162*>(&u);
    return __bfloat1622float2(b);
}

// ------------------------------ K0 ------------------------------------------
__global__ void k0_bias(const float* __restrict__ w1, const float* __restrict__ b1,
                        const float* __restrict__ w2) {
    __shared__ float tab[225][4];
    int tid = threadIdx.x;
    if (tid < 225) {
        int a = tid / 15, bb = tid % 15;
        float v0 = (a - 7) * (8.0f / 7.0f), v1 = (bb - 7) * (8.0f / 7.0f);
        float g0 = copysignf(log2f(fabsf(v0) + 1.0f) * (1.0f / 3.0f), v0);
        float g1 = copysignf(log2f(fabsf(v1) + 1.0f) * (1.0f / 3.0f), v1);
        float o0 = 0, o1 = 0, o2 = 0, o3 = 0;
        for (int j = 0; j < 512; j++) {
            float hv = fmaxf(w1[2 * j] * g0 + w1[2 * j + 1] * g1 + b1[j], 0.0f);
            o0 += hv * w2[j];        o1 += hv * w2[512 + j];
            o2 += hv * w2[1024 + j]; o3 += hv * w2[1536 + j];
        }
        tab[tid][0] = o0; tab[tid][1] = o1; tab[tid][2] = o2; tab[tid][3] = o3;
    }
    __syncthreads();
    for (int e = tid; e < 4 * 64 * 64; e += blockDim.x) {
        int h = e >> 12, i = (e >> 6) & 63, j = e & 63;
        int dy = (i >> 3) - (j >> 3) + 7, dx = (i & 7) - (j & 7) + 7;
        float v = tab[dy * 15 + dx][h];
        g_bias16[e] = 16.0f / (1.0f + expf(-v));
    }
}

__device__ __forceinline__ void splitpair(const float* w, unsigned* hi, unsigned* lo, int i) {
    split2(w[2 * i], w[2 * i + 1], hi[i], lo[i]);
}

__global__ void k0_wsplit(const float* __restrict__ qkvw, const float* __restrict__ pw,
                          const float* __restrict__ f1w, const float* __restrict__ f2w) {
    int i = blockIdx.x * 256 + threadIdx.x;
    if (i < 24576)       splitpair(qkvw, g_qkvh, g_qkvl, i);
    else if (i < 32768)  splitpair(pw,  g_pwh,  g_pwl,  i - 24576);
    else if (i < 65536)  splitpair(f1w, g_f1h,  g_f1l,  i - 32768);
    else if (i < 98304)  splitpair(f2w, g_f2h,  g_f2l,  i - 65536);
}

// ------------------- fused attention + MLP (1024 thr) -----------------------
#define XHI   0        // [64][68] x splits; after phase 7: x1 splits
#define XLO   4352
#define QSPH  8704
#define QSPL  13056
#define KSPH  17408
#define KSPL  21760
#define PHI_  8704
#define PLO_  17920
#define WPH   8704
#define WPL   17408
#define VSPH  27136
#define VSPL  31744
#define WQH   36352
#define WQL   45056
#define ATTN_ 36352
#define OHI_  36352
#define OLO_  40704
#define POUT  45056
// MLP regions (all alias dead attention scratch)
#define MW1H  8704     // [128][68] -> 17408
#define MW1L  17408    // -> 26112
#define MW2H  26112    // [128][68] -> 34816
#define MW2L  34816    // -> 43520
#define MHH   43520    // [64][68] -> 47872
#define MHL   47872    // -> 52224
#define MY    8704     // [64][133] = 8512 (aliases dead W1)
#define RG_   53760
#define IQ_   53824
#define IK_   54080
#define K1_SMEM (54336 * 4)

__global__ void __launch_bounds__(1024, 1)
kfused(const float* __restrict__ x,
       const float* __restrict__ n1w, const float* __restrict__ n1b,
       const float* __restrict__ qb, const float* __restrict__ vb,
       const float* __restrict__ ls, const float* __restrict__ pb,
       const float* __restrict__ n2w, const float* __restrict__ n2b,
       const float* __restrict__ b1, const float* __restrict__ b2,
       float* __restrict__ out) {
    extern __shared__ float sm[];
    unsigned* smu = (unsigned*)sm;
    int tid = threadIdx.x;
    int wid = tid >> 5, lane = tid & 31;
    int g = lane >> 2, q = lane & 3;
    int b = blockIdx.x >> 8, widx = blockIdx.x & 255;
    int wy = widx >> 4, wx = widx & 15;

    // prologue: prefetch QKV chunk-0 weights
    {
#pragma unroll
        for (int it = 0; it < 2; it++) {
            int j = it * 1024 + tid;
            int r = j >> 4, cq = (j & 15) << 2;
            cpa16(&smu[WQH + r * 68 + cq], &g_qkvh[r * 64 + cq]);
            cpa16(&smu[WQL + r * 68 + cq], &g_qkvl[r * 64 + cq]);
        }
        CP_COMMIT();
    }

    // phase 0: gather shifted window -> split [t][cpair]
    {
        const float* xb = x + (size_t)b * 128 * HW;
#pragma unroll
        for (int it = 0; it < 4; it++) {
            int idx = it * 1024 + tid;
            int t = idx & 63, cp = idx >> 6;
            int ti = t >> 3, tj = t & 7;
            int hh = (wy * 8 + ti + 4) & 127;
            int ww = (wx * 8 + tj + 4) & 127;
            const float* p = xb + (size_t)(2 * cp) * HW + hh * 128 + ww;
            float v0 = p[0], v1 = p[HW];
            split2(v0, v1, smu[XHI + t * 68 + cp], smu[XLO + t * 68 + cp]);
        }
        if (tid < 64) {
            int ti = tid >> 3, tj = tid & 7;
            int hs = wy * 8 + ti, ws = wx * 8 + tj;
            int hr = hs < 120 ? 0 : (hs < 124 ? 1 : 2);
            int wr = ws < 120 ? 0 : (ws < 124 ? 1 : 2);
            sm[RG_ + tid] = (float)(hr * 3 + wr);
        }
    }

    int mi = wid & 3;
    int m0 = mi * 16;

    // phase 1: QKV GEMM, 3 chunks of 128 cols, 4 mi x 8 nw warps
    {
        int nw = wid >> 2;
        int n0 = nw * 16;
        for (int ch = 0; ch < 3; ch++) {
            if (ch > 0) {
                __syncthreads();
#pragma unroll
                for (int it = 0; it < 2; it++) {
                    int j = it * 1024 + tid;
                    int r = j >> 4, cq = (j & 15) << 2;
                    cpa16(&smu[WQH + r * 68 + cq], &g_qkvh[(ch * 128 + r) * 64 + cq]);
                    cpa16(&smu[WQL + r * 68 + cq], &g_qkvl[(ch * 128 + r) * 64 + cq]);
                }
                CP_COMMIT();
            }
            CP_WAIT0();
            __syncthreads();
            float acc[2][4] = {};
#pragma unroll
            for (int ks = 0; ks < 8; ks++) {
                int kp = ks * 8;
                unsigned ah0, ah1, ah2, ah3, al0, al1, al2, al3;
                ldsm4(smu + XHI, 68, m0, kp, ah0, ah1, ah2, ah3);
                ldsm4(smu + XLO, 68, m0, kp, al0, al1, al2, al3);
                unsigned bh0, bh1, bh2, bh3, bl0, bl1, bl2, bl3;
                ldsm4(smu + WQH, 68, n0, kp, bh0, bh1, bh2, bh3);
                ldsm4(smu + WQL, 68, n0, kp, bl0, bl1, bl2, bl3);
                mma_bf16(acc[0], ah0, ah1, ah2, ah3, bh0, bh2);
                mma_bf16(acc[0], ah0, ah1, ah2, ah3, bl0, bl2);
                mma_bf16(acc[0], al0, al1, al2, al3, bh0, bh2);
                mma_bf16(acc[1], ah0, ah1, ah2, ah3, bh1, bh3);
                mma_bf16(acc[1], ah0, ah1, ah2, ah3, bl1, bl3);
                mma_bf16(acc[1], al0, al1, al2, al3, bh1, bh3);
            }
            int r0 = m0 + g, r1 = r0 + 8;
            if (ch == 0) {          // Q
#pragma unroll
                for (int nt = 0; nt < 2; nt++) {
                    int col0 = n0 + nt * 8 + 2 * q;
                    float b0c = qb[col0], b1c = qb[col0 + 1];
                    int dp = col0 >> 1;
                    split2(acc[nt][0] + b0c, acc[nt][1] + b1c,
                           smu[QSPH + r0 * 68 + dp], smu[QSPL + r0 * 68 + dp]);
                    split2(acc[nt][2] + b0c, acc[nt][3] + b1c,
                           smu[QSPH + r1 * 68 + dp], smu[QSPL + r1 * 68 + dp]);
                }
            } else if (ch == 1) {   // K
#pragma unroll
                for (int nt = 0; nt < 2; nt++) {
                    int col0 = n0 + nt * 8 + 2 * q;
                    int dp = col0 >> 1;
                    split2(acc[nt][0], acc[nt][1],
                           smu[KSPH + r0 * 68 + dp], smu[KSPL + r0 * 68 + dp]);
                    split2(acc[nt][2], acc[nt][3],
                           smu[KSPH + r1 * 68 + dp], smu[KSPL + r1 * 68 + dp]);
                }
            } else {                // V -> [d][upair]
#pragma unroll
                for (int nt = 0; nt < 2; nt++) {
                    int d0 = n0 + nt * 8 + 2 * q;
                    float v0 = acc[nt][0] + vb[d0], v1 = acc[nt][1] + vb[d0 + 1];
                    float v2 = acc[nt][2] + vb[d0], v3 = acc[nt][3] + vb[d0 + 1];
                    float p0 = __shfl_xor_sync(0xffffffffu, v0, 4);
                    float p1 = __shfl_xor_sync(0xffffffffu, v1, 4);
                    float p2 = __shfl_xor_sync(0xffffffffu, v2, 4);
                    float p3 = __shfl_xor_sync(0xffffffffu, v3, 4);
                    if (!(g & 1)) {
                        int up = (m0 + g) >> 1;
                        split2(v0, p0, smu[VSPH + d0 * 36 + up], smu[VSPL + d0 * 36 + up]);
                        split2(v1, p1, smu[VSPH + (d0 + 1) * 36 + up], smu[VSPL + (d0 + 1) * 36 + up]);
                    } else {
                        int up = (m0 + g + 7) >> 1;
                        split2(p2, v2, smu[VSPH + d0 * 36 + up], smu[VSPL + d0 * 36 + up]);
                        split2(p3, v3, smu[VSPH + (d0 + 1) * 36 + up], smu[VSPL + (d0 + 1) * 36 + up]);
                    }
                }
            }
        }
    }
    __syncthreads();

    // phase 2: inverse norms
    {
        int qk = tid >> 9, rem = tid & 511;
        int h = rem >> 7, sub = rem & 127;
        int t = sub >> 1, half = sub & 1;
        int base = (qk ? KSPH : QSPH) + t * 68 + h * 16 + half * 8;
        int baseL = base + 4352;
        float s = 0.f;
#pragma unroll
        for (int i = 0; i < 8; i++) {
            float2 fh = unpack2(smu[base + i]);
            float2 fl = unpack2(smu[baseL + i]);
            float a0 = fh.x + fl.x, a1 = fh.y + fl.y;
            s += a0 * a0 + a1 * a1;
        }
        s += __shfl_xor_sync(0xffffffffu, s, 1);
        if (half == 0)
            sm[(qk ? IK_ : IQ_) + h * 64 + t] = 1.0f / fmaxf(sqrtf(s), 1e-12f);
    }
    __syncthreads();

    // phase 3: logits MMA
    {
        int hw = wid >> 3, nhalf = (wid >> 2) & 1;
        float scale = __expf(fminf(ls[hw], LOG100f));
        float acc[2][2][4];
#pragma unroll
        for (int i = 0; i < 2; i++)
#pragma unroll
            for (int j = 0; j < 2; j++)
#pragma unroll
                for (int k = 0; k < 4; k++) acc[i][j][k] = 0.f;
#pragma unroll
        for (int ks = 0; ks < 2; ks++) {
            int kp = hw * 16 + ks * 8;
            unsigned ah0, ah1, ah2, ah3, al0, al1, al2, al3;
            ldsm4(smu + QSPH, 68, m0, kp, ah0, ah1, ah2, ah3);
            ldsm4(smu + QSPL, 68, m0, kp, al0, al1, al2, al3);
#pragma unroll
            for (int nh = 0; nh < 2; nh++) {
                int nr = nhalf * 32 + nh * 16;
                unsigned bh0, bh1, bh2, bh3, bl0, bl1, bl2, bl3;
                ldsm4(smu + KSPH, 68, nr, kp, bh0, bh1, bh2, bh3);
                ldsm4(smu + KSPL, 68, nr, kp, bl0, bl1, bl2, bl3);
                mma_bf16(acc[nh][0], ah0, ah1, ah2, ah3, bh0, bh2);
                mma_bf16(acc[nh][0], ah0, ah1, ah2, ah3, bl0, bl2);
                mma_bf16(acc[nh][0], al0, al1, al2, al3, bh0, bh2);
                mma_bf16(acc[nh][1], ah0, ah1, ah2, ah3, bh1, bh3);
                mma_bf16(acc[nh][1], ah0, ah1, ah2, ah3, bl1, bl3);
                mma_bf16(acc[nh][1], al0, al1, al2, al3, bh1, bh3);
            }
        }
        int r0 = m0 + g, r1 = r0 + 8;
        float iq0 = sm[IQ_ + hw * 64 + r0] * scale;
        float iq1 = sm[IQ_ + hw * 64 + r1] * scale;
        float rt0 = sm[RG_ + r0], rt1 = sm[RG_ + r1];
        float* A = &sm[ATTN_ + hw * 4352];
#pragma unroll
        for (int nh = 0; nh < 2; nh++)
#pragma unroll
            for (int nt = 0; nt < 2; nt++) {
                int col = nhalf * 32 + nh * 16 + nt * 8 + 2 * q;
                float ik0 = sm[IK_ + hw * 64 + col], ik1 = sm[IK_ + hw * 64 + col + 1];
                float ru0 = sm[RG_ + col], ru1 = sm[RG_ + col + 1];
                float2 b0v = *(const float2*)&g_bias16[(hw * 64 + r0) * 64 + col];
                float2 b1v = *(const float2*)&g_bias16[(hw * 64 + r1) * 64 + col];
                A[r0 * 68 + col]     = acc[nh][nt][0] * iq0 * ik0 + b0v.x + (rt0 != ru0 ? -100.f : 0.f);
                A[r0 * 68 + col + 1] = acc[nh][nt][1] * iq0 * ik1 + b0v.y + (rt0 != ru1 ? -100.f : 0.f);
                A[r1 * 68 + col]     = acc[nh][nt][2] * iq1 * ik0 + b1v.x + (rt1 != ru0 ? -100.f : 0.f);
                A[r1 * 68 + col + 1] = acc[nh][nt][3] * iq1 * ik1 + b1v.y + (rt1 != ru1 ? -100.f : 0.f);
            }
    }
    __syncthreads();

    // phase 4: softmax -> P splits
    {
        int r = tid >> 2, qt = tid & 3;
        int hw = r >> 6, t = r & 63;
        const float* row = &sm[ATTN_ + hw * 4352 + t * 68 + qt * 16];
        float e[16];
        float mx = -1e30f;
#pragma unroll
        for (int i = 0; i < 16; i++) { e[i] = row[i]; mx = fmaxf(mx, e[i]); }
        mx = fmaxf(mx, __shfl_xor_sync(0xffffffffu, mx, 1));
        mx = fmaxf(mx, __shfl_xor_sync(0xffffffffu, mx, 2));
        float s = 0.f;
#pragma unroll
        for (int i = 0; i < 16; i++) { e[i] = __expf(e[i] - mx); s += e[i]; }
        s += __shfl_xor_sync(0xffffffffu, s, 1);
        s += __shfl_xor_sync(0xffffffffu, s, 2);
        float inv = 1.0f / s;
        int pb_ = hw * 2304 + t * 36 + qt * 8;
#pragma unroll
        for (int i = 0; i < 8; i++)
            split2(e[2 * i] * inv, e[2 * i + 1] * inv,
                   smu[PHI_ + pb_ + i], smu[PLO_ + pb_ + i]);
    }
    __syncthreads();

    // phase 5: PV MMA
    {
        int hw = wid >> 3, nd = (wid >> 2) & 1;
        const unsigned* PH = smu + PHI_ + hw * 2304;
        const unsigned* PL = smu + PLO_ + hw * 2304;
        float acc[2][4] = {};
#pragma unroll
        for (int ks = 0; ks < 4; ks++) {
            int kp = ks * 8;
            unsigned ah0, ah1, ah2, ah3, al0, al1, al2, al3;
            ldsm4(PH, 36, m0, kp, ah0, ah1, ah2, ah3);
            ldsm4(PL, 36, m0, kp, al0, al1, al2, al3);
            int n0v = hw * 32 + nd * 16;
            unsigned bh0, bh1, bh2, bh3, bl0, bl1, bl2, bl3;
            ldsm4(smu + VSPH, 36, n0v, kp, bh0, bh1, bh2, bh3);
            ldsm4(smu + VSPL, 36, n0v, kp, bl0, bl1, bl2, bl3);
            mma_bf16(acc[0], ah0, ah1, ah2, ah3, bh0, bh2);
            mma_bf16(acc[0], ah0, ah1, ah2, ah3, bl0, bl2);
            mma_bf16(acc[0], al0, al1, al2, al3, bh0, bh2);
            mma_bf16(acc[1], ah0, ah1, ah2, ah3, bh1, bh3);
            mma_bf16(acc[1], ah0, ah1, ah2, ah3, bl1, bl3);
            mma_bf16(acc[1], al0, al1, al2, al3, bh1, bh3);
        }
        int r0 = m0 + g, r1 = r0 + 8;
#pragma unroll
        for (int nt = 0; nt < 2; nt++) {
            int dglob = hw * 32 + nd * 16 + nt * 8 + 2 * q;
            int dp = dglob >> 1;
            split2(acc[nt][0], acc[nt][1],
                   smu[OHI_ + r0 * 68 + dp], smu[OLO_ + r0 * 68 + dp]);
            split2(acc[nt][2], acc[nt][3],
                   smu[OHI_ + r1 * 68 + dp], smu[OLO_ + r1 * 68 + dp]);
        }
    }

    // phase 6: proj GEMM (cp.async staged)
    {
        int nw = wid >> 2;
        int n0 = nw * 16;
        __syncthreads();
#pragma unroll
        for (int it = 0; it < 2; it++) {
            int j = it * 1024 + tid;
            int r = j >> 4, cq = (j & 15) << 2;
            cpa16(&smu[WPH + r * 68 + cq], &g_pwh[r * 64 + cq]);
            cpa16(&smu[WPL + r * 68 + cq], &g_pwl[r * 64 + cq]);
        }
        CP_COMMIT();
        CP_WAIT0();
        __syncthreads();
        float acc[2][4] = {};
#pragma unroll
        for (int ks = 0; ks < 8; ks++) {
            int kp = ks * 8;
            unsigned ah0, ah1, ah2, ah3, al0, al1, al2, al3;
            ldsm4(smu + OHI_, 68, m0, kp, ah0, ah1, ah2, ah3);
            ldsm4(smu + OLO_, 68, m0, kp, al0, al1, al2, al3);
            unsigned bh0, bh1, bh2, bh3, bl0, bl1, bl2, bl3;
            ldsm4(smu + WPH, 68, n0, kp, bh0, bh1, bh2, bh3);
            ldsm4(smu + WPL, 68, n0, kp, bl0, bl1, bl2, bl3);
            mma_bf16(acc[0], ah0, ah1, ah2, ah3, bh0, bh2);
            mma_bf16(acc[0], ah0, ah1, ah2, ah3, bl0, bl2);
            mma_bf16(acc[0], al0, al1, al2, al3, bh0, bh2);
            mma_bf16(acc[1], ah0, ah1, ah2, ah3, bh1, bh3);
            mma_bf16(acc[1], ah0, ah1, ah2, ah3, bl1, bl3);
            mma_bf16(acc[1], al0, al1, al2, al3, bh1, bh3);
        }
        int r0 = m0 + g, r1 = r0 + 8;
#pragma unroll
        for (int nt = 0; nt < 2; nt++) {
            int col0 = n0 + nt * 8 + 2 * q;
            sm[POUT + r0 * 132 + col0]     = acc[nt][0] + pb[col0];
            sm[POUT + r0 * 132 + col0 + 1] = acc[nt][1] + pb[col0 + 1];
            sm[POUT + r1 * 132 + col0]     = acc[nt][2] + pb[col0];
            sm[POUT + r1 * 132 + col0 + 1] = acc[nt][3] + pb[col0 + 1];
        }
    }
    __syncthreads();

    // prefetch W1 chunk 0 (region WPH dead after sync above)
    {
#pragma unroll
        for (int it = 0; it < 2; it++) {
            int j = it * 1024 + tid;
            int r = j >> 4, cq = (j & 15) << 2;
            cpa16(&smu[MW1H + r * 68 + cq], &g_f1h[r * 64 + cq]);
            cpa16(&smu[MW1L + r * 68 + cq], &g_f1l[r * 64 + cq]);
        }
        CP_COMMIT();
    }

    // phase 7: LN + residual -> x1 splits in place (XHI/XLO)
    {
        int t = tid >> 4, ln = tid & 15;
        const float* prow = &sm[POUT + t * 132];
        int cb = ln * 8;
        float s1 = 0.f, s2 = 0.f;
#pragma unroll
        for (int c = 0; c < 8; c++) {
            float v = prow[cb + c];
            s1 += v; s2 += v * v;
        }
        s1 += __shfl_xor_sync(0xffffffffu, s1, 1);
        s2 += __shfl_xor_sync(0xffffffffu, s2, 1);
        s1 += __shfl_xor_sync(0xffffffffu, s1, 2);
        s2 += __shfl_xor_sync(0xffffffffu, s2, 2);
        s1 += __shfl_xor_sync(0xffffffffu, s1, 4);
        s2 += __shfl_xor_sync(0xffffffffu, s2, 4);
        s1 += __shfl_xor_sync(0xffffffffu, s1, 8);
        s2 += __shfl_xor_sync(0xffffffffu, s2, 8);
        float mu = s1 * (1.0f / 128.0f);
        float var = fmaxf(s2 * (1.0f / 128.0f) - mu * mu, 0.0f);
        float rs = rsqrtf(var + 1e-5f);
#pragma unroll
        for (int cp = 0; cp < 4; cp++) {
            unsigned uh = smu[XHI + t * 68 + ln * 4 + cp];
            unsigned ul = smu[XLO + t * 68 + ln * 4 + cp];
            float2 fh = unpack2(uh), fl = unpack2(ul);
            int cc = cb + 2 * cp;
            float x1a = fh.x + fl.x + (prow[cc] - mu) * rs * n1w[cc] + n1b[cc];
            float x1b = fh.y + fl.y + (prow[cc + 1] - mu) * rs * n1w[cc + 1] + n1b[cc + 1];
            split2(x1a, x1b, smu[XHI + t * 68 + ln * 4 + cp], smu[XLO + t * 68 + ln * 4 + cp]);
        }
    }
    __syncthreads();

    // ---- MLP on this CTA's 64 tokens: 4 chunks of 128 hidden ----
    {
        int nw = wid >> 2;
        int n0 = nw * 16;
        float acc2[2][4];
#pragma unroll
        for (int t = 0; t < 2; t++)
#pragma unroll
            for (int j = 0; j < 4; j++) acc2[t][j] = 0.f;

        for (int ch = 0; ch < 4; ch++) {
            CP_WAIT0();
            __syncthreads();                    // W1[ch] ready
            // stage W2 chunk (k-slice 64 kp of [128 out]) — overlaps fc1
#pragma unroll
            for (int it = 0; it < 2; it++) {
                int j = it * 1024 + tid;
                int r = j >> 4, cq = (j & 15) << 2;
                cpa16(&smu[MW2H + r * 68 + cq], &g_f2h[r * 256 + ch * 64 + cq]);
                cpa16(&smu[MW2L + r * 68 + cq], &g_f2l[r * 256 + ch * 64 + cq]);
            }
            CP_COMMIT();
            // fc1: m16 x n16 per warp (A = x1 splits, B = W1)
            float acc[2][4] = {};
#pragma unroll
            for (int ks = 0; ks < 8; ks++) {
                int kp = ks * 8;
                unsigned ah0, ah1, ah2, ah3, al0, al1, al2, al3;
                ldsm4(smu + XHI, 68, m0, kp, ah0, ah1, ah2, ah3);
                ldsm4(smu + XLO, 68, m0, kp, al0, al1, al2, al3);
                unsigned bh0, bh1, bh2, bh3, bl0, bl1, bl2, bl3;
                ldsm4(smu + MW1H, 68, n0, kp, bh0, bh1, bh2, bh3);
                ldsm4(smu + MW1L, 68, n0, kp, bl0, bl1, bl2, bl3);
                mma_bf16(acc[0], ah0, ah1, ah2, ah3, bh0, bh2);
                mma_bf16(acc[0], ah0, ah1, ah2, ah3, bl0, bl2);
                mma_bf16(acc[0], al0, al1, al2, al3, bh0, bh2);
                mma_bf16(acc[1], ah0, ah1, ah2, ah3, bh1, bh3);
                mma_bf16(acc[1], ah0, ah1, ah2, ah3, bl1, bl3);
                mma_bf16(acc[1], al0, al1, al2, al3, bh1, bh3);
            }
            // silu + split -> H [t][hpair] pitch 68
            int r0 = m0 + g, r1 = r0 + 8;
#pragma unroll
            for (int nt = 0; nt < 2; nt++) {
                int cw = n0 + nt * 8 + 2 * q;
                int col = ch * 128 + cw;
                float v0 = acc[nt][0] + b1[col],     v1 = acc[nt][1] + b1[col + 1];
                float v2 = acc[nt][2] + b1[col],     v3 = acc[nt][3] + b1[col + 1];
                v0 = v0 / (1.0f + __expf(-v0));
                v1 = v1 / (1.0f + __expf(-v1));
                v2 = v2 / (1.0f + __expf(-v2));
                v3 = v3 / (1.0f + __expf(-v3));
                int pp = cw >> 1;
                split2(v0, v1, smu[MHH + r0 * 68 + pp], smu[MHL + r0 * 68 + pp]);
                split2(v2, v3, smu[MHH + r1 * 68 + pp], smu[MHL + r1 * 68 + pp]);
            }
            CP_WAIT0();
            __syncthreads();                    // W2 + H ready; W1 reads done
            // prefetch next W1 (overlaps fc2)
            if (ch < 3) {
#pragma unroll
                for (int it = 0; it < 2; it++) {
                    int j = it * 1024 + tid;
                    int r = j >> 4, cq = (j & 15) << 2;
                    cpa16(&smu[MW1H + r * 68 + cq], &g_f1h[((ch + 1) * 128 + r) * 64 + cq]);
                    cpa16(&smu[MW1L + r * 68 + cq], &g_f1l[((ch + 1) * 128 + r) * 64 + cq]);
                }
                CP_COMMIT();
            }
            // fc2 partial: m16 x n16 per warp (A = H, B = W2)
#pragma unroll
            for (int ks = 0; ks < 8; ks++) {
                int kp = ks * 8;
                unsigned ah0, ah1, ah2, ah3, al0, al1, al2, al3;
                ldsm4(smu + MHH, 68, m0, kp, ah0, ah1, ah2, ah3);
                ldsm4(smu + MHL, 68, m0, kp, al0, al1, al2, al3);
                unsigned bh0, bh1, bh2, bh3, bl0, bl1, bl2, bl3;
                ldsm4(smu + MW2H, 68, n0, kp, bh0, bh1, bh2, bh3);
                ldsm4(smu + MW2L, 68, n0, kp, bl0, bl1, bl2, bl3);
                mma_bf16(acc2[0], ah0, ah1, ah2, ah3, bh0, bh2);
                mma_bf16(acc2[0], ah0, ah1, ah2, ah3, bl0, bl2);
                mma_bf16(acc2[0], al0, al1, al2, al3, bh0, bh2);
                mma_bf16(acc2[1], ah0, ah1, ah2, ah3, bh1, bh3);
                mma_bf16(acc2[1], ah0, ah1, ah2, ah3, bl1, bl3);
                mma_bf16(acc2[1], al0, al1, al2, al3, bh1, bh3);
            }
            __syncthreads();                    // H reads done before next chunk overwrites
        }
        CP_WAIT0();
        __syncthreads();                        // W1 region dead -> Y aliases it
        // Y = fc2 out + bias
        int r0 = m0 + g, r1 = r0 + 8;
#pragma unroll
        for (int nt = 0; nt < 2; nt++) {
            int col = n0 + nt * 8 + 2 * q;
            sm[MY + r0 * 133 + col]     = acc2[nt][0] + b2[col];
            sm[MY + r0 * 133 + col + 1] = acc2[nt][1] + b2[col + 1];
            sm[MY + r1 * 133 + col]     = acc2[nt][2] + b2[col];
            sm[MY + r1 * 133 + col + 1] = acc2[nt][3] + b2[col + 1];
        }
    }
    __syncthreads();

    // final LN + residual (x1 = hi+lo from splits), 16 thr/row
    {
        int t = tid >> 4, ln = tid & 15;
        float* yrow = &sm[MY + t * 133];
        int cb = ln * 8;
        float s1 = 0.f, s2 = 0.f;
#pragma unroll
        for (int c = 0; c < 8; c++) {
            float v = yrow[cb + c];
            s1 += v; s2 += v * v;
        }
        s1 += __shfl_xor_sync(0xffffffffu, s1, 1);
        s2 += __shfl_xor_sync(0xffffffffu, s2, 1);
        s1 += __shfl_xor_sync(0xffffffffu, s1, 2);
        s2 += __shfl_xor_sync(0xffffffffu, s2, 2);
        s1 += __shfl_xor_sync(0xffffffffu, s1, 4);
        s2 += __shfl_xor_sync(0xffffffffu, s2, 4);
        s1 += __shfl_xor_sync(0xffffffffu, s1, 8);
        s2 += __shfl_xor_sync(0xffffffffu, s2, 8);
        float mu = s1 * (1.0f / 128.0f);
        float var = fmaxf(s2 * (1.0f / 128.0f) - mu * mu, 0.0f);
        float rs = rsqrtf(var + 1e-5f);
#pragma unroll
        for (int cp = 0; cp < 4; cp++) {
            unsigned uh = smu[XHI + t * 68 + ln * 4 + cp];
            unsigned ul = smu[XLO + t * 68 + ln * 4 + cp];
            float2 fh = unpack2(uh), fl = unpack2(ul);
            int cc = cb + 2 * cp;
            float l0 = (yrow[cc] - mu) * rs * n2w[cc] + n2b[cc];
            float l1 = (yrow[cc + 1] - mu) * rs * n2w[cc + 1] + n2b[cc + 1];
            yrow[cc]     = fh.x + fl.x + l0;
            yrow[cc + 1] = fh.y + fl.y + l1;
        }
    }
    __syncthreads();

    // store -> NCHW at un-shifted window positions
    {
        float* ob = out + (size_t)b * 128 * HW;
#pragma unroll
        for (int it = 0; it < 8; it++) {
            int idx = it * 1024 + tid;
            int c = idx >> 6, t = idx & 63;
            int ti = t >> 3, tj = t & 7;
            int hh = (wy * 8 + ti + 4) & 127;
            int ww = (wx * 8 + tj + 4) & 127;
            ob[(size_t)c * HW + hh * 128 + ww] = sm[MY + t * 133 + c];
        }
    }
}

// ------------------------------ launch --------------------------------------
extern "C" void kernel_launch(void* const* d_in, const int* in_sizes, int n_in,
                              void* d_out, int out_size) {
    const float* x    = (const float*)d_in[0];
    const float* n1w  = (const float*)d_in[1];
    const float* n1b  = (const float*)d_in[2];
    const float* qkvw = (const float*)d_in[3];
    const float* qb   = (const float*)d_in[4];
    const float* vb   = (const float*)d_in[5];
    const float* ls   = (const float*)d_in[6];
    const float* cw1  = (const float*)d_in[7];
    const float* cb1  = (const float*)d_in[8];
    const float* cw2  = (const float*)d_in[9];
    const float* pw   = (const float*)d_in[10];
    const float* pb   = (const float*)d_in[11];
    const float* n2w  = (const float*)d_in[12];
    const float* n2b  = (const float*)d_in[13];
    const float* f1w  = (const float*)d_in[14];
    const float* f1b  = (const float*)d_in[15];
    const float* f2w  = (const float*)d_in[16];
    const float* f2b  = (const float*)d_in[17];
    float* out = (float*)d_out;

    cudaFuncSetAttribute(kfused, cudaFuncAttributeMaxDynamicSharedMemorySize, K1_SMEM);

    k0_bias<<<1, 256>>>(cw1, cb1, cw2);
    k0_wsplit<<<384, 256>>>(qkvw, pw, f1w, f2w);
    kfused<<<4096, 1024, K1_SMEM>>>(x, n1w, n1b, qb, vb, ls, pb,
                                    n2w, n2b, f1b, f2b, out);
}

// round 17
// speedup vs baseline: 1.1118x; 1.0273x over previous
#include <cuda_runtime.h>
#include <cuda_bf16.h>
#include <math.h>

#define HW 16384
#define LOG100f 4.605170185988092f

__device__ float g_tab[225 * 4];
__device__ float g_bias16[4 * 64 * 64];
__device__ unsigned g_qkvh[24576], g_qkvl[24576];   // [384][64]
__device__ unsigned g_pwh[8192],   g_pwl[8192];     // [128][64]
__device__ unsigned g_f1h[32768],  g_f1l[32768];    // [512][64]
__device__ unsigned g_f2h[32768],  g_f2l[32768];    // [128][256]

// ---------------------------------------------------------------------------
__device__ __forceinline__ void mma_bf16(float d[4], unsigned a0, unsigned a1,
                                         unsigned a2, unsigned a3,
                                         unsigned b0, unsigned b1) {
    asm volatile(
        "mma.sync.aligned.m16n8k16.row.col.f32.bf16.bf16.f32 "
        "{%0,%1,%2,%3},{%4,%5,%6,%7},{%8,%9},{%0,%1,%2,%3};"
        : "+f"(d[0]), "+f"(d[1]), "+f"(d[2]), "+f"(d[3])
        : "r"(a0), "r"(a1), "r"(a2), "r"(a3), "r"(b0), "r"(b1));
}

__device__ __forceinline__ void ldsm4(const unsigned* base, int P, int r0, int kp,
                                      unsigned& o0, unsigned& o1, unsigned& o2, unsigned& o3) {
    int lane = threadIdx.x & 31;
    const unsigned* p = base + (r0 + (lane & 15)) * P + kp + ((lane >> 4) << 2);
    unsigned a = (unsigned)__cvta_generic_to_shared(p);
    asm volatile("ldmatrix.sync.aligned.m8n8.x4.shared.b16 {%0,%1,%2,%3}, [%4];"
                 : "=r"(o0), "=r"(o1), "=r"(o2), "=r"(o3) : "r"(a));
}

__device__ __forceinline__ void cpa16(unsigned* dst, const unsigned* src) {
    unsigned d = (unsigned)__cvta_generic_to_shared(dst);
    asm volatile("cp.async.cg.shared.global [%0], [%1], 16;" :: "r"(d), "l"(src));
}
#define CP_COMMIT() asm volatile("cp.async.commit_group;" ::: "memory")
#define CP_WAIT0()  asm volatile("cp.async.wait_group 0;" ::: "memory")

__device__ __forceinline__ void split2(float v0, float v1, unsigned& hi, unsigned& lo) {
    __nv_bfloat16 h0 = __float2bfloat16(v0);
    __nv_bfloat16 h1 = __float2bfloat16(v1);
    float r0 = v0 - __bfloat162float(h0);
    float r1 = v1 - __bfloat162float(h1);
    __nv_bfloat16 l0 = __float2bfloat16(r0);
    __nv_bfloat16 l1 = __float2bfloat16(r1);
    hi = (unsigned)__bfloat16_as_ushort(h0) | ((unsigned)__bfloat16_as_ushort(h1) << 16);
    lo = (unsigned)__bfloat16_as_ushort(l0) | ((unsigned)__bfloat16_as_ushort(l1) << 16);
}

__device__ __forceinline__ float2 unpack2(unsigned u) {
    __nv_bfloat162 b = *reinterpret_cast<__nv_bfloat162*>(&u);
    return __bfloat1622float2(b);
}

// ------------------------------ K0 (parallelized) ---------------------------
__global__ void k0_tab(const float* __restrict__ w1, const float* __restrict__ b1,
                       const float* __restrict__ w2) {
    int pid = blockIdx.x;               // 0..224
    int a = pid / 15, bb = pid % 15;
    float v0 = (a - 7) * (8.0f / 7.0f), v1 = (bb - 7) * (8.0f / 7.0f);
    float g0 = copysignf(log2f(fabsf(v0) + 1.0f) * (1.0f / 3.0f), v0);
    float g1 = copysignf(log2f(fabsf(v1) + 1.0f) * (1.0f / 3.0f), v1);
    int tid = threadIdx.x;              // 256
    float o0 = 0, o1 = 0, o2 = 0, o3 = 0;
    for (int j = tid; j < 512; j += 256) {
        float hv = fmaxf(w1[2 * j] * g0 + w1[2 * j + 1] * g1 + b1[j], 0.0f);
        o0 += hv * w2[j];        o1 += hv * w2[512 + j];
        o2 += hv * w2[1024 + j]; o3 += hv * w2[1536 + j];
    }
#pragma unroll
    for (int off = 16; off; off >>= 1) {
        o0 += __shfl_xor_sync(0xffffffffu, o0, off);
        o1 += __shfl_xor_sync(0xffffffffu, o1, off);
        o2 += __shfl_xor_sync(0xffffffffu, o2, off);
        o3 += __shfl_xor_sync(0xffffffffu, o3, off);
    }
    __shared__ float red[8][4];
    int wid = tid >> 5, lane = tid & 31;
    if (lane == 0) { red[wid][0] = o0; red[wid][1] = o1; red[wid][2] = o2; red[wid][3] = o3; }
    __syncthreads();
    if (tid == 0) {
        float s0 = 0, s1 = 0, s2 = 0, s3 = 0;
#pragma unroll
        for (int w = 0; w < 8; w++) { s0 += red[w][0]; s1 += red[w][1]; s2 += red[w][2]; s3 += red[w][3]; }
        g_tab[pid * 4 + 0] = s0; g_tab[pid * 4 + 1] = s1;
        g_tab[pid * 4 + 2] = s2; g_tab[pid * 4 + 3] = s3;
    }
}

__global__ void k0_bias2() {
    int e = blockIdx.x * 1024 + threadIdx.x;    // 16 blocks -> 16384
    int h = e >> 12, i = (e >> 6) & 63, j = e & 63;
    int dy = (i >> 3) - (j >> 3) + 7, dx = (i & 7) - (j & 7) + 7;
    float v = g_tab[(dy * 15 + dx) * 4 + h];
    g_bias16[e] = 16.0f / (1.0f + expf(-v));
}

__device__ __forceinline__ void splitpair(const float* w, unsigned* hi, unsigned* lo, int i) {
    split2(w[2 * i], w[2 * i + 1], hi[i], lo[i]);
}

__global__ void k0_wsplit(const float* __restrict__ qkvw, const float* __restrict__ pw,
                          const float* __restrict__ f1w, const float* __restrict__ f2w) {
    int i = blockIdx.x * 256 + threadIdx.x;
    if (i < 24576)       splitpair(qkvw, g_qkvh, g_qkvl, i);
    else if (i < 32768)  splitpair(pw,  g_pwh,  g_pwl,  i - 24576);
    else if (i < 65536)  splitpair(f1w, g_f1h,  g_f1l,  i - 32768);
    else if (i < 98304)  splitpair(f2w, g_f2h,  g_f2l,  i - 65536);
}

// ------------------- fused attention + MLP (1024 thr) -----------------------
#define XHI   0        // [64][68] x splits; after phase 7: x1 splits
#define XLO   4352
#define QSPH  8704
#define QSPL  13056
#define KSPH  17408
#define KSPL  21760
#define PHI_  8704
#define PLO_  17920
#define WPH   8704
#define WPL   17408
#define VSPH  27136
#define VSPL  31744
#define WQH   36352
#define WQL   45056
#define ATTN_ 36352
#define OHI_  36352
#define OLO_  40704
#define POUT  45056
#define MW1H  8704
#define MW1L  17408
#define MW2H  26112
#define MW2L  34816
#define MHH   43520
#define MHL   47872
#define MY    8704
#define RG_   53760
#define IQ_   53824
#define IK_   54080
#define K1_SMEM (54336 * 4)

__global__ void __launch_bounds__(1024, 1)
kfused(const float* __restrict__ x,
       const float* __restrict__ n1w, const float* __restrict__ n1b,
       const float* __restrict__ qb, const float* __restrict__ vb,
       const float* __restrict__ ls, const float* __restrict__ pb,
       const float* __restrict__ n2w, const float* __restrict__ n2b,
       const float* __restrict__ b1, const float* __restrict__ b2,
       float* __restrict__ out) {
    extern __shared__ float sm[];
    unsigned* smu = (unsigned*)sm;
    int tid = threadIdx.x;
    int wid = tid >> 5, lane = tid & 31;
    int g = lane >> 2, q = lane & 3;
    int b = blockIdx.x >> 8, widx = blockIdx.x & 255;
    int wy = widx >> 4, wx = widx & 15;

    // prologue: prefetch QKV chunk-0 weights
    {
#pragma unroll
        for (int it = 0; it < 2; it++) {
            int j = it * 1024 + tid;
            int r = j >> 4, cq = (j & 15) << 2;
            cpa16(&smu[WQH + r * 68 + cq], &g_qkvh[r * 64 + cq]);
            cpa16(&smu[WQL + r * 68 + cq], &g_qkvl[r * 64 + cq]);
        }
        CP_COMMIT();
    }

    // phase 0: gather shifted window -> split [t][cpair]
    {
        const float* xb = x + (size_t)b * 128 * HW;
#pragma unroll
        for (int it = 0; it < 4; it++) {
            int idx = it * 1024 + tid;
            int t = idx & 63, cp = idx >> 6;
            int ti = t >> 3, tj = t & 7;
            int hh = (wy * 8 + ti + 4) & 127;
            int ww = (wx * 8 + tj + 4) & 127;
            const float* p = xb + (size_t)(2 * cp) * HW + hh * 128 + ww;
            float v0 = p[0], v1 = p[HW];
            split2(v0, v1, smu[XHI + t * 68 + cp], smu[XLO + t * 68 + cp]);
        }
        if (tid < 64) {
            int ti = tid >> 3, tj = tid & 7;
            int hs = wy * 8 + ti, ws = wx * 8 + tj;
            int hr = hs < 120 ? 0 : (hs < 124 ? 1 : 2);
            int wr = ws < 120 ? 0 : (ws < 124 ? 1 : 2);
            sm[RG_ + tid] = (float)(hr * 3 + wr);
        }
    }

    int mi = wid & 3;
    int m0 = mi * 16;

    // phase 1: QKV GEMM, 3 chunks of 128 cols, 4 mi x 8 nw warps
    {
        int nw = wid >> 2;
        int n0 = nw * 16;
        for (int ch = 0; ch < 3; ch++) {
            if (ch > 0) {
                __syncthreads();
#pragma unroll
                for (int it = 0; it < 2; it++) {
                    int j = it * 1024 + tid;
                    int r = j >> 4, cq = (j & 15) << 2;
                    cpa16(&smu[WQH + r * 68 + cq], &g_qkvh[(ch * 128 + r) * 64 + cq]);
                    cpa16(&smu[WQL + r * 68 + cq], &g_qkvl[(ch * 128 + r) * 64 + cq]);
                }
                CP_COMMIT();
            }
            CP_WAIT0();
            __syncthreads();
            float acc[2][4] = {};
#pragma unroll
            for (int ks = 0; ks < 8; ks++) {
                int kp = ks * 8;
                unsigned ah0, ah1, ah2, ah3, al0, al1, al2, al3;
                ldsm4(smu + XHI, 68, m0, kp, ah0, ah1, ah2, ah3);
                ldsm4(smu + XLO, 68, m0, kp, al0, al1, al2, al3);
                unsigned bh0, bh1, bh2, bh3, bl0, bl1, bl2, bl3;
                ldsm4(smu + WQH, 68, n0, kp, bh0, bh1, bh2, bh3);
                ldsm4(smu + WQL, 68, n0, kp, bl0, bl1, bl2, bl3);
                mma_bf16(acc[0], ah0, ah1, ah2, ah3, bh0, bh2);
                mma_bf16(acc[0], ah0, ah1, ah2, ah3, bl0, bl2);
                mma_bf16(acc[0], al0, al1, al2, al3, bh0, bh2);
                mma_bf16(acc[1], ah0, ah1, ah2, ah3, bh1, bh3);
                mma_bf16(acc[1], ah0, ah1, ah2, ah3, bl1, bl3);
                mma_bf16(acc[1], al0, al1, al2, al3, bh1, bh3);
            }
            int r0 = m0 + g, r1 = r0 + 8;
            if (ch == 0) {          // Q
#pragma unroll
                for (int nt = 0; nt < 2; nt++) {
                    int col0 = n0 + nt * 8 + 2 * q;
                    float b0c = qb[col0], b1c = qb[col0 + 1];
                    int dp = col0 >> 1;
                    split2(acc[nt][0] + b0c, acc[nt][1] + b1c,
                           smu[QSPH + r0 * 68 + dp], smu[QSPL + r0 * 68 + dp]);
                    split2(acc[nt][2] + b0c, acc[nt][3] + b1c,
                           smu[QSPH + r1 * 68 + dp], smu[QSPL + r1 * 68 + dp]);
                }
            } else if (ch == 1) {   // K
#pragma unroll
                for (int nt = 0; nt < 2; nt++) {
                    int col0 = n0 + nt * 8 + 2 * q;
                    int dp = col0 >> 1;
                    split2(acc[nt][0], acc[nt][1],
                           smu[KSPH + r0 * 68 + dp], smu[KSPL + r0 * 68 + dp]);
                    split2(acc[nt][2], acc[nt][3],
                           smu[KSPH + r1 * 68 + dp], smu[KSPL + r1 * 68 + dp]);
                }
            } else {                // V -> [d][upair]
#pragma unroll
                for (int nt = 0; nt < 2; nt++) {
                    int d0 = n0 + nt * 8 + 2 * q;
                    float v0 = acc[nt][0] + vb[d0], v1 = acc[nt][1] + vb[d0 + 1];
                    float v2 = acc[nt][2] + vb[d0], v3 = acc[nt][3] + vb[d0 + 1];
                    float p0 = __shfl_xor_sync(0xffffffffu, v0, 4);
                    float p1 = __shfl_xor_sync(0xffffffffu, v1, 4);
                    float p2 = __shfl_xor_sync(0xffffffffu, v2, 4);
                    float p3 = __shfl_xor_sync(0xffffffffu, v3, 4);
                    if (!(g & 1)) {
                        int up = (m0 + g) >> 1;
                        split2(v0, p0, smu[VSPH + d0 * 36 + up], smu[VSPL + d0 * 36 + up]);
                        split2(v1, p1, smu[VSPH + (d0 + 1) * 36 + up], smu[VSPL + (d0 + 1) * 36 + up]);
                    } else {
                        int up = (m0 + g + 7) >> 1;
                        split2(p2, v2, smu[VSPH + d0 * 36 + up], smu[VSPL + d0 * 36 + up]);
                        split2(p3, v3, smu[VSPH + (d0 + 1) * 36 + up], smu[VSPL + (d0 + 1) * 36 + up]);
                    }
                }
            }
        }
    }
    __syncthreads();

    // phase 2: inverse norms
    {
        int qk = tid >> 9, rem = tid & 511;
        int h = rem >> 7, sub = rem & 127;
        int t = sub >> 1, half = sub & 1;
        int base = (qk ? KSPH : QSPH) + t * 68 + h * 16 + half * 8;
        int baseL = base + 4352;
        float s = 0.f;
#pragma unroll
        for (int i = 0; i < 8; i++) {
            float2 fh = unpack2(smu[base + i]);
            float2 fl = unpack2(smu[baseL + i]);
            float a0 = fh.x + fl.x, a1 = fh.y + fl.y;
            s += a0 * a0 + a1 * a1;
        }
        s += __shfl_xor_sync(0xffffffffu, s, 1);
        if (half == 0)
            sm[(qk ? IK_ : IQ_) + h * 64 + t] = 1.0f / fmaxf(sqrtf(s), 1e-12f);
    }
    __syncthreads();

    // phase 3: logits MMA
    {
        int hw = wid >> 3, nhalf = (wid >> 2) & 1;
        float scale = __expf(fminf(ls[hw], LOG100f));
        float acc[2][2][4];
#pragma unroll
        for (int i = 0; i < 2; i++)
#pragma unroll
            for (int j = 0; j < 2; j++)
#pragma unroll
                for (int k = 0; k < 4; k++) acc[i][j][k] = 0.f;
#pragma unroll
        for (int ks = 0; ks < 2; ks++) {
            int kp = hw * 16 + ks * 8;
            unsigned ah0, ah1, ah2, ah3, al0, al1, al2, al3;
            ldsm4(smu + QSPH, 68, m0, kp, ah0, ah1, ah2, ah3);
            ldsm4(smu + QSPL, 68, m0, kp, al0, al1, al2, al3);
#pragma unroll
            for (int nh = 0; nh < 2; nh++) {
                int nr = nhalf * 32 + nh * 16;
                unsigned bh0, bh1, bh2, bh3, bl0, bl1, bl2, bl3;
                ldsm4(smu + KSPH, 68, nr, kp, bh0, bh1, bh2, bh3);
                ldsm4(smu + KSPL, 68, nr, kp, bl0, bl1, bl2, bl3);
                mma_bf16(acc[nh][0], ah0, ah1, ah2, ah3, bh0, bh2);
                mma_bf16(acc[nh][0], ah0, ah1, ah2, ah3, bl0, bl2);
                mma_bf16(acc[nh][0], al0, al1, al2, al3, bh0, bh2);
                mma_bf16(acc[nh][1], ah0, ah1, ah2, ah3, bh1, bh3);
                mma_bf16(acc[nh][1], ah0, ah1, ah2, ah3, bl1, bl3);
                mma_bf16(acc[nh][1], al0, al1, al2, al3, bh1, bh3);
            }
        }
        int r0 = m0 + g, r1 = r0 + 8;
        float iq0 = sm[IQ_ + hw * 64 + r0] * scale;
        float iq1 = sm[IQ_ + hw * 64 + r1] * scale;
        float rt0 = sm[RG_ + r0], rt1 = sm[RG_ + r1];
        float* A = &sm[ATTN_ + hw * 4352];
#pragma unroll
        for (int nh = 0; nh < 2; nh++)
#pragma unroll
            for (int nt = 0; nt < 2; nt++) {
                int col = nhalf * 32 + nh * 16 + nt * 8 + 2 * q;
                float ik0 = sm[IK_ + hw * 64 + col], ik1 = sm[IK_ + hw * 64 + col + 1];
                float ru0 = sm[RG_ + col], ru1 = sm[RG_ + col + 1];
                float2 b0v = *(const float2*)&g_bias16[(hw * 64 + r0) * 64 + col];
                float2 b1v = *(const float2*)&g_bias16[(hw * 64 + r1) * 64 + col];
                A[r0 * 68 + col]     = acc[nh][nt][0] * iq0 * ik0 + b0v.x + (rt0 != ru0 ? -100.f : 0.f);
                A[r0 * 68 + col + 1] = acc[nh][nt][1] * iq0 * ik1 + b0v.y + (rt0 != ru1 ? -100.f : 0.f);
                A[r1 * 68 + col]     = acc[nh][nt][2] * iq1 * ik0 + b1v.x + (rt1 != ru0 ? -100.f : 0.f);
                A[r1 * 68 + col + 1] = acc[nh][nt][3] * iq1 * ik1 + b1v.y + (rt1 != ru1 ? -100.f : 0.f);
            }
    }
    __syncthreads();

    // phase 4: softmax -> P splits
    {
        int r = tid >> 2, qt = tid & 3;
        int hw = r >> 6, t = r & 63;
        const float* row = &sm[ATTN_ + hw * 4352 + t * 68 + qt * 16];
        float e[16];
        float mx = -1e30f;
#pragma unroll
        for (int i = 0; i < 16; i++) { e[i] = row[i]; mx = fmaxf(mx, e[i]); }
        mx = fmaxf(mx, __shfl_xor_sync(0xffffffffu, mx, 1));
        mx = fmaxf(mx, __shfl_xor_sync(0xffffffffu, mx, 2));
        float s = 0.f;
#pragma unroll
        for (int i = 0; i < 16; i++) { e[i] = __expf(e[i] - mx); s += e[i]; }
        s += __shfl_xor_sync(0xffffffffu, s, 1);
        s += __shfl_xor_sync(0xffffffffu, s, 2);
        float inv = 1.0f / s;
        int pb_ = hw * 2304 + t * 36 + qt * 8;
#pragma unroll
        for (int i = 0; i < 8; i++)
            split2(e[2 * i] * inv, e[2 * i + 1] * inv,
                   smu[PHI_ + pb_ + i], smu[PLO_ + pb_ + i]);
    }
    __syncthreads();

    // phase 5: PV MMA
    {
        int hw = wid >> 3, nd = (wid >> 2) & 1;
        const unsigned* PH = smu + PHI_ + hw * 2304;
        const unsigned* PL = smu + PLO_ + hw * 2304;
        float acc[2][4] = {};
#pragma unroll
        for (int ks = 0; ks < 4; ks++) {
            int kp = ks * 8;
            unsigned ah0, ah1, ah2, ah3, al0, al1, al2, al3;
            ldsm4(PH, 36, m0, kp, ah0, ah1, ah2, ah3);
            ldsm4(PL, 36, m0, kp, al0, al1, al2, al3);
            int n0v = hw * 32 + nd * 16;
            unsigned bh0, bh1, bh2, bh3, bl0, bl1, bl2, bl3;
            ldsm4(smu + VSPH, 36, n0v, kp, bh0, bh1, bh2, bh3);
            ldsm4(smu + VSPL, 36, n0v, kp, bl0, bl1, bl2, bl3);
            mma_bf16(acc[0], ah0, ah1, ah2, ah3, bh0, bh2);
            mma_bf16(acc[0], ah0, ah1, ah2, ah3, bl0, bl2);
            mma_bf16(acc[0], al0, al1, al2, al3, bh0, bh2);
            mma_bf16(acc[1], ah0, ah1, ah2, ah3, bh1, bh3);
            mma_bf16(acc[1], ah0, ah1, ah2, ah3, bl1, bl3);
            mma_bf16(acc[1], al0, al1, al2, al3, bh1, bh3);
        }
        int r0 = m0 + g, r1 = r0 + 8;
#pragma unroll
        for (int nt = 0; nt < 2; nt++) {
            int dglob = hw * 32 + nd * 16 + nt * 8 + 2 * q;
            int dp = dglob >> 1;
            split2(acc[nt][0], acc[nt][1],
                   smu[OHI_ + r0 * 68 + dp], smu[OLO_ + r0 * 68 + dp]);
            split2(acc[nt][2], acc[nt][3],
                   smu[OHI_ + r1 * 68 + dp], smu[OLO_ + r1 * 68 + dp]);
        }
    }

    // phase 6: proj GEMM (cp.async staged)
    {
        int nw = wid >> 2;
        int n0 = nw * 16;
        __syncthreads();
#pragma unroll
        for (int it = 0; it < 2; it++) {
            int j = it * 1024 + tid;
            int r = j >> 4, cq = (j & 15) << 2;
            cpa16(&smu[WPH + r * 68 + cq], &g_pwh[r * 64 + cq]);
            cpa16(&smu[WPL + r * 68 + cq], &g_pwl[r * 64 + cq]);
        }
        CP_COMMIT();
        CP_WAIT0();
        __syncthreads();
        float acc[2][4] = {};
#pragma unroll
        for (int ks = 0; ks < 8; ks++) {
            int kp = ks * 8;
            unsigned ah0, ah1, ah2, ah3, al0, al1, al2, al3;
            ldsm4(smu + OHI_, 68, m0, kp, ah0, ah1, ah2, ah3);
            ldsm4(smu + OLO_, 68, m0, kp, al0, al1, al2, al3);
            unsigned bh0, bh1, bh2, bh3, bl0, bl1, bl2, bl3;
            ldsm4(smu + WPH, 68, n0, kp, bh0, bh1, bh2, bh3);
            ldsm4(smu + WPL, 68, n0, kp, bl0, bl1, bl2, bl3);
            mma_bf16(acc[0], ah0, ah1, ah2, ah3, bh0, bh2);
            mma_bf16(acc[0], ah0, ah1, ah2, ah3, bl0, bl2);
            mma_bf16(acc[0], al0, al1, al2, al3, bh0, bh2);
            mma_bf16(acc[1], ah0, ah1, ah2, ah3, bh1, bh3);
            mma_bf16(acc[1], ah0, ah1, ah2, ah3, bl1, bl3);
            mma_bf16(acc[1], al0, al1, al2, al3, bh1, bh3);
        }
        int r0 = m0 + g, r1 = r0 + 8;
#pragma unroll
        for (int nt = 0; nt < 2; nt++) {
            int col0 = n0 + nt * 8 + 2 * q;
            sm[POUT + r0 * 132 + col0]     = acc[nt][0] + pb[col0];
            sm[POUT + r0 * 132 + col0 + 1] = acc[nt][1] + pb[col0 + 1];
            sm[POUT + r1 * 132 + col0]     = acc[nt][2] + pb[col0];
            sm[POUT + r1 * 132 + col0 + 1] = acc[nt][3] + pb[col0 + 1];
        }
    }
    __syncthreads();

    // prefetch W1 chunk 0 (region WPH dead after sync above)
    {
#pragma unroll
        for (int it = 0; it < 2; it++) {
            int j = it * 1024 + tid;
            int r = j >> 4, cq = (j & 15) << 2;
            cpa16(&smu[MW1H + r * 68 + cq], &g_f1h[r * 64 + cq]);
            cpa16(&smu[MW1L + r * 68 + cq], &g_f1l[r * 64 + cq]);
        }
        CP_COMMIT();
    }

    // phase 7: LN + residual -> x1 splits in place (XHI/XLO)
    {
        int t = tid >> 4, ln = tid & 15;
        const float* prow = &sm[POUT + t * 132];
        int cb = ln * 8;
        float s1 = 0.f, s2 = 0.f;
#pragma unroll
        for (int c = 0; c < 8; c++) {
            float v = prow[cb + c];
            s1 += v; s2 += v * v;
        }
        s1 += __shfl_xor_sync(0xffffffffu, s1, 1);
        s2 += __shfl_xor_sync(0xffffffffu, s2, 1);
        s1 += __shfl_xor_sync(0xffffffffu, s1, 2);
        s2 += __shfl_xor_sync(0xffffffffu, s2, 2);
        s1 += __shfl_xor_sync(0xffffffffu, s1, 4);
        s2 += __shfl_xor_sync(0xffffffffu, s2, 4);
        s1 += __shfl_xor_sync(0xffffffffu, s1, 8);
        s2 += __shfl_xor_sync(0xffffffffu, s2, 8);
        float mu = s1 * (1.0f / 128.0f);
        float var = fmaxf(s2 * (1.0f / 128.0f) - mu * mu, 0.0f);
        float rs = rsqrtf(var + 1e-5f);
#pragma unroll
        for (int cp = 0; cp < 4; cp++) {
            unsigned uh = smu[XHI + t * 68 + ln * 4 + cp];
            unsigned ul = smu[XLO + t * 68 + ln * 4 + cp];
            float2 fh = unpack2(uh), fl = unpack2(ul);
            int cc = cb + 2 * cp;
            float x1a = fh.x + fl.x + (prow[cc] - mu) * rs * n1w[cc] + n1b[cc];
            float x1b = fh.y + fl.y + (prow[cc + 1] - mu) * rs * n1w[cc + 1] + n1b[cc + 1];
            split2(x1a, x1b, smu[XHI + t * 68 + ln * 4 + cp], smu[XLO + t * 68 + ln * 4 + cp]);
        }
    }
    __syncthreads();

    // ---- MLP on this CTA's 64 tokens: 4 chunks of 128 hidden ----
    {
        int nw = wid >> 2;
        int n0 = nw * 16;
        float acc2[2][4];
#pragma unroll
        for (int t = 0; t < 2; t++)
#pragma unroll
            for (int j = 0; j < 4; j++) acc2[t][j] = 0.f;

        for (int ch = 0; ch < 4; ch++) {
            CP_WAIT0();
            __syncthreads();                    // W1[ch] ready
#pragma unroll
            for (int it = 0; it < 2; it++) {
                int j = it * 1024 + tid;
                int r = j >> 4, cq = (j & 15) << 2;
                cpa16(&smu[MW2H + r * 68 + cq], &g_f2h[r * 256 + ch * 64 + cq]);
                cpa16(&smu[MW2L + r * 68 + cq], &g_f2l[r * 256 + ch * 64 + cq]);
            }
            CP_COMMIT();
            // fc1: m16 x n16 per warp
            float acc[2][4] = {};
#pragma unroll
            for (int ks = 0; ks < 8; ks++) {
                int kp = ks * 8;
                unsigned ah0, ah1, ah2, ah3, al0, al1, al2, al3;
                ldsm4(smu + XHI, 68, m0, kp, ah0, ah1, ah2, ah3);
                ldsm4(smu + XLO, 68, m0, kp, al0, al1, al2, al3);
                unsigned bh0, bh1, bh2, bh3, bl0, bl1, bl2, bl3;
                ldsm4(smu + MW1H, 68, n0, kp, bh0, bh1, bh2, bh3);
                ldsm4(smu + MW1L, 68, n0, kp, bl0, bl1, bl2, bl3);
                mma_bf16(acc[0], ah0, ah1, ah2, ah3, bh0, bh2);
                mma_bf16(acc[0], ah0, ah1, ah2, ah3, bl0, bl2);
                mma_bf16(acc[0], al0, al1, al2, al3, bh0, bh2);
                mma_bf16(acc[1], ah0, ah1, ah2, ah3, bh1, bh3);
                mma_bf16(acc[1], ah0, ah1, ah2, ah3, bl1, bl3);
                mma_bf16(acc[1], al0, al1, al2, al3, bh1, bh3);
            }
            // silu + split -> H
            int r0 = m0 + g, r1 = r0 + 8;
#pragma unroll
            for (int nt = 0; nt < 2; nt++) {
                int cw = n0 + nt * 8 + 2 * q;
                int col = ch * 128 + cw;
                float v0 = acc[nt][0] + b1[col],     v1 = acc[nt][1] + b1[col + 1];
                float v2 = acc[nt][2] + b1[col],     v3 = acc[nt][3] + b1[col + 1];
                v0 = v0 / (1.0f + __expf(-v0));
                v1 = v1 / (1.0f + __expf(-v1));
                v2 = v2 / (1.0f + __expf(-v2));
                v3 = v3 / (1.0f + __expf(-v3));
                int pp = cw >> 1;
                split2(v0, v1, smu[MHH + r0 * 68 + pp], smu[MHL + r0 * 68 + pp]);
                split2(v2, v3, smu[MHH + r1 * 68 + pp], smu[MHL + r1 * 68 + pp]);
            }
            CP_WAIT0();
            __syncthreads();                    // W2 + H ready
            if (ch < 3) {
#pragma unroll
                for (int it = 0; it < 2; it++) {
                    int j = it * 1024 + tid;
                    int r = j >> 4, cq = (j & 15) << 2;
                    cpa16(&smu[MW1H + r * 68 + cq], &g_f1h[((ch + 1) * 128 + r) * 64 + cq]);
                    cpa16(&smu[MW1L + r * 68 + cq], &g_f1l[((ch + 1) * 128 + r) * 64 + cq]);
                }
                CP_COMMIT();
            }
            // fc2 partial: m16 x n16 per warp
#pragma unroll
            for (int ks = 0; ks < 8; ks++) {
                int kp = ks * 8;
                unsigned ah0, ah1, ah2, ah3, al0, al1, al2, al3;
                ldsm4(smu + MHH, 68, m0, kp, ah0, ah1, ah2, ah3);
                ldsm4(smu + MHL, 68, m0, kp, al0, al1, al2, al3);
                unsigned bh0, bh1, bh2, bh3, bl0, bl1, bl2, bl3;
                ldsm4(smu + MW2H, 68, n0, kp, bh0, bh1, bh2, bh3);
                ldsm4(smu + MW2L, 68, n0, kp, bl0, bl1, bl2, bl3);
                mma_bf16(acc2[0], ah0, ah1, ah2, ah3, bh0, bh2);
                mma_bf16(acc2[0], ah0, ah1, ah2, ah3, bl0, bl2);
                mma_bf16(acc2[0], al0, al1, al2, al3, bh0, bh2);
                mma_bf16(acc2[1], ah0, ah1, ah2, ah3, bh1, bh3);
                mma_bf16(acc2[1], ah0, ah1, ah2, ah3, bl1, bl3);
                mma_bf16(acc2[1], al0, al1, al2, al3, bh1, bh3);
            }
            __syncthreads();
        }
        CP_WAIT0();
        __syncthreads();
        // Y = fc2 out + bias
        int r0 = m0 + g, r1 = r0 + 8;
#pragma unroll
        for (int nt = 0; nt < 2; nt++) {
            int col = n0 + nt * 8 + 2 * q;
            sm[MY + r0 * 133 + col]     = acc2[nt][0] + b2[col];
            sm[MY + r0 * 133 + col + 1] = acc2[nt][1] + b2[col + 1];
            sm[MY + r1 * 133 + col]     = acc2[nt][2] + b2[col];
            sm[MY + r1 * 133 + col + 1] = acc2[nt][3] + b2[col + 1];
        }
    }
    __syncthreads();

    // final LN + residual, 16 thr/row
    {
        int t = tid >> 4, ln = tid & 15;
        float* yrow = &sm[MY + t * 133];
        int cb = ln * 8;
        float s1 = 0.f, s2 = 0.f;
#pragma unroll
        for (int c = 0; c < 8; c++) {
            float v = yrow[cb + c];
            s1 += v; s2 += v * v;
        }
        s1 += __shfl_xor_sync(0xffffffffu, s1, 1);
        s2 += __shfl_xor_sync(0xffffffffu, s2, 1);
        s1 += __shfl_xor_sync(0xffffffffu, s1, 2);
        s2 += __shfl_xor_sync(0xffffffffu, s2, 2);
        s1 += __shfl_xor_sync(0xffffffffu, s1, 4);
        s2 += __shfl_xor_sync(0xffffffffu, s2, 4);
        s1 += __shfl_xor_sync(0xffffffffu, s1, 8);
        s2 += __shfl_xor_sync(0xffffffffu, s2, 8);
        float mu = s1 * (1.0f / 128.0f);
        float var = fmaxf(s2 * (1.0f / 128.0f) - mu * mu, 0.0f);
        float rs = rsqrtf(var + 1e-5f);
#pragma unroll
        for (int cp = 0; cp < 4; cp++) {
            unsigned uh = smu[XHI + t * 68 + ln * 4 + cp];
            unsigned ul = smu[XLO + t * 68 + ln * 4 + cp];
            float2 fh = unpack2(uh), fl = unpack2(ul);
            int cc = cb + 2 * cp;
            float l0 = (yrow[cc] - mu) * rs * n2w[cc] + n2b[cc];
            float l1 = (yrow[cc + 1] - mu) * rs * n2w[cc + 1] + n2b[cc + 1];
            yrow[cc]     = fh.x + fl.x + l0;
            yrow[cc + 1] = fh.y + fl.y + l1;
        }
    }
    __syncthreads();

    // store -> NCHW at un-shifted window positions
    {
        float* ob = out + (size_t)b * 128 * HW;
#pragma unroll
        for (int it = 0; it < 8; it++) {
            int idx = it * 1024 + tid;
            int c = idx >> 6, t = idx & 63;
            int ti = t >> 3, tj = t & 7;
            int hh = (wy * 8 + ti + 4) & 127;
            int ww = (wx * 8 + tj + 4) & 127;
            ob[(size_t)c * HW + hh * 128 + ww] = sm[MY + t * 133 + c];
        }
    }
}

// ------------------------------ launch --------------------------------------
extern "C" void kernel_launch(void* const* d_in, const int* in_sizes, int n_in,
                              void* d_out, int out_size) {
    const float* x    = (const float*)d_in[0];
    const float* n1w  = (const float*)d_in[1];
    const float* n1b  = (const float*)d_in[2];
    const float* qkvw = (const float*)d_in[3];
    const float* qb   = (const float*)d_in[4];
    const float* vb   = (const float*)d_in[5];
    const float* ls   = (const float*)d_in[6];
    const float* cw1  = (const float*)d_in[7];
    const float* cb1  = (const float*)d_in[8];
    const float* cw2  = (const float*)d_in[9];
    const float* pw   = (const float*)d_in[10];
    const float* pb   = (const float*)d_in[11];
    const float* n2w  = (const float*)d_in[12];
    const float* n2b  = (const float*)d_in[13];
    const float* f1w  = (const float*)d_in[14];
    const float* f1b  = (const float*)d_in[15];
    const float* f2w  = (const float*)d_in[16];
    const float* f2b  = (const float*)d_in[17];
    float* out = (float*)d_out;

    cudaFuncSetAttribute(kfused, cudaFuncAttributeMaxDynamicSharedMemorySize, K1_SMEM);

    k0_tab<<<225, 256>>>(cw1, cb1, cw2);
    k0_wsplit<<<384, 256>>>(qkvw, pw, f1w, f2w);
    k0_bias2<<<16, 1024>>>();
    kfused<<<4096, 1024, K1_SMEM>>>(x, n1w, n1b, qb, vb, ls, pb,
                                    n2w, n2b, f1b, f2b, out);
}